// round 8
// baseline (speedup 1.0000x reference)
#include <cuda_runtime.h>
#include <math.h>

typedef unsigned long long ull;
typedef unsigned int uint;

// ---------------- problem constants ----------------
#define NPTS_MAX 200000
#define NB_MAX   220000
#define NC_MAX   98304
#define IMG_ELEMS (4*512*48*64)

#define CVS0 (6.2831853f/512.0f)
#define CVS1 0.125f
#define CR0  (-3.14159265f)
#define CR1  (-2.0f)

// ---------------- scratch ----------------
__device__ float d_lin1[(size_t)NPTS_MAX*64];
__device__ float d_lin2[(size_t)NPTS_MAX*128];
__device__ float d_lin3[(size_t)NPTS_MAX*64];
__device__ float d_dense[IMG_ELEMS];
__device__ float d_conv[IMG_ELEMS];
__device__ float d_bevsum[NB_MAX*4];
__device__ float d_cylsum[NC_MAX*4];
__device__ float d_stats[1024];
__device__ float d_bn[1024];  // lin1 a@0 c@64; lin2 a@128 c@256; conv a@384 c@448; lin3 a@512 c@576
__device__ unsigned d_ctr[8];
__device__ float d_wt_hi[9*64*64];   // [dy][dx*64+cin][f]
__device__ float d_wt_lo[9*64*64];

// ---------------- helpers ----------------
__device__ __forceinline__ ull pk2(float v) {
    ull r; unsigned u = __float_as_uint(v);
    asm("mov.b64 %0, {%1, %1};" : "=l"(r) : "r"(u));
    return r;
}
__device__ __forceinline__ void ffma2(ull& d, ull a, ull b) {
    asm("fma.rn.f32x2 %0, %1, %2, %0;" : "+l"(d) : "l"(a), "l"(b));
}
__device__ __forceinline__ uint tf32(float f) {
    uint r; asm("cvt.rna.tf32.f32 %0, %1;" : "=r"(r) : "f"(f)); return r;
}
__device__ __forceinline__ void tf32split(float v, float& hi, float& lo) {
    uint h = tf32(v);
    hi = __uint_as_float(h);
    lo = __uint_as_float(tf32(v - hi));
}
__device__ __forceinline__ void mma_tf32(float* c, uint a0, uint a1, uint a2, uint a3, uint b0, uint b1) {
    asm volatile("mma.sync.aligned.m16n8k8.row.col.f32.tf32.tf32.f32 "
                 "{%0,%1,%2,%3},{%4,%5,%6,%7},{%8,%9},{%0,%1,%2,%3};"
                 : "+f"(c[0]), "+f"(c[1]), "+f"(c[2]), "+f"(c[3])
                 : "r"(a0), "r"(a1), "r"(a2), "r"(a3), "r"(b0), "r"(b1));
}

// ---------------- utility kernels ----------------
__global__ void __launch_bounds__(256) k_zero(float* outbev, int nb, int nc) {
    size_t tid = (size_t)blockIdx.x * blockDim.x + threadIdx.x;
    size_t stride = (size_t)gridDim.x * blockDim.x;
    float4 z = make_float4(0.f, 0.f, 0.f, 0.f);
    float4* p = (float4*)d_dense;
    for (size_t i = tid; i < IMG_ELEMS/4; i += stride) p[i] = z;
    float4* q = (float4*)outbev;
    size_t obw = (size_t)nb * 16;
    for (size_t i = tid; i < obw; i += stride) q[i] = z;
    float4* bs = (float4*)d_bevsum;
    for (size_t i = tid; i < (size_t)nb; i += stride) bs[i] = z;
    float4* cs = (float4*)d_cylsum;
    for (size_t i = tid; i < (size_t)nc; i += stride) cs[i] = z;
    if (tid < 256) ((float4*)d_stats)[tid] = z;
    if (tid < 8) d_ctr[tid] = 0u;
}

// transpose + hi/lo split conv weights: wc[f][cin][dy][dx] -> d_wt[dy][dx*64+cin][f]
__global__ void k_wprep(const float* __restrict__ wc) {
    int t = blockIdx.x*256 + threadIdx.x;
    if (t >= 36864) return;
    int f = t & 63, rr = t >> 6;
    int cin = rr & 63, dd = rr >> 6;       // dd = dy*3+dx
    float v = wc[(size_t)f*576 + cin*9 + dd];
    float hi, lo; tf32split(v, hi, lo);
    int o = (dd*64 + cin)*64 + f;          // dy*12288 + (dx*64+cin)*64 + f
    d_wt_hi[o] = hi;
    d_wt_lo[o] = lo;
}

__global__ void k_scatter(const float* __restrict__ pts, const float* __restrict__ pcyl,
                          const int* __restrict__ binv, const int* __restrict__ cinv, int n) {
    int i = blockIdx.x*blockDim.x + threadIdx.x;
    if (i >= n) return;
    float x = pts[(size_t)i*5+1], y = pts[(size_t)i*5+2], z = pts[(size_t)i*5+3];
    int bi = binv[i], ci = cinv[i];
    atomicAdd(&d_bevsum[bi*4+0], x);
    atomicAdd(&d_bevsum[bi*4+1], y);
    atomicAdd(&d_bevsum[bi*4+2], z);
    atomicAdd(&d_bevsum[bi*4+3], 1.0f);
    float p0 = pcyl[(size_t)i*3], p1 = pcyl[(size_t)i*3+1], p2 = pcyl[(size_t)i*3+2];
    atomicAdd(&d_cylsum[ci*4+0], p0);
    atomicAdd(&d_cylsum[ci*4+1], p1);
    atomicAdd(&d_cylsum[ci*4+2], p2);
    atomicAdd(&d_cylsum[ci*4+3], 1.0f);
}

__global__ void __launch_bounds__(256) k_lin1(
        const float* __restrict__ pts, const float* __restrict__ pcyl,
        const float* __restrict__ cylidx, const float* __restrict__ bevidx,
        const int* __restrict__ binv, const int* __restrict__ cinv,
        const float* __restrict__ w1, int n) {
    __shared__ float sw[16*64];
    for (int t = threadIdx.x; t < 1024; t += 256) { int o = t >> 4, k = t & 15; sw[k*64+o] = w1[t]; }
    __syncthreads();
    int i = blockIdx.x*256 + threadIdx.x;
    if (i >= n) return;
    float x = pts[(size_t)i*5+1], y = pts[(size_t)i*5+2], z = pts[(size_t)i*5+3], it = pts[(size_t)i*5+4];
    float phi = pcyl[(size_t)i*3], zc = pcyl[(size_t)i*3+1], rho = pcyl[(size_t)i*3+2];
    float bix = bevidx[2*(size_t)i], biy = bevidx[2*(size_t)i+1];
    float cix = cylidx[2*(size_t)i], ciy = cylidx[2*(size_t)i+1];
    int bi = binv[i], ci = cinv[i];
    float bcnt = d_bevsum[bi*4+3];
    float bmx = d_bevsum[bi*4]/bcnt, bmy = d_bevsum[bi*4+1]/bcnt;
    float ccnt = d_cylsum[ci*4+3];
    float cm0 = d_cylsum[ci*4]/ccnt, cm1 = d_cylsum[ci*4+1]/ccnt;
    float f[16];
    f[0]=x; f[1]=y; f[2]=z; f[3]=phi; f[4]=zc; f[5]=rho;
    f[6] = x - ((floorf(bix)+0.5f)*0.32f + 0.0f);
    f[7] = y - ((floorf(biy)+0.5f)*0.32f + (-40.0f));
    f[8] = phi - ((floorf(cix)+0.5f)*CVS0 + CR0);
    f[9] = zc  - ((floorf(ciy)+0.5f)*CVS1 + CR1);
    f[10]= x - bmx; f[11]= y - bmy;
    f[12]= phi - cm0; f[13]= zc - cm1;
    f[14]= sqrtf(x*x + y*y + z*z);
    f[15]= it;
    ull acc[32];
    #pragma unroll
    for (int o = 0; o < 32; o++) acc[o] = 0ULL;
    #pragma unroll
    for (int k = 0; k < 16; k++) {
        ull v = pk2(f[k]);
        const ulonglong2* wr = (const ulonglong2*)&sw[k*64];
        #pragma unroll
        for (int m = 0; m < 16; m++) {
            ulonglong2 w = wr[m];
            ffma2(acc[2*m], v, w.x); ffma2(acc[2*m+1], v, w.y);
        }
    }
    ulonglong2* op = (ulonglong2*)&d_lin1[(size_t)i*64];
    #pragma unroll
    for (int m = 0; m < 16; m++) op[m] = make_ulonglong2(acc[2*m], acc[2*m+1]);
}

// per-channel sum/sumsq + last-block BN finalize
__global__ void k_stats(const float* __restrict__ data, int rows, int C, int shift,
                        float* __restrict__ out, const float* __restrict__ g,
                        const float* __restrict__ b, float invn, int bbase, int ctr_idx) {
    int tid = threadIdx.x;
    int c = tid & (C-1);
    int sub = tid >> shift;
    int rpb = 256 >> shift;
    float s = 0.f, s2 = 0.f;
    for (long r = (long)blockIdx.x*rpb + sub; r < rows; r += (long)gridDim.x*rpb) {
        float v = data[(size_t)r*C + c];
        s += v; s2 += v*v;
    }
    __shared__ float sh[512];
    sh[tid] = s; sh[256+tid] = s2;
    __syncthreads();
    if (sub == 0) {
        for (int j = 1; j < rpb; j++) { s += sh[j*C + c]; s2 += sh[256 + j*C + c]; }
        atomicAdd(&out[c], s);
        atomicAdd(&out[C+c], s2);
    }
    __threadfence();
    __syncthreads();
    __shared__ unsigned s_ord;
    if (tid == 0) s_ord = atomicAdd(&d_ctr[ctr_idx], 1u);
    __syncthreads();
    if (s_ord == gridDim.x - 1 && tid < C) {
        float m = __ldcg(&out[tid]) * invn;
        float v = __ldcg(&out[C+tid]) * invn - m*m;
        float a = g[tid] * rsqrtf(v + 1e-3f);
        d_bn[bbase + tid]     = a;
        d_bn[bbase + C + tid] = b[tid] - m*a;
    }
}

// ---------------- lin2: 3xTF32 MMA GEMM  [N,64] @ [64,128] ----------------
// smem: A hi/lo [128][68] x2, B hi/lo [64][136] x2; stage reuses front
#define L2_SMEM ((2*128*68 + 2*64*136)*4)
__global__ void __launch_bounds__(256) k_lin2(const float* __restrict__ w2, int n) {
    extern __shared__ float dsm[];
    float* s_ah = dsm;                 // [p][k] pitch 68
    float* s_al = s_ah + 128*68;
    float* s_bh = s_al + 128*68;       // [k][o] pitch 136
    float* s_bl = s_bh + 64*136;
    __shared__ float sa[64], sc[64];
    int tid = threadIdx.x;
    if (tid < 64) { sa[tid] = d_bn[tid]; sc[tid] = d_bn[64+tid]; }
    for (int t = tid; t < 8192; t += 256) {
        int o = t >> 6, k = t & 63;
        float hi, lo; tf32split(w2[t], hi, lo);
        s_bh[k*136 + o] = hi;
        s_bl[k*136 + o] = lo;
    }
    __syncthreads();
    int pbase = blockIdx.x*128;
    for (int idx = tid; idx < 128*16; idx += 256) {
        int lp = idx >> 4, kq = idx & 15;
        int p = pbase + lp, k = kq*4;
        float4 v = make_float4(0.f,0.f,0.f,0.f);
        if (p < n) v = *(const float4*)&d_lin1[(size_t)p*64 + k];
        float h0,l0,h1,l1,h2,l2,h3,l3;
        tf32split(fmaxf(fmaf(v.x, sa[k+0], sc[k+0]), 0.f), h0, l0);
        tf32split(fmaxf(fmaf(v.y, sa[k+1], sc[k+1]), 0.f), h1, l1);
        tf32split(fmaxf(fmaf(v.z, sa[k+2], sc[k+2]), 0.f), h2, l2);
        tf32split(fmaxf(fmaf(v.w, sa[k+3], sc[k+3]), 0.f), h3, l3);
        *(float4*)&s_ah[lp*68 + k] = make_float4(h0,h1,h2,h3);
        *(float4*)&s_al[lp*68 + k] = make_float4(l0,l1,l2,l3);
    }
    __syncthreads();
    int wid = tid >> 5, lane = tid & 31;
    int g = lane >> 2, tg = lane & 3;
    int m0 = wid*16;
    const uint* uah = (const uint*)s_ah;
    const uint* ual = (const uint*)s_al;
    const uint* ubh = (const uint*)s_bh;
    const uint* ubl = (const uint*)s_bl;
    float c[16][4];
    #pragma unroll
    for (int nt = 0; nt < 16; nt++)
        #pragma unroll
        for (int j = 0; j < 4; j++) c[nt][j] = 0.f;
    #pragma unroll
    for (int kc = 0; kc < 8; kc++) {
        int k0 = kc*8;
        int i00 = (m0+g)*68 + k0 + tg, i10 = (m0+g+8)*68 + k0 + tg;
        uint a0h = uah[i00], a1h = uah[i10], a2h = uah[i00+4], a3h = uah[i10+4];
        uint a0l = ual[i00], a1l = ual[i10], a2l = ual[i00+4], a3l = ual[i10+4];
        #pragma unroll
        for (int nt = 0; nt < 16; nt++) {
            int j0 = (k0+tg)*136 + nt*8 + g, j1 = (k0+tg+4)*136 + nt*8 + g;
            uint b0h = ubh[j0], b1h = ubh[j1];
            uint b0l = ubl[j0], b1l = ubl[j1];
            mma_tf32(c[nt], a0h, a1h, a2h, a3h, b0h, b1h);
            mma_tf32(c[nt], a0h, a1h, a2h, a3h, b0l, b1l);
            mma_tf32(c[nt], a0l, a1l, a2l, a3l, b0h, b1h);
        }
    }
    __syncthreads();
    float* stage = dsm;              // [p][o] pitch 132
    #pragma unroll
    for (int nt = 0; nt < 16; nt++) {
        int n0 = nt*8 + tg*2;
        *(float2*)&stage[(m0+g)*132   + n0] = make_float2(c[nt][0], c[nt][1]);
        *(float2*)&stage[(m0+g+8)*132 + n0] = make_float2(c[nt][2], c[nt][3]);
    }
    __syncthreads();
    for (int idx = tid; idx < 128*32; idx += 256) {
        int lp = idx >> 5, q = idx & 31;
        int p = pbase + lp;
        if (p < n)
            *(float4*)&d_lin2[(size_t)p*128 + q*4] = *(const float4*)&stage[lp*132 + q*4];
    }
}

// segment-max of bn_relu(lin2[:, :64]) into dense image
__global__ void k_cylmax(const float* __restrict__ pts, const float* __restrict__ cylidx, int n) {
    __shared__ float sa[64], sc[64];
    if (threadIdx.x < 64) { sa[threadIdx.x] = d_bn[128+threadIdx.x]; sc[threadIdx.x] = d_bn[256+threadIdx.x]; }
    __syncthreads();
    int i = blockIdx.x*blockDim.x + threadIdx.x;
    if (i >= n) return;
    int b = (int)pts[(size_t)i*5];
    int iy = (int)floorf(cylidx[2*(size_t)i]);   iy = max(0, min(iy, 511));
    int ix = (int)floorf(cylidx[2*(size_t)i+1]); ix = max(0, min(ix, 47));
    unsigned* dst = (unsigned*)&d_dense[(((size_t)b*512 + iy)*48 + ix)*64];
    const float4* src = (const float4*)&d_lin2[(size_t)i*128];
    #pragma unroll
    for (int j = 0; j < 16; j++) {
        float4 v = src[j];
        int c = j*4;
        float r0 = fmaxf(fmaf(v.x, sa[c+0], sc[c+0]), 0.f);
        float r1 = fmaxf(fmaf(v.y, sa[c+1], sc[c+1]), 0.f);
        float r2 = fmaxf(fmaf(v.z, sa[c+2], sc[c+2]), 0.f);
        float r3 = fmaxf(fmaf(v.w, sa[c+3], sc[c+3]), 0.f);
        atomicMax(dst+c+0, __float_as_uint(r0));
        atomicMax(dst+c+1, __float_as_uint(r1));
        atomicMax(dst+c+2, __float_as_uint(r2));
        atomicMax(dst+c+3, __float_as_uint(r3));
    }
}

// ---------------- conv: 3xTF32 implicit-GEMM MMA ----------------
// tile 8x16 positions (M=128), N=64 out-ch, K = 3 dy stages x 192 (dx*64+cin)
#define CV_SMEM ((2*180*68 + 2*192*72)*4)
__global__ void __launch_bounds__(256) k_conv() {
    extern __shared__ float dsm[];
    float* s_ih = dsm;                    // [pos][cin] pitch 68, pos = hy*18+hx (10x18)
    float* s_il = s_ih + 180*68;
    float* s_wh = s_il + 180*68;          // [dx*64+cin][f] pitch 72
    float* s_wl = s_wh + 192*72;
    int x0 = blockIdx.x*16, y0 = blockIdx.y*8, bb = blockIdx.z;
    int tid = threadIdx.x;
    // input halo hi/lo
    for (int idx = tid; idx < 180*16; idx += 256) {
        int pos = idx >> 4, c4 = idx & 15;
        int hy = pos / 18, hx = pos - hy*18;
        int gy = y0 + hy - 1, gx = x0 + hx - 1;
        float4 v = make_float4(0.f,0.f,0.f,0.f);
        if (gy >= 0 && gy < 512 && gx >= 0 && gx < 48)
            v = *(const float4*)&d_dense[(((size_t)bb*512 + gy)*48 + gx)*64 + c4*4];
        float h0,l0,h1,l1,h2,l2,h3,l3;
        tf32split(v.x, h0, l0); tf32split(v.y, h1, l1);
        tf32split(v.z, h2, l2); tf32split(v.w, h3, l3);
        *(float4*)&s_ih[pos*68 + c4*4] = make_float4(h0,h1,h2,h3);
        *(float4*)&s_il[pos*68 + c4*4] = make_float4(l0,l1,l2,l3);
    }
    int wid = tid >> 5, lane = tid & 31;
    int g = lane >> 2, tg = lane & 3;
    const uint* uih = (const uint*)s_ih;
    const uint* uil = (const uint*)s_il;
    const uint* uwh = (const uint*)s_wh;
    const uint* uwl = (const uint*)s_wl;
    float c[8][4];
    #pragma unroll
    for (int nt = 0; nt < 8; nt++)
        #pragma unroll
        for (int j = 0; j < 4; j++) c[nt][j] = 0.f;
    for (int dy = 0; dy < 3; dy++) {
        __syncthreads();
        for (int t = tid; t < 12288; t += 256) {
            int k = t >> 6, f = t & 63;
            s_wh[k*72 + f] = d_wt_hi[dy*12288 + t];
            s_wl[k*72 + f] = d_wt_lo[dy*12288 + t];
        }
        __syncthreads();
        int hbase = (wid + dy)*18;
        #pragma unroll
        for (int ch = 0; ch < 24; ch++) {
            int dx = ch >> 3, cin0 = (ch & 7)*8;
            int k0 = ch*8;
            int i00 = (hbase + g + dx)*68 + cin0 + tg;
            int i10 = i00 + 8*68;
            uint a0h = uih[i00], a1h = uih[i10], a2h = uih[i00+4], a3h = uih[i10+4];
            uint a0l = uil[i00], a1l = uil[i10], a2l = uil[i00+4], a3l = uil[i10+4];
            #pragma unroll
            for (int nt = 0; nt < 8; nt++) {
                int j0 = (k0+tg)*72 + nt*8 + g, j1 = (k0+tg+4)*72 + nt*8 + g;
                uint b0h = uwh[j0], b1h = uwh[j1];
                uint b0l = uwl[j0], b1l = uwl[j1];
                mma_tf32(c[nt], a0h, a1h, a2h, a3h, b0h, b1h);
                mma_tf32(c[nt], a0h, a1h, a2h, a3h, b0l, b1l);
                mma_tf32(c[nt], a0l, a1l, a2l, a3l, b0h, b1h);
            }
        }
    }
    // epilogue: row m = wid*16 + g (gy = y0+wid, gx = x0+g / +8)
    int gy = y0 + wid;
    size_t rb = ((size_t)bb*512 + gy)*48;
    #pragma unroll
    for (int nt = 0; nt < 8; nt++) {
        int col = nt*8 + tg*2;
        *(float2*)&d_conv[(rb + x0 + g)*64 + col]     = make_float2(c[nt][0], c[nt][1]);
        *(float2*)&d_conv[(rb + x0 + g + 8)*64 + col] = make_float2(c[nt][2], c[nt][3]);
    }
}

// ---------------- lin3: 3xTF32 MMA GEMM [N,128] @ [128,64], gather inlined ----------------
#define L3_SMEM ((2*128*132 + 2*128*72)*4)
__global__ void __launch_bounds__(256) k_lin3(const float* __restrict__ pts,
        const float* __restrict__ cylidx, const float* __restrict__ w3, int n) {
    extern __shared__ float dsm[];
    float* s_ah = dsm;                 // [p][k] pitch 132
    float* s_al = s_ah + 128*132;
    float* s_bh = s_al + 128*132;      // [k][o] pitch 72
    float* s_bl = s_bh + 128*72;
    __shared__ float pa[64], pc[64], ca[64], cs[64];
    __shared__ float s_w4[4][128];
    __shared__ int   s_o4[4][128];
    int tid = threadIdx.x;
    if (tid < 64) {
        pa[tid] = d_bn[192+tid]; pc[tid] = d_bn[320+tid];
        ca[tid] = d_bn[384+tid]; cs[tid] = d_bn[448+tid];
    }
    for (int t = tid; t < 8192; t += 256) {
        int o = t >> 7, k = t & 127;
        float hi, lo; tf32split(w3[t], hi, lo);
        s_bh[k*72 + o] = hi;
        s_bl[k*72 + o] = lo;
    }
    int pbase = blockIdx.x*128;
    if (tid < 128) {
        int p = pbase + tid;
        int i = (p < n) ? p : (n-1);
        float yq = cylidx[2*(size_t)i], xq = cylidx[2*(size_t)i+1];
        int y0i = (int)floorf(yq); int y1i = min(y0i+1, 511); y0i = min(max(y0i,0), 511);
        int x0i = (int)floorf(xq); int x1i = min(x0i+1, 47);  x0i = min(max(x0i,0), 47);
        s_w4[0][tid] = ((float)x1i - xq)*((float)y1i - yq);
        s_w4[1][tid] = ((float)x1i - xq)*(yq - (float)y0i);
        s_w4[2][tid] = (xq - (float)x0i)*((float)y1i - yq);
        s_w4[3][tid] = (xq - (float)x0i)*(yq - (float)y0i);
        int b = (int)pts[(size_t)i*5];
        int base = b*512*48*64;
        s_o4[0][tid] = base + (y0i*48 + x0i)*64;
        s_o4[1][tid] = base + (y1i*48 + x0i)*64;
        s_o4[2][tid] = base + (y0i*48 + x1i)*64;
        s_o4[3][tid] = base + (y1i*48 + x1i)*64;
    }
    __syncthreads();
    for (int idx = tid; idx < 128*16; idx += 256) {
        int lp = idx >> 4, kq = idx & 15;
        int p = pbase + lp, k = kq*4;
        float4 v = make_float4(0.f,0.f,0.f,0.f);
        if (p < n) {
            v = *(const float4*)&d_lin2[(size_t)p*128 + 64 + k];
            v.x = fmaxf(fmaf(v.x, pa[k+0], pc[k+0]), 0.f);
            v.y = fmaxf(fmaf(v.y, pa[k+1], pc[k+1]), 0.f);
            v.z = fmaxf(fmaf(v.z, pa[k+2], pc[k+2]), 0.f);
            v.w = fmaxf(fmaf(v.w, pa[k+3], pc[k+3]), 0.f);
        }
        float h0,l0,h1,l1,h2,l2,h3,l3;
        tf32split(v.x, h0, l0); tf32split(v.y, h1, l1);
        tf32split(v.z, h2, l2); tf32split(v.w, h3, l3);
        *(float4*)&s_ah[lp*132 + k] = make_float4(h0,h1,h2,h3);
        *(float4*)&s_al[lp*132 + k] = make_float4(l0,l1,l2,l3);
    }
    for (int idx = tid; idx < 128*16; idx += 256) {
        int lp = idx >> 4, kq = idx & 15;
        int p = pbase + lp, c = kq*4;
        float4 r = make_float4(0.f,0.f,0.f,0.f);
        if (p < n) {
            float wa = s_w4[0][lp], wb = s_w4[1][lp], wcw = s_w4[2][lp], wd = s_w4[3][lp];
            float4 av = *(const float4*)&d_conv[s_o4[0][lp] + c];
            float4 bv = *(const float4*)&d_conv[s_o4[1][lp] + c];
            float4 cv = *(const float4*)&d_conv[s_o4[2][lp] + c];
            float4 dv = *(const float4*)&d_conv[s_o4[3][lp] + c];
            r.x = wa*fmaxf(fmaf(av.x, ca[c+0], cs[c+0]),0.f) + wb*fmaxf(fmaf(bv.x, ca[c+0], cs[c+0]),0.f)
                + wcw*fmaxf(fmaf(cv.x, ca[c+0], cs[c+0]),0.f) + wd*fmaxf(fmaf(dv.x, ca[c+0], cs[c+0]),0.f);
            r.y = wa*fmaxf(fmaf(av.y, ca[c+1], cs[c+1]),0.f) + wb*fmaxf(fmaf(bv.y, ca[c+1], cs[c+1]),0.f)
                + wcw*fmaxf(fmaf(cv.y, ca[c+1], cs[c+1]),0.f) + wd*fmaxf(fmaf(dv.y, ca[c+1], cs[c+1]),0.f);
            r.z = wa*fmaxf(fmaf(av.z, ca[c+2], cs[c+2]),0.f) + wb*fmaxf(fmaf(bv.z, ca[c+2], cs[c+2]),0.f)
                + wcw*fmaxf(fmaf(cv.z, ca[c+2], cs[c+2]),0.f) + wd*fmaxf(fmaf(dv.z, ca[c+2], cs[c+2]),0.f);
            r.w = wa*fmaxf(fmaf(av.w, ca[c+3], cs[c+3]),0.f) + wb*fmaxf(fmaf(bv.w, ca[c+3], cs[c+3]),0.f)
                + wcw*fmaxf(fmaf(cv.w, ca[c+3], cs[c+3]),0.f) + wd*fmaxf(fmaf(dv.w, ca[c+3], cs[c+3]),0.f);
        }
        float h0,l0,h1,l1,h2,l2,h3,l3;
        tf32split(r.x, h0, l0); tf32split(r.y, h1, l1);
        tf32split(r.z, h2, l2); tf32split(r.w, h3, l3);
        *(float4*)&s_ah[lp*132 + 64 + c] = make_float4(h0,h1,h2,h3);
        *(float4*)&s_al[lp*132 + 64 + c] = make_float4(l0,l1,l2,l3);
    }
    __syncthreads();
    int wid = tid >> 5, lane = tid & 31;
    int g = lane >> 2, tg = lane & 3;
    int m0 = wid*16;
    const uint* uah = (const uint*)s_ah;
    const uint* ual = (const uint*)s_al;
    const uint* ubh = (const uint*)s_bh;
    const uint* ubl = (const uint*)s_bl;
    float c[8][4];
    #pragma unroll
    for (int nt = 0; nt < 8; nt++)
        #pragma unroll
        for (int j = 0; j < 4; j++) c[nt][j] = 0.f;
    #pragma unroll
    for (int kc = 0; kc < 16; kc++) {
        int k0 = kc*8;
        int i00 = (m0+g)*132 + k0 + tg, i10 = (m0+g+8)*132 + k0 + tg;
        uint a0h = uah[i00], a1h = uah[i10], a2h = uah[i00+4], a3h = uah[i10+4];
        uint a0l = ual[i00], a1l = ual[i10], a2l = ual[i00+4], a3l = ual[i10+4];
        #pragma unroll
        for (int nt = 0; nt < 8; nt++) {
            int j0 = (k0+tg)*72 + nt*8 + g, j1 = (k0+tg+4)*72 + nt*8 + g;
            uint b0h = ubh[j0], b1h = ubh[j1];
            uint b0l = ubl[j0], b1l = ubl[j1];
            mma_tf32(c[nt], a0h, a1h, a2h, a3h, b0h, b1h);
            mma_tf32(c[nt], a0h, a1h, a2h, a3h, b0l, b1l);
            mma_tf32(c[nt], a0l, a1l, a2l, a3l, b0h, b1h);
        }
    }
    __syncthreads();
    float* stage = dsm;              // [p][o] pitch 68
    #pragma unroll
    for (int nt = 0; nt < 8; nt++) {
        int n0 = nt*8 + tg*2;
        *(float2*)&stage[(m0+g)*68   + n0] = make_float2(c[nt][0], c[nt][1]);
        *(float2*)&stage[(m0+g+8)*68 + n0] = make_float2(c[nt][2], c[nt][3]);
    }
    __syncthreads();
    for (int idx = tid; idx < 128*16; idx += 256) {
        int lp = idx >> 4, q = idx & 15;
        int p = pbase + lp;
        if (p < n)
            *(float4*)&d_lin3[(size_t)p*64 + q*4] = *(const float4*)&stage[lp*68 + q*4];
    }
}

// final: bn_relu(lin3) -> out; atomicMax into bev_max; extra blocks do voxel coords
__global__ void k_final(const int* __restrict__ binv, const int* __restrict__ bcoord,
                        float* __restrict__ out, int n, int nb, int nblk) {
    if (blockIdx.x >= nblk) {
        int i = (blockIdx.x - nblk)*blockDim.x + threadIdx.x;
        if (i < nb) {
            int c = bcoord[i];
            int vb = c / 55000;
            int r  = c % 55000;
            int vx = r / 250;
            int vy = r % 250;
            float* o = out + (size_t)n*64 + (size_t)nb*64 + (size_t)i*4;
            o[0] = (float)vb; o[1] = 0.f; o[2] = (float)vy; o[3] = (float)vx;
        }
        return;
    }
    __shared__ float sa[64], sc[64];
    if (threadIdx.x < 64) { sa[threadIdx.x] = d_bn[512+threadIdx.x]; sc[threadIdx.x] = d_bn[576+threadIdx.x]; }
    __syncthreads();
    int i = blockIdx.x*blockDim.x + threadIdx.x;
    if (i >= n) return;
    int bi = binv[i];
    const float4* src = (const float4*)&d_lin3[(size_t)i*64];
    float4* dst = (float4*)(out + (size_t)i*64);
    unsigned* mx = (unsigned*)(out + (size_t)n*64 + (size_t)bi*64);
    #pragma unroll
    for (int j = 0; j < 16; j++) {
        float4 v = src[j];
        int c = j*4;
        float r0 = fmaxf(fmaf(v.x, sa[c+0], sc[c+0]), 0.f);
        float r1 = fmaxf(fmaf(v.y, sa[c+1], sc[c+1]), 0.f);
        float r2 = fmaxf(fmaf(v.z, sa[c+2], sc[c+2]), 0.f);
        float r3 = fmaxf(fmaf(v.w, sa[c+3], sc[c+3]), 0.f);
        dst[j] = make_float4(r0, r1, r2, r3);
        atomicMax(mx+c+0, __float_as_uint(r0));
        atomicMax(mx+c+1, __float_as_uint(r1));
        atomicMax(mx+c+2, __float_as_uint(r2));
        atomicMax(mx+c+3, __float_as_uint(r3));
    }
}

// ---------------- launcher ----------------
extern "C" void kernel_launch(void* const* d_in, const int* in_sizes, int n_in,
                              void* d_out, int out_size) {
    const float* points = (const float*)d_in[0];
    const float* pcyl   = (const float*)d_in[1];
    const float* cylidx = (const float*)d_in[2];
    const float* bevidx = (const float*)d_in[3];
    const float* w1 = (const float*)d_in[4];
    const float* g1 = (const float*)d_in[5];
    const float* b1 = (const float*)d_in[6];
    const float* w2 = (const float*)d_in[7];
    const float* g2 = (const float*)d_in[8];
    const float* b2 = (const float*)d_in[9];
    const float* wc = (const float*)d_in[10];
    const float* gc = (const float*)d_in[11];
    const float* bc = (const float*)d_in[12];
    const float* w3 = (const float*)d_in[13];
    const float* g3 = (const float*)d_in[14];
    const float* b3 = (const float*)d_in[15];
    const int* binv   = (const int*)d_in[16];
    const int* bcoord = (const int*)d_in[17];
    const int* cinv   = (const int*)d_in[18];

    int n  = in_sizes[0] / 5;
    int nb = in_sizes[17];
    int nc = in_sizes[19];
    float* out = (float*)d_out;
    float invn = 1.0f/(float)n;

    void *p_lin1, *p_lin2, *p_conv, *p_lin3, *p_stats;
    cudaGetSymbolAddress(&p_lin1, d_lin1);
    cudaGetSymbolAddress(&p_lin2, d_lin2);
    cudaGetSymbolAddress(&p_conv, d_conv);
    cudaGetSymbolAddress(&p_lin3, d_lin3);
    cudaGetSymbolAddress(&p_stats, d_stats);

    static bool attr_done = false;
    if (!attr_done) {
        cudaFuncSetAttribute(k_conv, cudaFuncAttributeMaxDynamicSharedMemorySize, CV_SMEM);
        cudaFuncSetAttribute(k_lin2, cudaFuncAttributeMaxDynamicSharedMemorySize, L2_SMEM);
        cudaFuncSetAttribute(k_lin3, cudaFuncAttributeMaxDynamicSharedMemorySize, L3_SMEM);
        attr_done = true;
    }

    int nblk = (n + 255) / 256;
    int gblk = (n + 127) / 128;
    k_zero<<<512, 256>>>(out + (size_t)n*64, nb, nc);
    k_wprep<<<144, 256>>>(wc);
    k_scatter<<<nblk, 256>>>(points, pcyl, binv, cinv, n);
    k_lin1<<<nblk, 256>>>(points, pcyl, cylidx, bevidx, binv, cinv, w1, n);
    k_stats<<<512, 256>>>((const float*)p_lin1, n, 64, 6, (float*)p_stats + 0,
                          g1, b1, invn, 0, 0);
    k_lin2<<<gblk, 256, L2_SMEM>>>(w2, n);
    k_stats<<<512, 256>>>((const float*)p_lin2, n, 128, 7, (float*)p_stats + 128,
                          g2, b2, invn, 128, 1);
    k_cylmax<<<nblk, 256>>>(points, cylidx, n);
    dim3 cg(3, 64, 4);
    k_conv<<<cg, 256, CV_SMEM>>>();
    k_stats<<<512, 256>>>((const float*)p_conv, 4*512*48, 64, 6, (float*)p_stats + 384,
                          gc, bc, 1.0f/98304.0f, 384, 2);
    k_lin3<<<gblk, 256, L3_SMEM>>>(points, cylidx, w3, n);
    k_stats<<<512, 256>>>((const float*)p_lin3, n, 64, 6, (float*)p_stats + 512,
                          g3, b3, invn, 512, 3);
    int vblk = (nb + 255) / 256;
    k_final<<<nblk + vblk, 256>>>(binv, bcoord, out, n, nb, nblk);
}

// round 9
// speedup vs baseline: 1.2221x; 1.2221x over previous
#include <cuda_runtime.h>
#include <math.h>

typedef unsigned long long ull;
typedef unsigned int uint;

// ---------------- problem constants ----------------
#define NPTS_MAX 200000
#define NB_MAX   220000
#define NC_MAX   98304
#define IMG_ELEMS (4*512*48*64)

#define CVS0 (6.2831853f/512.0f)
#define CVS1 0.125f
#define CR0  (-3.14159265f)
#define CR1  (-2.0f)

// ---------------- scratch ----------------
__device__ float d_lin1[(size_t)NPTS_MAX*64];
__device__ float d_lin2[(size_t)NPTS_MAX*128];
__device__ float d_lin3[(size_t)NPTS_MAX*64];
__device__ float d_dense[IMG_ELEMS];
__device__ float d_conv[IMG_ELEMS];
__device__ float d_bevsum[NB_MAX*4];
__device__ float d_cylsum[NC_MAX*4];
__device__ float d_stats[1024];
__device__ float d_bn[1024];  // lin1 a@0 c@64; lin2 a@128 c@256; conv a@384 c@448; lin3 a@512 c@576
__device__ unsigned d_ctr[8];
__device__ float d_wt_hi[3*192*64];   // [dy][dx*64+cin][f], tf32-valued fp32
__device__ uint  d_wcb_h[3*96*64];    // [dy][kpair][f], packed bf16(hi) pairs
__device__ uint  d_wcb_l[3*96*64];    // packed bf16(lo) pairs

// ---------------- helpers ----------------
__device__ __forceinline__ ull pk2(float v) {
    ull r; unsigned u = __float_as_uint(v);
    asm("mov.b64 %0, {%1, %1};" : "=l"(r) : "r"(u));
    return r;
}
__device__ __forceinline__ void ffma2(ull& d, ull a, ull b) {
    asm("fma.rn.f32x2 %0, %1, %2, %0;" : "+l"(d) : "l"(a), "l"(b));
}
__device__ __forceinline__ uint tf32(float f) {
    uint r; asm("cvt.rna.tf32.f32 %0, %1;" : "=r"(r) : "f"(f)); return r;
}
__device__ __forceinline__ void tf32split(float v, float& hi, float& lo) {
    uint h = tf32(v);
    hi = __uint_as_float(h);
    lo = v - hi;
}
// pack (k even -> low half, k odd -> high half)
__device__ __forceinline__ uint pkbf2(float ev, float od) {
    uint r; asm("cvt.rn.bf16x2.f32 %0, %1, %2;" : "=r"(r) : "f"(od), "f"(ev)); return r;
}
__device__ __forceinline__ void mma_tf32(float* c, uint a0, uint a1, uint a2, uint a3, uint b0, uint b1) {
    asm volatile("mma.sync.aligned.m16n8k8.row.col.f32.tf32.tf32.f32 "
                 "{%0,%1,%2,%3},{%4,%5,%6,%7},{%8,%9},{%0,%1,%2,%3};"
                 : "+f"(c[0]), "+f"(c[1]), "+f"(c[2]), "+f"(c[3])
                 : "r"(a0), "r"(a1), "r"(a2), "r"(a3), "r"(b0), "r"(b1));
}
__device__ __forceinline__ void mma_bf16(float* c, uint a0, uint a1, uint a2, uint a3, uint b0, uint b1) {
    asm volatile("mma.sync.aligned.m16n8k16.row.col.f32.bf16.bf16.f32 "
                 "{%0,%1,%2,%3},{%4,%5,%6,%7},{%8,%9},{%0,%1,%2,%3};"
                 : "+f"(c[0]), "+f"(c[1]), "+f"(c[2]), "+f"(c[3])
                 : "r"(a0), "r"(a1), "r"(a2), "r"(a3), "r"(b0), "r"(b1));
}

// ---------------- utility kernels ----------------
__global__ void __launch_bounds__(256) k_zero(float* outbev, int nb, int nc) {
    size_t tid = (size_t)blockIdx.x * blockDim.x + threadIdx.x;
    size_t stride = (size_t)gridDim.x * blockDim.x;
    float4 z = make_float4(0.f, 0.f, 0.f, 0.f);
    float4* p = (float4*)d_dense;
    for (size_t i = tid; i < IMG_ELEMS/4; i += stride) p[i] = z;
    float4* q = (float4*)outbev;
    size_t obw = (size_t)nb * 16;
    for (size_t i = tid; i < obw; i += stride) q[i] = z;
    float4* bs = (float4*)d_bevsum;
    for (size_t i = tid; i < (size_t)nb; i += stride) bs[i] = z;
    float4* cs = (float4*)d_cylsum;
    for (size_t i = tid; i < (size_t)nc; i += stride) cs[i] = z;
    if (tid < 256) ((float4*)d_stats)[tid] = z;
    if (tid < 8) d_ctr[tid] = 0u;
}

// conv weight prep: wc[f][cin][dy][dx] -> d_wt_hi[dy][dx*64+cin][f] + packed bf16 pairs
__global__ void k_wprep(const float* __restrict__ wc) {
    int t = blockIdx.x*256 + threadIdx.x;
    if (t >= 18432) return;
    int f = t & 63;
    int q = t >> 6;              // 0..287
    int cinp = q & 31;
    int dxy = q >> 5;            // 0..8
    int dx = dxy % 3, dy = dxy / 3;
    int cin0 = cinp*2;
    float v0 = wc[(size_t)f*576 + cin0*9     + dy*3 + dx];
    float v1 = wc[(size_t)f*576 + (cin0+1)*9 + dy*3 + dx];
    float h0, l0, h1, l1;
    tf32split(v0, h0, l0);
    tf32split(v1, h1, l1);
    d_wt_hi[dy*12288 + (dx*64+cin0)*64 + f]   = h0;
    d_wt_hi[dy*12288 + (dx*64+cin0+1)*64 + f] = h1;
    d_wcb_h[dy*6144 + (dx*32+cinp)*64 + f] = pkbf2(h0, h1);
    d_wcb_l[dy*6144 + (dx*32+cinp)*64 + f] = pkbf2(l0, l1);
}

__global__ void k_scatter(const float* __restrict__ pts, const float* __restrict__ pcyl,
                          const int* __restrict__ binv, const int* __restrict__ cinv, int n) {
    int i = blockIdx.x*blockDim.x + threadIdx.x;
    if (i >= n) return;
    float x = pts[(size_t)i*5+1], y = pts[(size_t)i*5+2], z = pts[(size_t)i*5+3];
    int bi = binv[i], ci = cinv[i];
    atomicAdd(&d_bevsum[bi*4+0], x);
    atomicAdd(&d_bevsum[bi*4+1], y);
    atomicAdd(&d_bevsum[bi*4+2], z);
    atomicAdd(&d_bevsum[bi*4+3], 1.0f);
    float p0 = pcyl[(size_t)i*3], p1 = pcyl[(size_t)i*3+1], p2 = pcyl[(size_t)i*3+2];
    atomicAdd(&d_cylsum[ci*4+0], p0);
    atomicAdd(&d_cylsum[ci*4+1], p1);
    atomicAdd(&d_cylsum[ci*4+2], p2);
    atomicAdd(&d_cylsum[ci*4+3], 1.0f);
}

__global__ void __launch_bounds__(256) k_lin1(
        const float* __restrict__ pts, const float* __restrict__ pcyl,
        const float* __restrict__ cylidx, const float* __restrict__ bevidx,
        const int* __restrict__ binv, const int* __restrict__ cinv,
        const float* __restrict__ w1, int n) {
    __shared__ float sw[16*64];
    for (int t = threadIdx.x; t < 1024; t += 256) { int o = t >> 4, k = t & 15; sw[k*64+o] = w1[t]; }
    __syncthreads();
    int i = blockIdx.x*256 + threadIdx.x;
    if (i >= n) return;
    float x = pts[(size_t)i*5+1], y = pts[(size_t)i*5+2], z = pts[(size_t)i*5+3], it = pts[(size_t)i*5+4];
    float phi = pcyl[(size_t)i*3], zc = pcyl[(size_t)i*3+1], rho = pcyl[(size_t)i*3+2];
    float bix = bevidx[2*(size_t)i], biy = bevidx[2*(size_t)i+1];
    float cix = cylidx[2*(size_t)i], ciy = cylidx[2*(size_t)i+1];
    int bi = binv[i], ci = cinv[i];
    float bcnt = d_bevsum[bi*4+3];
    float bmx = d_bevsum[bi*4]/bcnt, bmy = d_bevsum[bi*4+1]/bcnt;
    float ccnt = d_cylsum[ci*4+3];
    float cm0 = d_cylsum[ci*4]/ccnt, cm1 = d_cylsum[ci*4+1]/ccnt;
    float f[16];
    f[0]=x; f[1]=y; f[2]=z; f[3]=phi; f[4]=zc; f[5]=rho;
    f[6] = x - ((floorf(bix)+0.5f)*0.32f + 0.0f);
    f[7] = y - ((floorf(biy)+0.5f)*0.32f + (-40.0f));
    f[8] = phi - ((floorf(cix)+0.5f)*CVS0 + CR0);
    f[9] = zc  - ((floorf(ciy)+0.5f)*CVS1 + CR1);
    f[10]= x - bmx; f[11]= y - bmy;
    f[12]= phi - cm0; f[13]= zc - cm1;
    f[14]= sqrtf(x*x + y*y + z*z);
    f[15]= it;
    ull acc[32];
    #pragma unroll
    for (int o = 0; o < 32; o++) acc[o] = 0ULL;
    #pragma unroll
    for (int k = 0; k < 16; k++) {
        ull v = pk2(f[k]);
        const ulonglong2* wr = (const ulonglong2*)&sw[k*64];
        #pragma unroll
        for (int m = 0; m < 16; m++) {
            ulonglong2 w = wr[m];
            ffma2(acc[2*m], v, w.x); ffma2(acc[2*m+1], v, w.y);
        }
    }
    ulonglong2* op = (ulonglong2*)&d_lin1[(size_t)i*64];
    #pragma unroll
    for (int m = 0; m < 16; m++) op[m] = make_ulonglong2(acc[2*m], acc[2*m+1]);
}

// per-channel sum/sumsq + last-block BN finalize
__global__ void k_stats(const float* __restrict__ data, int rows, int C, int shift,
                        float* __restrict__ out, const float* __restrict__ g,
                        const float* __restrict__ b, float invn, int bbase, int ctr_idx) {
    int tid = threadIdx.x;
    int c = tid & (C-1);
    int sub = tid >> shift;
    int rpb = 256 >> shift;
    float s = 0.f, s2 = 0.f;
    for (long r = (long)blockIdx.x*rpb + sub; r < rows; r += (long)gridDim.x*rpb) {
        float v = data[(size_t)r*C + c];
        s += v; s2 += v*v;
    }
    __shared__ float sh[512];
    sh[tid] = s; sh[256+tid] = s2;
    __syncthreads();
    if (sub == 0) {
        for (int j = 1; j < rpb; j++) { s += sh[j*C + c]; s2 += sh[256 + j*C + c]; }
        atomicAdd(&out[c], s);
        atomicAdd(&out[C+c], s2);
    }
    __threadfence();
    __syncthreads();
    __shared__ unsigned s_ord;
    if (tid == 0) s_ord = atomicAdd(&d_ctr[ctr_idx], 1u);
    __syncthreads();
    if (s_ord == gridDim.x - 1 && tid < C) {
        float m = __ldcg(&out[tid]) * invn;
        float v = __ldcg(&out[C+tid]) * invn - m*m;
        float a = g[tid] * rsqrtf(v + 1e-3f);
        d_bn[bbase + tid]     = a;
        d_bn[bbase + C + tid] = b[tid] - m*a;
    }
}

// ---------------- lin2: single-tf32 MMA GEMM  [N,64] @ [64,128] ----------------
#define L2_SMEM (17408*4)
__global__ void __launch_bounds__(256) k_lin2(const float* __restrict__ w2, int n) {
    extern __shared__ float dsm[];
    float* s_a = dsm;                // [p][k] pitch 68
    float* s_b = dsm + 128*68;       // [k][o] pitch 136
    __shared__ float sa[64], sc[64];
    int tid = threadIdx.x;
    if (tid < 64) { sa[tid] = d_bn[tid]; sc[tid] = d_bn[64+tid]; }
    for (int t = tid; t < 8192; t += 256) {
        int o = t >> 6, k = t & 63;
        s_b[k*136 + o] = __uint_as_float(tf32(w2[t]));
    }
    __syncthreads();
    int pbase = blockIdx.x*128;
    for (int idx = tid; idx < 128*16; idx += 256) {
        int lp = idx >> 4, kq = idx & 15;
        int p = pbase + lp, k = kq*4;
        float4 v = make_float4(0.f,0.f,0.f,0.f);
        if (p < n) v = *(const float4*)&d_lin1[(size_t)p*64 + k];
        uint4 tv;
        tv.x = tf32(fmaxf(fmaf(v.x, sa[k+0], sc[k+0]), 0.f));
        tv.y = tf32(fmaxf(fmaf(v.y, sa[k+1], sc[k+1]), 0.f));
        tv.z = tf32(fmaxf(fmaf(v.z, sa[k+2], sc[k+2]), 0.f));
        tv.w = tf32(fmaxf(fmaf(v.w, sa[k+3], sc[k+3]), 0.f));
        *(uint4*)&s_a[lp*68 + k] = tv;
    }
    __syncthreads();
    int wid = tid >> 5, lane = tid & 31;
    int g = lane >> 2, tg = lane & 3;
    int m0 = wid*16;
    const uint* ua = (const uint*)s_a;
    const uint* ub = (const uint*)s_b;
    float c[16][4];
    #pragma unroll
    for (int nt = 0; nt < 16; nt++)
        #pragma unroll
        for (int j = 0; j < 4; j++) c[nt][j] = 0.f;
    #pragma unroll
    for (int kc = 0; kc < 8; kc++) {
        int k0 = kc*8;
        uint a0 = ua[(m0+g)*68   + k0 + tg];
        uint a1 = ua[(m0+g+8)*68 + k0 + tg];
        uint a2 = ua[(m0+g)*68   + k0 + tg + 4];
        uint a3 = ua[(m0+g+8)*68 + k0 + tg + 4];
        #pragma unroll
        for (int nt = 0; nt < 16; nt++) {
            uint b0 = ub[(k0+tg)*136   + nt*8 + g];
            uint b1 = ub[(k0+tg+4)*136 + nt*8 + g];
            mma_tf32(c[nt], a0, a1, a2, a3, b0, b1);
        }
    }
    __syncthreads();
    float* stage = dsm;              // [p][o] pitch 132
    #pragma unroll
    for (int nt = 0; nt < 16; nt++) {
        int n0 = nt*8 + tg*2;
        *(float2*)&stage[(m0+g)*132   + n0] = make_float2(c[nt][0], c[nt][1]);
        *(float2*)&stage[(m0+g+8)*132 + n0] = make_float2(c[nt][2], c[nt][3]);
    }
    __syncthreads();
    for (int idx = tid; idx < 128*32; idx += 256) {
        int lp = idx >> 5, q = idx & 31;
        int p = pbase + lp;
        if (p < n)
            *(float4*)&d_lin2[(size_t)p*128 + q*4] = *(const float4*)&stage[lp*132 + q*4];
    }
}

// segment-max of bn_relu(lin2[:, :64]) into dense image
__global__ void k_cylmax(const float* __restrict__ pts, const float* __restrict__ cylidx, int n) {
    __shared__ float sa[64], sc[64];
    if (threadIdx.x < 64) { sa[threadIdx.x] = d_bn[128+threadIdx.x]; sc[threadIdx.x] = d_bn[256+threadIdx.x]; }
    __syncthreads();
    int i = blockIdx.x*blockDim.x + threadIdx.x;
    if (i >= n) return;
    int b = (int)pts[(size_t)i*5];
    int iy = (int)floorf(cylidx[2*(size_t)i]);   iy = max(0, min(iy, 511));
    int ix = (int)floorf(cylidx[2*(size_t)i+1]); ix = max(0, min(ix, 47));
    unsigned* dst = (unsigned*)&d_dense[(((size_t)b*512 + iy)*48 + ix)*64];
    const float4* src = (const float4*)&d_lin2[(size_t)i*128];
    #pragma unroll
    for (int j = 0; j < 16; j++) {
        float4 v = src[j];
        int c = j*4;
        float r0 = fmaxf(fmaf(v.x, sa[c+0], sc[c+0]), 0.f);
        float r1 = fmaxf(fmaf(v.y, sa[c+1], sc[c+1]), 0.f);
        float r2 = fmaxf(fmaf(v.z, sa[c+2], sc[c+2]), 0.f);
        float r3 = fmaxf(fmaf(v.w, sa[c+3], sc[c+3]), 0.f);
        atomicMax(dst+c+0, __float_as_uint(r0));
        atomicMax(dst+c+1, __float_as_uint(r1));
        atomicMax(dst+c+2, __float_as_uint(r2));
        atomicMax(dst+c+3, __float_as_uint(r3));
    }
}

// ---------------- conv: tf32 hi-MMA + ONE bf16 k16 correction MMA ----------------
// tile 16x8 positions (M=128), N=64 out-ch, K = 3 dy stages x 192
// smem floats: s_ih[180*68] | s_cah[180*36](u32) | s_cal[180*36] | s_wh[192*72] | s_cwh[96*72] | s_cwl[96*72]
#define CV_SMEM ((180*68 + 180*36*2 + 192*72 + 96*72*2)*4)
__global__ void __launch_bounds__(256) k_conv() {
    extern __shared__ float dsm[];
    float* s_ih  = dsm;                       // [pos][cin] pitch 68 (tf32 hi, fp32)
    uint*  s_cah = (uint*)(dsm + 180*68);     // [pos][cinpair] pitch 36, bf16(hi) pairs
    uint*  s_cal = s_cah + 180*36;
    float* s_wh  = (float*)(s_cal + 180*36);  // [k][f] pitch 72
    uint*  s_cwh = (uint*)(s_wh + 192*72);    // [kpair][f] pitch 72
    uint*  s_cwl = s_cwh + 96*72;
    int x0 = blockIdx.x*16, y0 = blockIdx.y*8, bb = blockIdx.z;
    int tid = threadIdx.x;
    // input halo: tf32 hi (fp32) + packed bf16 hi/lo pairs
    for (int idx = tid; idx < 180*16; idx += 256) {
        int pos = idx >> 4, c4 = idx & 15;
        int hy = pos / 18, hx = pos - hy*18;
        int gy = y0 + hy - 1, gx = x0 + hx - 1;
        float4 v = make_float4(0.f,0.f,0.f,0.f);
        if (gy >= 0 && gy < 512 && gx >= 0 && gx < 48)
            v = *(const float4*)&d_dense[(((size_t)bb*512 + gy)*48 + gx)*64 + c4*4];
        float h0,l0,h1,l1,h2,l2,h3,l3;
        tf32split(v.x, h0, l0); tf32split(v.y, h1, l1);
        tf32split(v.z, h2, l2); tf32split(v.w, h3, l3);
        *(float4*)&s_ih[pos*68 + c4*4] = make_float4(h0,h1,h2,h3);
        s_cah[pos*36 + c4*2]   = pkbf2(h0, h1);
        s_cah[pos*36 + c4*2+1] = pkbf2(h2, h3);
        s_cal[pos*36 + c4*2]   = pkbf2(l0, l1);
        s_cal[pos*36 + c4*2+1] = pkbf2(l2, l3);
    }
    int wid = tid >> 5, lane = tid & 31;
    int g = lane >> 2, tg = lane & 3;
    const uint* uih = (const uint*)s_ih;
    const uint* uwh = (const uint*)s_wh;
    float c[8][4];
    #pragma unroll
    for (int nt = 0; nt < 8; nt++)
        #pragma unroll
        for (int j = 0; j < 4; j++) c[nt][j] = 0.f;
    for (int dy = 0; dy < 3; dy++) {
        __syncthreads();
        for (int t = tid; t < 12288; t += 256) {
            int k = t >> 6, f = t & 63;
            s_wh[k*72 + f] = d_wt_hi[dy*12288 + t];
        }
        for (int t = tid; t < 6144; t += 256) {
            int kp = t >> 6, f = t & 63;
            s_cwh[kp*72 + f] = d_wcb_h[dy*6144 + t];
            s_cwl[kp*72 + f] = d_wcb_l[dy*6144 + t];
        }
        __syncthreads();
        int hbase = (wid + dy)*18;
        #pragma unroll
        for (int ch = 0; ch < 24; ch++) {
            int dx = ch >> 3, cin0 = (ch & 7)*8;
            int k0 = ch*8, kp0 = ch*4;
            int cp0 = (ch & 7)*4;
            int pos0 = hbase + g + dx, pos1 = pos0 + 8;
            uint a0 = uih[pos0*68 + cin0 + tg];
            uint a1 = uih[pos1*68 + cin0 + tg];
            uint a2 = uih[pos0*68 + cin0 + tg + 4];
            uint a3 = uih[pos1*68 + cin0 + tg + 4];
            uint ac0 = s_cah[pos0*36 + cp0 + tg];
            uint ac1 = s_cah[pos1*36 + cp0 + tg];
            uint ac2 = s_cal[pos0*36 + cp0 + tg];
            uint ac3 = s_cal[pos1*36 + cp0 + tg];
            #pragma unroll
            for (int nt = 0; nt < 8; nt++) {
                int col = nt*8 + g;
                uint b0 = uwh[(k0+tg)*72   + col];
                uint b1 = uwh[(k0+tg+4)*72 + col];
                uint bc0 = s_cwl[(kp0+tg)*72 + col];   // ext-k 0..7: Ah x Bl
                uint bc1 = s_cwh[(kp0+tg)*72 + col];   // ext-k 8..15: Al x Bh
                mma_tf32(c[nt], a0, a1, a2, a3, b0, b1);
                mma_bf16(c[nt], ac0, ac1, ac2, ac3, bc0, bc1);
            }
        }
    }
    int gy = y0 + wid;
    size_t rb = ((size_t)bb*512 + gy)*48;
    #pragma unroll
    for (int nt = 0; nt < 8; nt++) {
        int col = nt*8 + tg*2;
        *(float2*)&d_conv[(rb + x0 + g)*64 + col]     = make_float2(c[nt][0], c[nt][1]);
        *(float2*)&d_conv[(rb + x0 + g + 8)*64 + col] = make_float2(c[nt][2], c[nt][3]);
    }
}

// ---------------- lin3: single-tf32 MMA GEMM [N,128] @ [128,64], gather inlined ----------------
#define L3_SMEM ((128*132 + 128*72)*4)
__global__ void __launch_bounds__(256) k_lin3(const float* __restrict__ pts,
        const float* __restrict__ cylidx, const float* __restrict__ w3, int n) {
    extern __shared__ float dsm[];
    float* s_a = dsm;                 // [p][k] pitch 132
    float* s_b = dsm + 128*132;       // [k][o] pitch 72
    __shared__ float pa[64], pc[64], ca[64], cs[64];
    __shared__ float s_w4[4][128];
    __shared__ int   s_o4[4][128];
    int tid = threadIdx.x;
    if (tid < 64) {
        pa[tid] = d_bn[192+tid]; pc[tid] = d_bn[320+tid];
        ca[tid] = d_bn[384+tid]; cs[tid] = d_bn[448+tid];
    }
    for (int t = tid; t < 8192; t += 256) {
        int o = t >> 7, k = t & 127;
        s_b[k*72 + o] = __uint_as_float(tf32(w3[t]));
    }
    int pbase = blockIdx.x*128;
    if (tid < 128) {
        int p = pbase + tid;
        int i = (p < n) ? p : (n-1);
        float yq = cylidx[2*(size_t)i], xq = cylidx[2*(size_t)i+1];
        int y0i = (int)floorf(yq); int y1i = min(y0i+1, 511); y0i = min(max(y0i,0), 511);
        int x0i = (int)floorf(xq); int x1i = min(x0i+1, 47);  x0i = min(max(x0i,0), 47);
        s_w4[0][tid] = ((float)x1i - xq)*((float)y1i - yq);
        s_w4[1][tid] = ((float)x1i - xq)*(yq - (float)y0i);
        s_w4[2][tid] = (xq - (float)x0i)*((float)y1i - yq);
        s_w4[3][tid] = (xq - (float)x0i)*(yq - (float)y0i);
        int b = (int)pts[(size_t)i*5];
        int base = b*512*48*64;
        s_o4[0][tid] = base + (y0i*48 + x0i)*64;
        s_o4[1][tid] = base + (y1i*48 + x0i)*64;
        s_o4[2][tid] = base + (y0i*48 + x1i)*64;
        s_o4[3][tid] = base + (y1i*48 + x1i)*64;
    }
    __syncthreads();
    for (int idx = tid; idx < 128*16; idx += 256) {
        int lp = idx >> 4, kq = idx & 15;
        int p = pbase + lp, k = kq*4;
        float4 v = make_float4(0.f,0.f,0.f,0.f);
        if (p < n) {
            v = *(const float4*)&d_lin2[(size_t)p*128 + 64 + k];
            v.x = fmaxf(fmaf(v.x, pa[k+0], pc[k+0]), 0.f);
            v.y = fmaxf(fmaf(v.y, pa[k+1], pc[k+1]), 0.f);
            v.z = fmaxf(fmaf(v.z, pa[k+2], pc[k+2]), 0.f);
            v.w = fmaxf(fmaf(v.w, pa[k+3], pc[k+3]), 0.f);
        }
        uint4 tv;
        tv.x = tf32(v.x); tv.y = tf32(v.y); tv.z = tf32(v.z); tv.w = tf32(v.w);
        *(uint4*)&s_a[lp*132 + k] = tv;
    }
    for (int idx = tid; idx < 128*16; idx += 256) {
        int lp = idx >> 4, kq = idx & 15;
        int p = pbase + lp, c = kq*4;
        float4 r = make_float4(0.f,0.f,0.f,0.f);
        if (p < n) {
            float wa = s_w4[0][lp], wb = s_w4[1][lp], wcw = s_w4[2][lp], wd = s_w4[3][lp];
            float4 av = *(const float4*)&d_conv[s_o4[0][lp] + c];
            float4 bv = *(const float4*)&d_conv[s_o4[1][lp] + c];
            float4 cv = *(const float4*)&d_conv[s_o4[2][lp] + c];
            float4 dv = *(const float4*)&d_conv[s_o4[3][lp] + c];
            r.x = wa*fmaxf(fmaf(av.x, ca[c+0], cs[c+0]),0.f) + wb*fmaxf(fmaf(bv.x, ca[c+0], cs[c+0]),0.f)
                + wcw*fmaxf(fmaf(cv.x, ca[c+0], cs[c+0]),0.f) + wd*fmaxf(fmaf(dv.x, ca[c+0], cs[c+0]),0.f);
            r.y = wa*fmaxf(fmaf(av.y, ca[c+1], cs[c+1]),0.f) + wb*fmaxf(fmaf(bv.y, ca[c+1], cs[c+1]),0.f)
                + wcw*fmaxf(fmaf(cv.y, ca[c+1], cs[c+1]),0.f) + wd*fmaxf(fmaf(dv.y, ca[c+1], cs[c+1]),0.f);
            r.z = wa*fmaxf(fmaf(av.z, ca[c+2], cs[c+2]),0.f) + wb*fmaxf(fmaf(bv.z, ca[c+2], cs[c+2]),0.f)
                + wcw*fmaxf(fmaf(cv.z, ca[c+2], cs[c+2]),0.f) + wd*fmaxf(fmaf(dv.z, ca[c+2], cs[c+2]),0.f);
            r.w = wa*fmaxf(fmaf(av.w, ca[c+3], cs[c+3]),0.f) + wb*fmaxf(fmaf(bv.w, ca[c+3], cs[c+3]),0.f)
                + wcw*fmaxf(fmaf(cv.w, ca[c+3], cs[c+3]),0.f) + wd*fmaxf(fmaf(dv.w, ca[c+3], cs[c+3]),0.f);
        }
        uint4 tv;
        tv.x = tf32(r.x); tv.y = tf32(r.y); tv.z = tf32(r.z); tv.w = tf32(r.w);
        *(uint4*)&s_a[lp*132 + 64 + c] = tv;
    }
    __syncthreads();
    int wid = tid >> 5, lane = tid & 31;
    int g = lane >> 2, tg = lane & 3;
    int m0 = wid*16;
    const uint* ua = (const uint*)s_a;
    const uint* ub = (const uint*)s_b;
    float c[8][4];
    #pragma unroll
    for (int nt = 0; nt < 8; nt++)
        #pragma unroll
        for (int j = 0; j < 4; j++) c[nt][j] = 0.f;
    #pragma unroll
    for (int kc = 0; kc < 16; kc++) {
        int k0 = kc*8;
        uint a0 = ua[(m0+g)*132   + k0 + tg];
        uint a1 = ua[(m0+g+8)*132 + k0 + tg];
        uint a2 = ua[(m0+g)*132   + k0 + tg + 4];
        uint a3 = ua[(m0+g+8)*132 + k0 + tg + 4];
        #pragma unroll
        for (int nt = 0; nt < 8; nt++) {
            uint b0 = ub[(k0+tg)*72   + nt*8 + g];
            uint b1 = ub[(k0+tg+4)*72 + nt*8 + g];
            mma_tf32(c[nt], a0, a1, a2, a3, b0, b1);
        }
    }
    __syncthreads();
    float* stage = dsm;              // [p][o] pitch 68
    #pragma unroll
    for (int nt = 0; nt < 8; nt++) {
        int n0 = nt*8 + tg*2;
        *(float2*)&stage[(m0+g)*68   + n0] = make_float2(c[nt][0], c[nt][1]);
        *(float2*)&stage[(m0+g+8)*68 + n0] = make_float2(c[nt][2], c[nt][3]);
    }
    __syncthreads();
    for (int idx = tid; idx < 128*16; idx += 256) {
        int lp = idx >> 4, q = idx & 15;
        int p = pbase + lp;
        if (p < n)
            *(float4*)&d_lin3[(size_t)p*64 + q*4] = *(const float4*)&stage[lp*68 + q*4];
    }
}

// final: bn_relu(lin3) -> out; atomicMax into bev_max; extra blocks do voxel coords
__global__ void k_final(const int* __restrict__ binv, const int* __restrict__ bcoord,
                        float* __restrict__ out, int n, int nb, int nblk) {
    if (blockIdx.x >= nblk) {
        int i = (blockIdx.x - nblk)*blockDim.x + threadIdx.x;
        if (i < nb) {
            int c = bcoord[i];
            int vb = c / 55000;
            int r  = c % 55000;
            int vx = r / 250;
            int vy = r % 250;
            float* o = out + (size_t)n*64 + (size_t)nb*64 + (size_t)i*4;
            o[0] = (float)vb; o[1] = 0.f; o[2] = (float)vy; o[3] = (float)vx;
        }
        return;
    }
    __shared__ float sa[64], sc[64];
    if (threadIdx.x < 64) { sa[threadIdx.x] = d_bn[512+threadIdx.x]; sc[threadIdx.x] = d_bn[576+threadIdx.x]; }
    __syncthreads();
    int i = blockIdx.x*blockDim.x + threadIdx.x;
    if (i >= n) return;
    int bi = binv[i];
    const float4* src = (const float4*)&d_lin3[(size_t)i*64];
    float4* dst = (float4*)(out + (size_t)i*64);
    unsigned* mx = (unsigned*)(out + (size_t)n*64 + (size_t)bi*64);
    #pragma unroll
    for (int j = 0; j < 16; j++) {
        float4 v = src[j];
        int c = j*4;
        float r0 = fmaxf(fmaf(v.x, sa[c+0], sc[c+0]), 0.f);
        float r1 = fmaxf(fmaf(v.y, sa[c+1], sc[c+1]), 0.f);
        float r2 = fmaxf(fmaf(v.z, sa[c+2], sc[c+2]), 0.f);
        float r3 = fmaxf(fmaf(v.w, sa[c+3], sc[c+3]), 0.f);
        dst[j] = make_float4(r0, r1, r2, r3);
        atomicMax(mx+c+0, __float_as_uint(r0));
        atomicMax(mx+c+1, __float_as_uint(r1));
        atomicMax(mx+c+2, __float_as_uint(r2));
        atomicMax(mx+c+3, __float_as_uint(r3));
    }
}

// ---------------- launcher ----------------
extern "C" void kernel_launch(void* const* d_in, const int* in_sizes, int n_in,
                              void* d_out, int out_size) {
    const float* points = (const float*)d_in[0];
    const float* pcyl   = (const float*)d_in[1];
    const float* cylidx = (const float*)d_in[2];
    const float* bevidx = (const float*)d_in[3];
    const float* w1 = (const float*)d_in[4];
    const float* g1 = (const float*)d_in[5];
    const float* b1 = (const float*)d_in[6];
    const float* w2 = (const float*)d_in[7];
    const float* g2 = (const float*)d_in[8];
    const float* b2 = (const float*)d_in[9];
    const float* wc = (const float*)d_in[10];
    const float* gc = (const float*)d_in[11];
    const float* bc = (const float*)d_in[12];
    const float* w3 = (const float*)d_in[13];
    const float* g3 = (const float*)d_in[14];
    const float* b3 = (const float*)d_in[15];
    const int* binv   = (const int*)d_in[16];
    const int* bcoord = (const int*)d_in[17];
    const int* cinv   = (const int*)d_in[18];

    int n  = in_sizes[0] / 5;
    int nb = in_sizes[17];
    int nc = in_sizes[19];
    float* out = (float*)d_out;
    float invn = 1.0f/(float)n;

    void *p_lin1, *p_lin2, *p_conv, *p_lin3, *p_stats;
    cudaGetSymbolAddress(&p_lin1, d_lin1);
    cudaGetSymbolAddress(&p_lin2, d_lin2);
    cudaGetSymbolAddress(&p_conv, d_conv);
    cudaGetSymbolAddress(&p_lin3, d_lin3);
    cudaGetSymbolAddress(&p_stats, d_stats);

    static bool attr_done = false;
    if (!attr_done) {
        cudaFuncSetAttribute(k_conv, cudaFuncAttributeMaxDynamicSharedMemorySize, CV_SMEM);
        cudaFuncSetAttribute(k_lin2, cudaFuncAttributeMaxDynamicSharedMemorySize, L2_SMEM);
        cudaFuncSetAttribute(k_lin3, cudaFuncAttributeMaxDynamicSharedMemorySize, L3_SMEM);
        attr_done = true;
    }

    int nblk = (n + 255) / 256;
    int gblk = (n + 127) / 128;
    k_zero<<<512, 256>>>(out + (size_t)n*64, nb, nc);
    k_wprep<<<72, 256>>>(wc);
    k_scatter<<<nblk, 256>>>(points, pcyl, binv, cinv, n);
    k_lin1<<<nblk, 256>>>(points, pcyl, cylidx, bevidx, binv, cinv, w1, n);
    k_stats<<<512, 256>>>((const float*)p_lin1, n, 64, 6, (float*)p_stats + 0,
                          g1, b1, invn, 0, 0);
    k_lin2<<<gblk, 256, L2_SMEM>>>(w2, n);
    k_stats<<<512, 256>>>((const float*)p_lin2, n, 128, 7, (float*)p_stats + 128,
                          g2, b2, invn, 128, 1);
    k_cylmax<<<nblk, 256>>>(points, cylidx, n);
    dim3 cg(3, 64, 4);
    k_conv<<<cg, 256, CV_SMEM>>>();
    k_stats<<<512, 256>>>((const float*)p_conv, 4*512*48, 64, 6, (float*)p_stats + 384,
                          gc, bc, 1.0f/98304.0f, 384, 2);
    k_lin3<<<gblk, 256, L3_SMEM>>>(points, cylidx, w3, n);
    k_stats<<<512, 256>>>((const float*)p_lin3, n, 64, 6, (float*)p_stats + 512,
                          g3, b3, invn, 512, 3);
    int vblk = (nb + 255) / 256;
    k_final<<<nblk + vblk, 256>>>(binv, bcoord, out, n, nb, nblk);
}

// round 10
// speedup vs baseline: 1.2606x; 1.0315x over previous
#include <cuda_runtime.h>
#include <math.h>

typedef unsigned long long ull;
typedef unsigned int uint;

// ---------------- problem constants ----------------
#define NPTS_MAX 200000
#define NB_MAX   220000
#define NC_MAX   98304
#define IMG_ELEMS (4*512*48*64)

#define CVS0 (6.2831853f/512.0f)
#define CVS1 0.125f
#define CR0  (-3.14159265f)
#define CR1  (-2.0f)

// ---------------- scratch ----------------
__device__ float d_lin1[(size_t)NPTS_MAX*64];
__device__ float d_lin2[(size_t)NPTS_MAX*128];
__device__ float d_lin3[(size_t)NPTS_MAX*64];
__device__ float d_dense[IMG_ELEMS];
__device__ float d_conv[IMG_ELEMS];
__device__ float d_bevsum[NB_MAX*4];
__device__ float d_cylsum[NC_MAX*4];
__device__ float d_stats[1024];
__device__ float d_bn[1024];  // lin1 a@0 c@64; lin2 a@128 c@256; conv a@384 c@448; lin3 a@512 c@576
__device__ unsigned d_ctr[8];
__device__ float d_wt_hi[3*192*64];   // [dy][dx*64+cin][f], tf32-valued fp32
__device__ uint  d_wcb_h[3*96*64];    // [dy][kpair][f], packed bf16(hi) pairs
__device__ uint  d_wcb_l[3*96*64];    // packed bf16(lo) pairs

// ---------------- helpers ----------------
__device__ __forceinline__ ull pk2(float v) {
    ull r; unsigned u = __float_as_uint(v);
    asm("mov.b64 %0, {%1, %1};" : "=l"(r) : "r"(u));
    return r;
}
__device__ __forceinline__ void ffma2(ull& d, ull a, ull b) {
    asm("fma.rn.f32x2 %0, %1, %2, %0;" : "+l"(d) : "l"(a), "l"(b));
}
__device__ __forceinline__ uint tf32(float f) {
    uint r; asm("cvt.rna.tf32.f32 %0, %1;" : "=r"(r) : "f"(f)); return r;
}
__device__ __forceinline__ void tf32split(float v, float& hi, float& lo) {
    uint h = tf32(v);
    hi = __uint_as_float(h);
    lo = v - hi;
}
__device__ __forceinline__ uint pkbf2(float ev, float od) {
    uint r; asm("cvt.rn.bf16x2.f32 %0, %1, %2;" : "=r"(r) : "f"(od), "f"(ev)); return r;
}
__device__ __forceinline__ void mma_tf32(float* c, uint a0, uint a1, uint a2, uint a3, uint b0, uint b1) {
    asm volatile("mma.sync.aligned.m16n8k8.row.col.f32.tf32.tf32.f32 "
                 "{%0,%1,%2,%3},{%4,%5,%6,%7},{%8,%9},{%0,%1,%2,%3};"
                 : "+f"(c[0]), "+f"(c[1]), "+f"(c[2]), "+f"(c[3])
                 : "r"(a0), "r"(a1), "r"(a2), "r"(a3), "r"(b0), "r"(b1));
}
__device__ __forceinline__ void mma_bf16(float* c, uint a0, uint a1, uint a2, uint a3, uint b0, uint b1) {
    asm volatile("mma.sync.aligned.m16n8k16.row.col.f32.bf16.bf16.f32 "
                 "{%0,%1,%2,%3},{%4,%5,%6,%7},{%8,%9},{%0,%1,%2,%3};"
                 : "+f"(c[0]), "+f"(c[1]), "+f"(c[2]), "+f"(c[3])
                 : "r"(a0), "r"(a1), "r"(a2), "r"(a3), "r"(b0), "r"(b1));
}
// last-block BN finalize, shared pattern
__device__ __forceinline__ void bn_finalize_inline(int ctr_idx, unsigned nblocks, int tid,
                                                   int C, float invn, int sbase, int bbase,
                                                   const float* g, const float* b) {
    __threadfence();
    __shared__ unsigned s_ord;
    if (tid == 0) s_ord = atomicAdd(&d_ctr[ctr_idx], 1u);
    __syncthreads();
    if (s_ord == nblocks - 1 && tid < C) {
        float m = __ldcg(&d_stats[sbase + tid]) * invn;
        float v = __ldcg(&d_stats[sbase + C + tid]) * invn - m*m;
        float a = g[tid] * rsqrtf(v + 1e-3f);
        d_bn[bbase + tid]     = a;
        d_bn[bbase + C + tid] = b[tid] - m*a;
    }
}

// ---------------- utility kernels ----------------
// zero everything + conv weight prep fused
__global__ void __launch_bounds__(256) k_zero(float* outbev, int nb, int nc,
                                              const float* __restrict__ wc) {
    size_t tid = (size_t)blockIdx.x * blockDim.x + threadIdx.x;
    size_t stride = (size_t)gridDim.x * blockDim.x;
    if (tid < 18432) {
        int t = (int)tid;
        int f = t & 63;
        int q = t >> 6;
        int cinp = q & 31;
        int dxy = q >> 5;
        int dx = dxy % 3, dy = dxy / 3;
        int cin0 = cinp*2;
        float v0 = wc[(size_t)f*576 + cin0*9     + dy*3 + dx];
        float v1 = wc[(size_t)f*576 + (cin0+1)*9 + dy*3 + dx];
        float h0, l0, h1, l1;
        tf32split(v0, h0, l0);
        tf32split(v1, h1, l1);
        d_wt_hi[dy*12288 + (dx*64+cin0)*64 + f]   = h0;
        d_wt_hi[dy*12288 + (dx*64+cin0+1)*64 + f] = h1;
        d_wcb_h[dy*6144 + (dx*32+cinp)*64 + f] = pkbf2(h0, h1);
        d_wcb_l[dy*6144 + (dx*32+cinp)*64 + f] = pkbf2(l0, l1);
    }
    float4 z = make_float4(0.f, 0.f, 0.f, 0.f);
    float4* p = (float4*)d_dense;
    for (size_t i = tid; i < IMG_ELEMS/4; i += stride) p[i] = z;
    float4* q = (float4*)outbev;
    size_t obw = (size_t)nb * 16;
    for (size_t i = tid; i < obw; i += stride) q[i] = z;
    float4* bs = (float4*)d_bevsum;
    for (size_t i = tid; i < (size_t)nb; i += stride) bs[i] = z;
    float4* cs = (float4*)d_cylsum;
    for (size_t i = tid; i < (size_t)nc; i += stride) cs[i] = z;
    if (tid < 256) ((float4*)d_stats)[tid] = z;
    if (tid < 8) d_ctr[tid] = 0u;
}

__global__ void k_scatter(const float* __restrict__ pts, const float* __restrict__ pcyl,
                          const int* __restrict__ binv, const int* __restrict__ cinv, int n) {
    int i = blockIdx.x*blockDim.x + threadIdx.x;
    if (i >= n) return;
    float x = pts[(size_t)i*5+1], y = pts[(size_t)i*5+2], z = pts[(size_t)i*5+3];
    int bi = binv[i], ci = cinv[i];
    atomicAdd(&d_bevsum[bi*4+0], x);
    atomicAdd(&d_bevsum[bi*4+1], y);
    atomicAdd(&d_bevsum[bi*4+2], z);
    atomicAdd(&d_bevsum[bi*4+3], 1.0f);
    float p0 = pcyl[(size_t)i*3], p1 = pcyl[(size_t)i*3+1], p2 = pcyl[(size_t)i*3+2];
    atomicAdd(&d_cylsum[ci*4+0], p0);
    atomicAdd(&d_cylsum[ci*4+1], p1);
    atomicAdd(&d_cylsum[ci*4+2], p2);
    atomicAdd(&d_cylsum[ci*4+3], 1.0f);
}

__global__ void __launch_bounds__(256) k_lin1(
        const float* __restrict__ pts, const float* __restrict__ pcyl,
        const float* __restrict__ cylidx, const float* __restrict__ bevidx,
        const int* __restrict__ binv, const int* __restrict__ cinv,
        const float* __restrict__ w1, int n) {
    __shared__ float sw[16*64];
    for (int t = threadIdx.x; t < 1024; t += 256) { int o = t >> 4, k = t & 15; sw[k*64+o] = w1[t]; }
    __syncthreads();
    int i = blockIdx.x*256 + threadIdx.x;
    if (i >= n) return;
    float x = pts[(size_t)i*5+1], y = pts[(size_t)i*5+2], z = pts[(size_t)i*5+3], it = pts[(size_t)i*5+4];
    float phi = pcyl[(size_t)i*3], zc = pcyl[(size_t)i*3+1], rho = pcyl[(size_t)i*3+2];
    float bix = bevidx[2*(size_t)i], biy = bevidx[2*(size_t)i+1];
    float cix = cylidx[2*(size_t)i], ciy = cylidx[2*(size_t)i+1];
    int bi = binv[i], ci = cinv[i];
    float bcnt = d_bevsum[bi*4+3];
    float bmx = d_bevsum[bi*4]/bcnt, bmy = d_bevsum[bi*4+1]/bcnt;
    float ccnt = d_cylsum[ci*4+3];
    float cm0 = d_cylsum[ci*4]/ccnt, cm1 = d_cylsum[ci*4+1]/ccnt;
    float f[16];
    f[0]=x; f[1]=y; f[2]=z; f[3]=phi; f[4]=zc; f[5]=rho;
    f[6] = x - ((floorf(bix)+0.5f)*0.32f + 0.0f);
    f[7] = y - ((floorf(biy)+0.5f)*0.32f + (-40.0f));
    f[8] = phi - ((floorf(cix)+0.5f)*CVS0 + CR0);
    f[9] = zc  - ((floorf(ciy)+0.5f)*CVS1 + CR1);
    f[10]= x - bmx; f[11]= y - bmy;
    f[12]= phi - cm0; f[13]= zc - cm1;
    f[14]= sqrtf(x*x + y*y + z*z);
    f[15]= it;
    ull acc[32];
    #pragma unroll
    for (int o = 0; o < 32; o++) acc[o] = 0ULL;
    #pragma unroll
    for (int k = 0; k < 16; k++) {
        ull v = pk2(f[k]);
        const ulonglong2* wr = (const ulonglong2*)&sw[k*64];
        #pragma unroll
        for (int m = 0; m < 16; m++) {
            ulonglong2 w = wr[m];
            ffma2(acc[2*m], v, w.x); ffma2(acc[2*m+1], v, w.y);
        }
    }
    ulonglong2* op = (ulonglong2*)&d_lin1[(size_t)i*64];
    #pragma unroll
    for (int m = 0; m < 16; m++) op[m] = make_ulonglong2(acc[2*m], acc[2*m+1]);
}

// generic stats + finalize (used for lin1 only)
__global__ void k_stats(const float* __restrict__ data, int rows, int C, int shift,
                        float* __restrict__ out, const float* __restrict__ g,
                        const float* __restrict__ b, float invn, int bbase, int ctr_idx) {
    int tid = threadIdx.x;
    int c = tid & (C-1);
    int sub = tid >> shift;
    int rpb = 256 >> shift;
    float s = 0.f, s2 = 0.f;
    for (long r = (long)blockIdx.x*rpb + sub; r < rows; r += (long)gridDim.x*rpb) {
        float v = data[(size_t)r*C + c];
        s += v; s2 += v*v;
    }
    __shared__ float sh[512];
    sh[tid] = s; sh[256+tid] = s2;
    __syncthreads();
    if (sub == 0) {
        for (int j = 1; j < rpb; j++) { s += sh[j*C + c]; s2 += sh[256 + j*C + c]; }
        atomicAdd(&out[c], s);
        atomicAdd(&out[C+c], s2);
    }
    __syncthreads();
    bn_finalize_inline(ctr_idx, gridDim.x, tid, C, invn, (int)(out - d_stats), bbase, g, b);
}

// ---------------- lin2: tf32 MMA GEMM [N,64]@[64,128] + fused stats ----------------
#define L2_SMEM (17408*4)
__global__ void __launch_bounds__(256) k_lin2(const float* __restrict__ w2,
        const float* __restrict__ g2, const float* __restrict__ b2, int n, float invn) {
    extern __shared__ float dsm[];
    float* s_a = dsm;                // [p][k] pitch 68
    float* s_b = dsm + 128*68;       // [k][o] pitch 136
    __shared__ float sa[64], sc[64];
    __shared__ float red[512];
    int tid = threadIdx.x;
    if (tid < 64) { sa[tid] = d_bn[tid]; sc[tid] = d_bn[64+tid]; }
    for (int t = tid; t < 8192; t += 256) {
        int o = t >> 6, k = t & 63;
        s_b[k*136 + o] = __uint_as_float(tf32(w2[t]));
    }
    __syncthreads();
    int pbase = blockIdx.x*128;
    for (int idx = tid; idx < 128*16; idx += 256) {
        int lp = idx >> 4, kq = idx & 15;
        int p = pbase + lp, k = kq*4;
        uint4 tv = make_uint4(0u,0u,0u,0u);
        if (p < n) {
            float4 v = *(const float4*)&d_lin1[(size_t)p*64 + k];
            tv.x = tf32(fmaxf(fmaf(v.x, sa[k+0], sc[k+0]), 0.f));
            tv.y = tf32(fmaxf(fmaf(v.y, sa[k+1], sc[k+1]), 0.f));
            tv.z = tf32(fmaxf(fmaf(v.z, sa[k+2], sc[k+2]), 0.f));
            tv.w = tf32(fmaxf(fmaf(v.w, sa[k+3], sc[k+3]), 0.f));
        }
        *(uint4*)&s_a[lp*68 + k] = tv;
    }
    __syncthreads();
    int wid = tid >> 5, lane = tid & 31;
    int g = lane >> 2, tg = lane & 3;
    int m0 = wid*16;
    const uint* ua = (const uint*)s_a;
    const uint* ub = (const uint*)s_b;
    float c[16][4];
    #pragma unroll
    for (int nt = 0; nt < 16; nt++)
        #pragma unroll
        for (int j = 0; j < 4; j++) c[nt][j] = 0.f;
    #pragma unroll
    for (int kc = 0; kc < 8; kc++) {
        int k0 = kc*8;
        uint a0 = ua[(m0+g)*68   + k0 + tg];
        uint a1 = ua[(m0+g+8)*68 + k0 + tg];
        uint a2 = ua[(m0+g)*68   + k0 + tg + 4];
        uint a3 = ua[(m0+g+8)*68 + k0 + tg + 4];
        #pragma unroll
        for (int nt = 0; nt < 16; nt++) {
            uint b0 = ub[(k0+tg)*136   + nt*8 + g];
            uint b1 = ub[(k0+tg+4)*136 + nt*8 + g];
            mma_tf32(c[nt], a0, a1, a2, a3, b0, b1);
        }
    }
    __syncthreads();
    float* stage = dsm;              // [p][o] pitch 132
    #pragma unroll
    for (int nt = 0; nt < 16; nt++) {
        int n0 = nt*8 + tg*2;
        *(float2*)&stage[(m0+g)*132   + n0] = make_float2(c[nt][0], c[nt][1]);
        *(float2*)&stage[(m0+g+8)*132 + n0] = make_float2(c[nt][2], c[nt][3]);
    }
    __syncthreads();
    for (int idx = tid; idx < 128*32; idx += 256) {
        int lp = idx >> 5, q = idx & 31;
        int p = pbase + lp;
        if (p < n)
            *(float4*)&d_lin2[(size_t)p*128 + q*4] = *(const float4*)&stage[lp*132 + q*4];
    }
    // fused stats: column reduce over stage (invalid rows are exact zeros)
    {
        int col = tid & 127, half = tid >> 7;
        float s = 0.f, s2 = 0.f;
        int r0 = half*64;
        for (int r = r0; r < r0+64; r++) {
            float v = stage[r*132 + col];
            s += v; s2 += v*v;
        }
        red[half*128 + col] = s;
        red[256 + half*128 + col] = s2;
        __syncthreads();
        if (half == 0) {
            atomicAdd(&d_stats[128+col], red[col] + red[128+col]);
            atomicAdd(&d_stats[256+col], red[256+col] + red[384+col]);
        }
        __syncthreads();
    }
    bn_finalize_inline(1, gridDim.x, tid, 128, invn, 128, 128, g2, b2);
}

// segment-max of bn_relu(lin2[:, :64]) into dense image
__global__ void k_cylmax(const float* __restrict__ pts, const float* __restrict__ cylidx, int n) {
    __shared__ float sa[64], sc[64];
    if (threadIdx.x < 64) { sa[threadIdx.x] = d_bn[128+threadIdx.x]; sc[threadIdx.x] = d_bn[256+threadIdx.x]; }
    __syncthreads();
    int i = blockIdx.x*blockDim.x + threadIdx.x;
    if (i >= n) return;
    int b = (int)pts[(size_t)i*5];
    int iy = (int)floorf(cylidx[2*(size_t)i]);   iy = max(0, min(iy, 511));
    int ix = (int)floorf(cylidx[2*(size_t)i+1]); ix = max(0, min(ix, 47));
    unsigned* dst = (unsigned*)&d_dense[(((size_t)b*512 + iy)*48 + ix)*64];
    const float4* src = (const float4*)&d_lin2[(size_t)i*128];
    #pragma unroll
    for (int j = 0; j < 16; j++) {
        float4 v = src[j];
        int c = j*4;
        float r0 = fmaxf(fmaf(v.x, sa[c+0], sc[c+0]), 0.f);
        float r1 = fmaxf(fmaf(v.y, sa[c+1], sc[c+1]), 0.f);
        float r2 = fmaxf(fmaf(v.z, sa[c+2], sc[c+2]), 0.f);
        float r3 = fmaxf(fmaf(v.w, sa[c+3], sc[c+3]), 0.f);
        atomicMax(dst+c+0, __float_as_uint(r0));
        atomicMax(dst+c+1, __float_as_uint(r1));
        atomicMax(dst+c+2, __float_as_uint(r2));
        atomicMax(dst+c+3, __float_as_uint(r3));
    }
}

// ---------------- conv: tf32 + bf16 correction MMA, fused stats ----------------
#define CV_SMEM ((180*68 + 180*36*2 + 192*72 + 96*72*2)*4)
__global__ void __launch_bounds__(256) k_conv(const float* __restrict__ gc,
                                              const float* __restrict__ bc) {
    extern __shared__ float dsm[];
    float* s_ih  = dsm;                       // [pos][cin] pitch 68 (tf32 hi, fp32)
    uint*  s_cah = (uint*)(dsm + 180*68);     // [pos][cinpair] pitch 36, bf16(hi) pairs
    uint*  s_cal = s_cah + 180*36;
    float* s_wh  = (float*)(s_cal + 180*36);  // [k][f] pitch 72
    uint*  s_cwh = (uint*)(s_wh + 192*72);    // [kpair][f] pitch 72
    uint*  s_cwl = s_cwh + 96*72;
    __shared__ float red[512];
    int x0 = blockIdx.x*16, y0 = blockIdx.y*8, bb = blockIdx.z;
    int tid = threadIdx.x;
    for (int idx = tid; idx < 180*16; idx += 256) {
        int pos = idx >> 4, c4 = idx & 15;
        int hy = pos / 18, hx = pos - hy*18;
        int gy = y0 + hy - 1, gx = x0 + hx - 1;
        float4 v = make_float4(0.f,0.f,0.f,0.f);
        if (gy >= 0 && gy < 512 && gx >= 0 && gx < 48)
            v = *(const float4*)&d_dense[(((size_t)bb*512 + gy)*48 + gx)*64 + c4*4];
        float h0,l0,h1,l1,h2,l2,h3,l3;
        tf32split(v.x, h0, l0); tf32split(v.y, h1, l1);
        tf32split(v.z, h2, l2); tf32split(v.w, h3, l3);
        *(float4*)&s_ih[pos*68 + c4*4] = make_float4(h0,h1,h2,h3);
        s_cah[pos*36 + c4*2]   = pkbf2(h0, h1);
        s_cah[pos*36 + c4*2+1] = pkbf2(h2, h3);
        s_cal[pos*36 + c4*2]   = pkbf2(l0, l1);
        s_cal[pos*36 + c4*2+1] = pkbf2(l2, l3);
    }
    int wid = tid >> 5, lane = tid & 31;
    int g = lane >> 2, tg = lane & 3;
    const uint* uih = (const uint*)s_ih;
    const uint* uwh = (const uint*)s_wh;
    float c[8][4];
    #pragma unroll
    for (int nt = 0; nt < 8; nt++)
        #pragma unroll
        for (int j = 0; j < 4; j++) c[nt][j] = 0.f;
    for (int dy = 0; dy < 3; dy++) {
        __syncthreads();
        for (int t = tid; t < 12288; t += 256) {
            int k = t >> 6, f = t & 63;
            s_wh[k*72 + f] = d_wt_hi[dy*12288 + t];
        }
        for (int t = tid; t < 6144; t += 256) {
            int kp = t >> 6, f = t & 63;
            s_cwh[kp*72 + f] = d_wcb_h[dy*6144 + t];
            s_cwl[kp*72 + f] = d_wcb_l[dy*6144 + t];
        }
        __syncthreads();
        int hbase = (wid + dy)*18;
        #pragma unroll
        for (int ch = 0; ch < 24; ch++) {
            int dx = ch >> 3, cin0 = (ch & 7)*8;
            int k0 = ch*8, kp0 = ch*4;
            int cp0 = (ch & 7)*4;
            int pos0 = hbase + g + dx, pos1 = pos0 + 8;
            uint a0 = uih[pos0*68 + cin0 + tg];
            uint a1 = uih[pos1*68 + cin0 + tg];
            uint a2 = uih[pos0*68 + cin0 + tg + 4];
            uint a3 = uih[pos1*68 + cin0 + tg + 4];
            uint ac0 = s_cah[pos0*36 + cp0 + tg];
            uint ac1 = s_cah[pos1*36 + cp0 + tg];
            uint ac2 = s_cal[pos0*36 + cp0 + tg];
            uint ac3 = s_cal[pos1*36 + cp0 + tg];
            #pragma unroll
            for (int nt = 0; nt < 8; nt++) {
                int col = nt*8 + g;
                uint b0 = uwh[(k0+tg)*72   + col];
                uint b1 = uwh[(k0+tg+4)*72 + col];
                uint bc0 = s_cwl[(kp0+tg)*72 + col];
                uint bc1 = s_cwh[(kp0+tg)*72 + col];
                mma_tf32(c[nt], a0, a1, a2, a3, b0, b1);
                mma_bf16(c[nt], ac0, ac1, ac2, ac3, bc0, bc1);
            }
        }
    }
    // stage results (alias dead correction-A region), coalesced gmem write + stats
    float* stage = (float*)s_cah;    // [pos 0..127][ch] pitch 68 (8704 floats <= 12960)
    __syncthreads();
    #pragma unroll
    for (int nt = 0; nt < 8; nt++) {
        int col = nt*8 + tg*2;
        *(float2*)&stage[(wid*16 + g)*68   + col] = make_float2(c[nt][0], c[nt][1]);
        *(float2*)&stage[(wid*16 + g + 8)*68 + col] = make_float2(c[nt][2], c[nt][3]);
    }
    __syncthreads();
    for (int idx = tid; idx < 128*16; idx += 256) {
        int pos = idx >> 4, q = idx & 15;
        int gy = y0 + (pos >> 4), gx = x0 + (pos & 15);
        *(float4*)&d_conv[(((size_t)bb*512 + gy)*48 + gx)*64 + q*4] =
            *(const float4*)&stage[pos*68 + q*4];
    }
    {
        int col = tid & 63, qtr = tid >> 6;
        float s = 0.f, s2 = 0.f;
        int r0 = qtr*32;
        for (int r = r0; r < r0+32; r++) {
            float v = stage[r*68 + col];
            s += v; s2 += v*v;
        }
        red[qtr*64 + col] = s;
        red[256 + qtr*64 + col] = s2;
        __syncthreads();
        if (qtr == 0) {
            atomicAdd(&d_stats[384+col], red[col] + red[64+col] + red[128+col] + red[192+col]);
            atomicAdd(&d_stats[448+col], red[256+col] + red[320+col] + red[384+col] + red[448+col]);
        }
        __syncthreads();
    }
    unsigned nblocks = gridDim.x * gridDim.y * gridDim.z;
    bn_finalize_inline(2, nblocks, tid, 64, 1.0f/98304.0f, 384, 384, gc, bc);
}

// ---------------- lin3: tf32 MMA GEMM [N,128]@[128,64], gather inlined + fused stats ----------------
#define L3_SMEM ((128*132 + 128*72)*4)
__global__ void __launch_bounds__(256) k_lin3(const float* __restrict__ pts,
        const float* __restrict__ cylidx, const float* __restrict__ w3,
        const float* __restrict__ g3, const float* __restrict__ b3, int n, float invn) {
    extern __shared__ float dsm[];
    float* s_a = dsm;                 // [p][k] pitch 132
    float* s_b = dsm + 128*132;       // [k][o] pitch 72
    __shared__ float pa[64], pc[64], ca[64], cs[64];
    __shared__ float s_w4[4][128];
    __shared__ int   s_o4[4][128];
    __shared__ float red[512];
    int tid = threadIdx.x;
    if (tid < 64) {
        pa[tid] = d_bn[192+tid]; pc[tid] = d_bn[320+tid];
        ca[tid] = d_bn[384+tid]; cs[tid] = d_bn[448+tid];
    }
    for (int t = tid; t < 8192; t += 256) {
        int o = t >> 7, k = t & 127;
        s_b[k*72 + o] = __uint_as_float(tf32(w3[t]));
    }
    int pbase = blockIdx.x*128;
    if (tid < 128) {
        int p = pbase + tid;
        int i = (p < n) ? p : (n-1);
        float yq = cylidx[2*(size_t)i], xq = cylidx[2*(size_t)i+1];
        int y0i = (int)floorf(yq); int y1i = min(y0i+1, 511); y0i = min(max(y0i,0), 511);
        int x0i = (int)floorf(xq); int x1i = min(x0i+1, 47);  x0i = min(max(x0i,0), 47);
        s_w4[0][tid] = ((float)x1i - xq)*((float)y1i - yq);
        s_w4[1][tid] = ((float)x1i - xq)*(yq - (float)y0i);
        s_w4[2][tid] = (xq - (float)x0i)*((float)y1i - yq);
        s_w4[3][tid] = (xq - (float)x0i)*(yq - (float)y0i);
        int b = (int)pts[(size_t)i*5];
        int base = b*512*48*64;
        s_o4[0][tid] = base + (y0i*48 + x0i)*64;
        s_o4[1][tid] = base + (y1i*48 + x0i)*64;
        s_o4[2][tid] = base + (y0i*48 + x1i)*64;
        s_o4[3][tid] = base + (y1i*48 + x1i)*64;
    }
    __syncthreads();
    for (int idx = tid; idx < 128*16; idx += 256) {
        int lp = idx >> 4, kq = idx & 15;
        int p = pbase + lp, k = kq*4;
        uint4 tv = make_uint4(0u,0u,0u,0u);
        if (p < n) {
            float4 v = *(const float4*)&d_lin2[(size_t)p*128 + 64 + k];
            tv.x = tf32(fmaxf(fmaf(v.x, pa[k+0], pc[k+0]), 0.f));
            tv.y = tf32(fmaxf(fmaf(v.y, pa[k+1], pc[k+1]), 0.f));
            tv.z = tf32(fmaxf(fmaf(v.z, pa[k+2], pc[k+2]), 0.f));
            tv.w = tf32(fmaxf(fmaf(v.w, pa[k+3], pc[k+3]), 0.f));
        }
        *(uint4*)&s_a[lp*132 + k] = tv;
    }
    for (int idx = tid; idx < 128*16; idx += 256) {
        int lp = idx >> 4, kq = idx & 15;
        int p = pbase + lp, c = kq*4;
        uint4 tv = make_uint4(0u,0u,0u,0u);
        if (p < n) {
            float wa = s_w4[0][lp], wb = s_w4[1][lp], wcw = s_w4[2][lp], wd = s_w4[3][lp];
            float4 av = *(const float4*)&d_conv[s_o4[0][lp] + c];
            float4 bv = *(const float4*)&d_conv[s_o4[1][lp] + c];
            float4 cv = *(const float4*)&d_conv[s_o4[2][lp] + c];
            float4 dv = *(const float4*)&d_conv[s_o4[3][lp] + c];
            float rx = wa*fmaxf(fmaf(av.x, ca[c+0], cs[c+0]),0.f) + wb*fmaxf(fmaf(bv.x, ca[c+0], cs[c+0]),0.f)
                + wcw*fmaxf(fmaf(cv.x, ca[c+0], cs[c+0]),0.f) + wd*fmaxf(fmaf(dv.x, ca[c+0], cs[c+0]),0.f);
            float ry = wa*fmaxf(fmaf(av.y, ca[c+1], cs[c+1]),0.f) + wb*fmaxf(fmaf(bv.y, ca[c+1], cs[c+1]),0.f)
                + wcw*fmaxf(fmaf(cv.y, ca[c+1], cs[c+1]),0.f) + wd*fmaxf(fmaf(dv.y, ca[c+1], cs[c+1]),0.f);
            float rz = wa*fmaxf(fmaf(av.z, ca[c+2], cs[c+2]),0.f) + wb*fmaxf(fmaf(bv.z, ca[c+2], cs[c+2]),0.f)
                + wcw*fmaxf(fmaf(cv.z, ca[c+2], cs[c+2]),0.f) + wd*fmaxf(fmaf(dv.z, ca[c+2], cs[c+2]),0.f);
            float rw = wa*fmaxf(fmaf(av.w, ca[c+3], cs[c+3]),0.f) + wb*fmaxf(fmaf(bv.w, ca[c+3], cs[c+3]),0.f)
                + wcw*fmaxf(fmaf(cv.w, ca[c+3], cs[c+3]),0.f) + wd*fmaxf(fmaf(dv.w, ca[c+3], cs[c+3]),0.f);
            tv.x = tf32(rx); tv.y = tf32(ry); tv.z = tf32(rz); tv.w = tf32(rw);
        }
        *(uint4*)&s_a[lp*132 + 64 + c] = tv;
    }
    __syncthreads();
    int wid = tid >> 5, lane = tid & 31;
    int g = lane >> 2, tg = lane & 3;
    int m0 = wid*16;
    const uint* ua = (const uint*)s_a;
    const uint* ub = (const uint*)s_b;
    float c[8][4];
    #pragma unroll
    for (int nt = 0; nt < 8; nt++)
        #pragma unroll
        for (int j = 0; j < 4; j++) c[nt][j] = 0.f;
    #pragma unroll
    for (int kc = 0; kc < 16; kc++) {
        int k0 = kc*8;
        uint a0 = ua[(m0+g)*132   + k0 + tg];
        uint a1 = ua[(m0+g+8)*132 + k0 + tg];
        uint a2 = ua[(m0+g)*132   + k0 + tg + 4];
        uint a3 = ua[(m0+g+8)*132 + k0 + tg + 4];
        #pragma unroll
        for (int nt = 0; nt < 8; nt++) {
            uint b0 = ub[(k0+tg)*72   + nt*8 + g];
            uint b1 = ub[(k0+tg+4)*72 + nt*8 + g];
            mma_tf32(c[nt], a0, a1, a2, a3, b0, b1);
        }
    }
    __syncthreads();
    float* stage = dsm;              // [p][o] pitch 68
    #pragma unroll
    for (int nt = 0; nt < 8; nt++) {
        int n0 = nt*8 + tg*2;
        *(float2*)&stage[(m0+g)*68   + n0] = make_float2(c[nt][0], c[nt][1]);
        *(float2*)&stage[(m0+g+8)*68 + n0] = make_float2(c[nt][2], c[nt][3]);
    }
    __syncthreads();
    for (int idx = tid; idx < 128*16; idx += 256) {
        int lp = idx >> 4, q = idx & 15;
        int p = pbase + lp;
        if (p < n)
            *(float4*)&d_lin3[(size_t)p*64 + q*4] = *(const float4*)&stage[lp*68 + q*4];
    }
    // fused stats (invalid rows are exact zeros)
    {
        int col = tid & 63, qtr = tid >> 6;
        float s = 0.f, s2 = 0.f;
        int r0 = qtr*32;
        for (int r = r0; r < r0+32; r++) {
            float v = stage[r*68 + col];
            s += v; s2 += v*v;
        }
        red[qtr*64 + col] = s;
        red[256 + qtr*64 + col] = s2;
        __syncthreads();
        if (qtr == 0) {
            atomicAdd(&d_stats[512+col], red[col] + red[64+col] + red[128+col] + red[192+col]);
            atomicAdd(&d_stats[576+col], red[256+col] + red[320+col] + red[384+col] + red[448+col]);
        }
        __syncthreads();
    }
    bn_finalize_inline(3, gridDim.x, tid, 64, invn, 512, 512, g3, b3);
}

// final: bn_relu(lin3) -> out; atomicMax into bev_max; extra blocks do voxel coords
__global__ void k_final(const int* __restrict__ binv, const int* __restrict__ bcoord,
                        float* __restrict__ out, int n, int nb, int nblk) {
    if (blockIdx.x >= nblk) {
        int i = (blockIdx.x - nblk)*blockDim.x + threadIdx.x;
        if (i < nb) {
            int c = bcoord[i];
            int vb = c / 55000;
            int r  = c % 55000;
            int vx = r / 250;
            int vy = r % 250;
            float* o = out + (size_t)n*64 + (size_t)nb*64 + (size_t)i*4;
            o[0] = (float)vb; o[1] = 0.f; o[2] = (float)vy; o[3] = (float)vx;
        }
        return;
    }
    __shared__ float sa[64], sc[64];
    if (threadIdx.x < 64) { sa[threadIdx.x] = d_bn[512+threadIdx.x]; sc[threadIdx.x] = d_bn[576+threadIdx.x]; }
    __syncthreads();
    int i = blockIdx.x*blockDim.x + threadIdx.x;
    if (i >= n) return;
    int bi = binv[i];
    const float4* src = (const float4*)&d_lin3[(size_t)i*64];
    float4* dst = (float4*)(out + (size_t)i*64);
    unsigned* mx = (unsigned*)(out + (size_t)n*64 + (size_t)bi*64);
    #pragma unroll
    for (int j = 0; j < 16; j++) {
        float4 v = src[j];
        int c = j*4;
        float r0 = fmaxf(fmaf(v.x, sa[c+0], sc[c+0]), 0.f);
        float r1 = fmaxf(fmaf(v.y, sa[c+1], sc[c+1]), 0.f);
        float r2 = fmaxf(fmaf(v.z, sa[c+2], sc[c+2]), 0.f);
        float r3 = fmaxf(fmaf(v.w, sa[c+3], sc[c+3]), 0.f);
        dst[j] = make_float4(r0, r1, r2, r3);
        atomicMax(mx+c+0, __float_as_uint(r0));
        atomicMax(mx+c+1, __float_as_uint(r1));
        atomicMax(mx+c+2, __float_as_uint(r2));
        atomicMax(mx+c+3, __float_as_uint(r3));
    }
}

// ---------------- launcher ----------------
extern "C" void kernel_launch(void* const* d_in, const int* in_sizes, int n_in,
                              void* d_out, int out_size) {
    const float* points = (const float*)d_in[0];
    const float* pcyl   = (const float*)d_in[1];
    const float* cylidx = (const float*)d_in[2];
    const float* bevidx = (const float*)d_in[3];
    const float* w1 = (const float*)d_in[4];
    const float* g1 = (const float*)d_in[5];
    const float* b1 = (const float*)d_in[6];
    const float* w2 = (const float*)d_in[7];
    const float* g2 = (const float*)d_in[8];
    const float* b2 = (const float*)d_in[9];
    const float* wc = (const float*)d_in[10];
    const float* gc = (const float*)d_in[11];
    const float* bc = (const float*)d_in[12];
    const float* w3 = (const float*)d_in[13];
    const float* g3 = (const float*)d_in[14];
    const float* b3 = (const float*)d_in[15];
    const int* binv   = (const int*)d_in[16];
    const int* bcoord = (const int*)d_in[17];
    const int* cinv   = (const int*)d_in[18];

    int n  = in_sizes[0] / 5;
    int nb = in_sizes[17];
    int nc = in_sizes[19];
    float* out = (float*)d_out;
    float invn = 1.0f/(float)n;

    void *p_lin1, *p_stats;
    cudaGetSymbolAddress(&p_lin1, d_lin1);
    cudaGetSymbolAddress(&p_stats, d_stats);

    static bool attr_done = false;
    if (!attr_done) {
        cudaFuncSetAttribute(k_conv, cudaFuncAttributeMaxDynamicSharedMemorySize, CV_SMEM);
        cudaFuncSetAttribute(k_lin2, cudaFuncAttributeMaxDynamicSharedMemorySize, L2_SMEM);
        cudaFuncSetAttribute(k_lin3, cudaFuncAttributeMaxDynamicSharedMemorySize, L3_SMEM);
        attr_done = true;
    }

    int nblk = (n + 255) / 256;
    int gblk = (n + 127) / 128;
    k_zero<<<512, 256>>>(out + (size_t)n*64, nb, nc, wc);
    k_scatter<<<nblk, 256>>>(points, pcyl, binv, cinv, n);
    k_lin1<<<nblk, 256>>>(points, pcyl, cylidx, bevidx, binv, cinv, w1, n);
    k_stats<<<512, 256>>>((const float*)p_lin1, n, 64, 6, (float*)p_stats + 0,
                          g1, b1, invn, 0, 0);
    k_lin2<<<gblk, 256, L2_SMEM>>>(w2, g2, b2, n, invn);
    k_cylmax<<<nblk, 256>>>(points, cylidx, n);
    dim3 cg(3, 64, 4);
    k_conv<<<cg, 256, CV_SMEM>>>(gc, bc);
    k_lin3<<<gblk, 256, L3_SMEM>>>(points, cylidx, w3, g3, b3, n, invn);
    int vblk = (nb + 255) / 256;
    k_final<<<nblk + vblk, 256>>>(binv, bcoord, out, n, nb, nblk);
}

// round 11
// speedup vs baseline: 1.3208x; 1.0478x over previous
#include <cuda_runtime.h>
#include <math.h>

typedef unsigned long long ull;
typedef unsigned int uint;

// ---------------- problem constants ----------------
#define NPTS_MAX 200000
#define NB_MAX   220000
#define NC_MAX   98304
#define IMG_ELEMS (4*512*48*64)

#define CVS0 (6.2831853f/512.0f)
#define CVS1 0.125f
#define CR0  (-3.14159265f)
#define CR1  (-2.0f)

// ---------------- scratch ----------------
__device__ float d_lin1[(size_t)NPTS_MAX*64];
__device__ float d_lin2[(size_t)NPTS_MAX*128];
__device__ float d_lin3[(size_t)NPTS_MAX*64];
__device__ float d_dense[IMG_ELEMS];
__device__ float d_conv[IMG_ELEMS];
__device__ float d_bevsum[NB_MAX*4];
__device__ float d_cylsum[NC_MAX*4];
__device__ float d_stats[1024];
__device__ float d_bn[1024];  // lin1 a@0 c@64; lin2 a@128 c@256; conv a@384 c@448; lin3 a@512 c@576
__device__ unsigned d_ctr[8];
__device__ float d_wt_hi[3*192*64];   // [dy][dx*64+cin][f], tf32-valued fp32
__device__ uint  d_wcb_h[3*96*64];    // [dy][kpair][f], packed bf16(hi) pairs
__device__ uint  d_wcb_l[3*96*64];    // packed bf16(lo) pairs

// ---------------- helpers ----------------
__device__ __forceinline__ uint tf32(float f) {
    uint r; asm("cvt.rna.tf32.f32 %0, %1;" : "=r"(r) : "f"(f)); return r;
}
__device__ __forceinline__ void tf32split(float v, float& hi, float& lo) {
    uint h = tf32(v);
    hi = __uint_as_float(h);
    lo = v - hi;
}
__device__ __forceinline__ uint pkbf2(float ev, float od) {
    uint r; asm("cvt.rn.bf16x2.f32 %0, %1, %2;" : "=r"(r) : "f"(od), "f"(ev)); return r;
}
__device__ __forceinline__ void mma_tf32(float* c, uint a0, uint a1, uint a2, uint a3, uint b0, uint b1) {
    asm volatile("mma.sync.aligned.m16n8k8.row.col.f32.tf32.tf32.f32 "
                 "{%0,%1,%2,%3},{%4,%5,%6,%7},{%8,%9},{%0,%1,%2,%3};"
                 : "+f"(c[0]), "+f"(c[1]), "+f"(c[2]), "+f"(c[3])
                 : "r"(a0), "r"(a1), "r"(a2), "r"(a3), "r"(b0), "r"(b1));
}
__device__ __forceinline__ void mma_bf16(float* c, uint a0, uint a1, uint a2, uint a3, uint b0, uint b1) {
    asm volatile("mma.sync.aligned.m16n8k16.row.col.f32.bf16.bf16.f32 "
                 "{%0,%1,%2,%3},{%4,%5,%6,%7},{%8,%9},{%0,%1,%2,%3};"
                 : "+f"(c[0]), "+f"(c[1]), "+f"(c[2]), "+f"(c[3])
                 : "r"(a0), "r"(a1), "r"(a2), "r"(a3), "r"(b0), "r"(b1));
}
__device__ __forceinline__ void bn_finalize_inline(int ctr_idx, unsigned nblocks, int tid,
                                                   int C, float invn, int sbase, int bbase,
                                                   const float* g, const float* b) {
    __threadfence();
    __shared__ unsigned s_ord;
    if (tid == 0) s_ord = atomicAdd(&d_ctr[ctr_idx], 1u);
    __syncthreads();
    if (s_ord == nblocks - 1 && tid < C) {
        float m = __ldcg(&d_stats[sbase + tid]) * invn;
        float v = __ldcg(&d_stats[sbase + C + tid]) * invn - m*m;
        float a = g[tid] * rsqrtf(v + 1e-3f);
        d_bn[bbase + tid]     = a;
        d_bn[bbase + C + tid] = b[tid] - m*a;
    }
}

// ---------------- utility kernels ----------------
__global__ void __launch_bounds__(256) k_zero(float* outbev, int nb, int nc,
                                              const float* __restrict__ wc) {
    size_t tid = (size_t)blockIdx.x * blockDim.x + threadIdx.x;
    size_t stride = (size_t)gridDim.x * blockDim.x;
    if (tid < 18432) {
        int t = (int)tid;
        int f = t & 63;
        int q = t >> 6;
        int cinp = q & 31;
        int dxy = q >> 5;
        int dx = dxy % 3, dy = dxy / 3;
        int cin0 = cinp*2;
        float v0 = wc[(size_t)f*576 + cin0*9     + dy*3 + dx];
        float v1 = wc[(size_t)f*576 + (cin0+1)*9 + dy*3 + dx];
        float h0, l0, h1, l1;
        tf32split(v0, h0, l0);
        tf32split(v1, h1, l1);
        d_wt_hi[dy*12288 + (dx*64+cin0)*64 + f]   = h0;
        d_wt_hi[dy*12288 + (dx*64+cin0+1)*64 + f] = h1;
        d_wcb_h[dy*6144 + (dx*32+cinp)*64 + f] = pkbf2(h0, h1);
        d_wcb_l[dy*6144 + (dx*32+cinp)*64 + f] = pkbf2(l0, l1);
    }
    float4 z = make_float4(0.f, 0.f, 0.f, 0.f);
    float4* p = (float4*)d_dense;
    for (size_t i = tid; i < IMG_ELEMS/4; i += stride) p[i] = z;
    float4* q = (float4*)outbev;
    size_t obw = (size_t)nb * 16;
    for (size_t i = tid; i < obw; i += stride) q[i] = z;
    float4* bs = (float4*)d_bevsum;
    for (size_t i = tid; i < (size_t)nb; i += stride) bs[i] = z;
    float4* cs = (float4*)d_cylsum;
    for (size_t i = tid; i < (size_t)nc; i += stride) cs[i] = z;
    if (tid < 256) ((float4*)d_stats)[tid] = z;
    if (tid < 8) d_ctr[tid] = 0u;
}

__global__ void k_scatter(const float* __restrict__ pts, const float* __restrict__ pcyl,
                          const int* __restrict__ binv, const int* __restrict__ cinv, int n) {
    int i = blockIdx.x*blockDim.x + threadIdx.x;
    if (i >= n) return;
    float x = pts[(size_t)i*5+1], y = pts[(size_t)i*5+2], z = pts[(size_t)i*5+3];
    int bi = binv[i], ci = cinv[i];
    atomicAdd(&d_bevsum[bi*4+0], x);
    atomicAdd(&d_bevsum[bi*4+1], y);
    atomicAdd(&d_bevsum[bi*4+2], z);
    atomicAdd(&d_bevsum[bi*4+3], 1.0f);
    float p0 = pcyl[(size_t)i*3], p1 = pcyl[(size_t)i*3+1], p2 = pcyl[(size_t)i*3+2];
    atomicAdd(&d_cylsum[ci*4+0], p0);
    atomicAdd(&d_cylsum[ci*4+1], p1);
    atomicAdd(&d_cylsum[ci*4+2], p2);
    atomicAdd(&d_cylsum[ci*4+3], 1.0f);
}

// ---------------- lin1: tf32+bf16corr MMA [N,16]@[16,64], fused stats ----------------
// block 256 thr, tile 256 points; smem stage [256][68] dominates
#define L1_SMEM (17408*4)
__global__ void __launch_bounds__(256) k_lin1(
        const float* __restrict__ pts, const float* __restrict__ pcyl,
        const float* __restrict__ cylidx, const float* __restrict__ bevidx,
        const int* __restrict__ binv, const int* __restrict__ cinv,
        const float* __restrict__ w1, const float* __restrict__ g1,
        const float* __restrict__ b1, int n, float invn) {
    extern __shared__ float dsm[];
    float* s_a  = dsm;                       // [p][k] pitch 20 (5120)
    uint*  s_cah = (uint*)(dsm + 5120);      // [p][kp] pitch 12 (3072)
    uint*  s_cal = s_cah + 3072;             // (3072)
    float* s_b  = (float*)(s_cal + 3072);    // [k][o] pitch 68 (1088)
    uint*  s_bch = (uint*)(s_b + 1088);      // [kp][o] pitch 72 (576)
    uint*  s_bcl = s_bch + 576;              // (576)
    __shared__ float red[512];
    int tid = threadIdx.x;
    // weights hi/lo
    for (int t = tid; t < 512; t += 256) {
        int o = t & 63, kp = t >> 6;
        float h0,l0,h1,l1;
        tf32split(w1[o*16 + 2*kp],   h0, l0);
        tf32split(w1[o*16 + 2*kp+1], h1, l1);
        s_b[(2*kp)*68 + o]   = h0;
        s_b[(2*kp+1)*68 + o] = h1;
        s_bch[kp*72 + o] = pkbf2(h0, h1);
        s_bcl[kp*72 + o] = pkbf2(l0, l1);
    }
    int pbase = blockIdx.x*256;
    int p = pbase + tid;
    {
        float f[16];
        #pragma unroll
        for (int k = 0; k < 16; k++) f[k] = 0.f;
        if (p < n) {
            size_t i = (size_t)p;
            float x = pts[i*5+1], y = pts[i*5+2], z = pts[i*5+3], it = pts[i*5+4];
            float phi = pcyl[i*3], zc = pcyl[i*3+1], rho = pcyl[i*3+2];
            float bix = bevidx[2*i], biy = bevidx[2*i+1];
            float cix = cylidx[2*i], ciy = cylidx[2*i+1];
            int bi = binv[p], ci = cinv[p];
            float bcnt = d_bevsum[bi*4+3];
            float bmx = d_bevsum[bi*4]/bcnt, bmy = d_bevsum[bi*4+1]/bcnt;
            float ccnt = d_cylsum[ci*4+3];
            float cm0 = d_cylsum[ci*4]/ccnt, cm1 = d_cylsum[ci*4+1]/ccnt;
            f[0]=x; f[1]=y; f[2]=z; f[3]=phi; f[4]=zc; f[5]=rho;
            f[6] = x - ((floorf(bix)+0.5f)*0.32f + 0.0f);
            f[7] = y - ((floorf(biy)+0.5f)*0.32f + (-40.0f));
            f[8] = phi - ((floorf(cix)+0.5f)*CVS0 + CR0);
            f[9] = zc  - ((floorf(ciy)+0.5f)*CVS1 + CR1);
            f[10]= x - bmx; f[11]= y - bmy;
            f[12]= phi - cm0; f[13]= zc - cm1;
            f[14]= sqrtf(x*x + y*y + z*z);
            f[15]= it;
        }
        float h[16], l[16];
        #pragma unroll
        for (int k = 0; k < 16; k++) tf32split(f[k], h[k], l[k]);
        #pragma unroll
        for (int k4 = 0; k4 < 4; k4++)
            *(float4*)&s_a[tid*20 + k4*4] = make_float4(h[4*k4],h[4*k4+1],h[4*k4+2],h[4*k4+3]);
        #pragma unroll
        for (int kp = 0; kp < 8; kp++) {
            s_cah[tid*12 + kp] = pkbf2(h[2*kp], h[2*kp+1]);
            s_cal[tid*12 + kp] = pkbf2(l[2*kp], l[2*kp+1]);
        }
    }
    __syncthreads();
    int wid = tid >> 5, lane = tid & 31;
    int g = lane >> 2, tg = lane & 3;
    int m0 = wid*32;
    const uint* ua = (const uint*)s_a;
    const uint* ub = (const uint*)s_b;
    float c[2][8][4];
    #pragma unroll
    for (int mt = 0; mt < 2; mt++)
        #pragma unroll
        for (int nt = 0; nt < 8; nt++)
            #pragma unroll
            for (int j = 0; j < 4; j++) c[mt][nt][j] = 0.f;
    #pragma unroll
    for (int kc = 0; kc < 2; kc++) {
        int k0 = kc*8, kp0 = kc*4;
        #pragma unroll
        for (int mt = 0; mt < 2; mt++) {
            int mb = m0 + mt*16;
            uint a0 = ua[(mb+g)*20   + k0 + tg];
            uint a1 = ua[(mb+g+8)*20 + k0 + tg];
            uint a2 = ua[(mb+g)*20   + k0 + tg + 4];
            uint a3 = ua[(mb+g+8)*20 + k0 + tg + 4];
            uint ac0 = s_cah[(mb+g)*12   + kp0 + tg];
            uint ac1 = s_cah[(mb+g+8)*12 + kp0 + tg];
            uint ac2 = s_cal[(mb+g)*12   + kp0 + tg];
            uint ac3 = s_cal[(mb+g+8)*12 + kp0 + tg];
            #pragma unroll
            for (int nt = 0; nt < 8; nt++) {
                int col = nt*8 + g;
                uint b0 = ub[(k0+tg)*68   + col];
                uint b1 = ub[(k0+tg+4)*68 + col];
                uint bc0 = s_bcl[(kp0+tg)*72 + col];
                uint bc1 = s_bch[(kp0+tg)*72 + col];
                mma_tf32(c[mt][nt], a0, a1, a2, a3, b0, b1);
                mma_bf16(c[mt][nt], ac0, ac1, ac2, ac3, bc0, bc1);
            }
        }
    }
    __syncthreads();
    float* stage = dsm;              // [p][o] pitch 68
    #pragma unroll
    for (int mt = 0; mt < 2; mt++) {
        int mb = m0 + mt*16;
        #pragma unroll
        for (int nt = 0; nt < 8; nt++) {
            int n0 = nt*8 + tg*2;
            *(float2*)&stage[(mb+g)*68   + n0] = make_float2(c[mt][nt][0], c[mt][nt][1]);
            *(float2*)&stage[(mb+g+8)*68 + n0] = make_float2(c[mt][nt][2], c[mt][nt][3]);
        }
    }
    __syncthreads();
    for (int idx = tid; idx < 256*16; idx += 256) {
        int lp = idx >> 4, q = idx & 15;
        int pp = pbase + lp;
        if (pp < n)
            *(float4*)&d_lin1[(size_t)pp*64 + q*4] = *(const float4*)&stage[lp*68 + q*4];
    }
    // fused stats (invalid rows are exact zeros)
    {
        int col = tid & 63, qtr = tid >> 6;
        float s = 0.f, s2 = 0.f;
        int r0 = qtr*64;
        for (int r = r0; r < r0+64; r++) {
            float v = stage[r*68 + col];
            s += v; s2 += v*v;
        }
        red[qtr*64 + col] = s;
        red[256 + qtr*64 + col] = s2;
        __syncthreads();
        if (qtr == 0) {
            atomicAdd(&d_stats[col],    red[col] + red[64+col] + red[128+col] + red[192+col]);
            atomicAdd(&d_stats[64+col], red[256+col] + red[320+col] + red[384+col] + red[448+col]);
        }
        __syncthreads();
    }
    bn_finalize_inline(0, gridDim.x, tid, 64, invn, 0, 0, g1, b1);
}

// ---------------- lin2: tf32 MMA GEMM [N,64]@[64,128] + fused stats ----------------
#define L2_SMEM (17408*4)
__global__ void __launch_bounds__(256) k_lin2(const float* __restrict__ w2,
        const float* __restrict__ g2, const float* __restrict__ b2, int n, float invn) {
    extern __shared__ float dsm[];
    float* s_a = dsm;                // [p][k] pitch 68
    float* s_b = dsm + 128*68;       // [k][o] pitch 136
    __shared__ float sa[64], sc[64];
    __shared__ float red[512];
    int tid = threadIdx.x;
    if (tid < 64) { sa[tid] = d_bn[tid]; sc[tid] = d_bn[64+tid]; }
    for (int t = tid; t < 8192; t += 256) {
        int o = t >> 6, k = t & 63;
        s_b[k*136 + o] = __uint_as_float(tf32(w2[t]));
    }
    __syncthreads();
    int pbase = blockIdx.x*128;
    for (int idx = tid; idx < 128*16; idx += 256) {
        int lp = idx >> 4, kq = idx & 15;
        int p = pbase + lp, k = kq*4;
        uint4 tv = make_uint4(0u,0u,0u,0u);
        if (p < n) {
            float4 v = *(const float4*)&d_lin1[(size_t)p*64 + k];
            tv.x = tf32(fmaxf(fmaf(v.x, sa[k+0], sc[k+0]), 0.f));
            tv.y = tf32(fmaxf(fmaf(v.y, sa[k+1], sc[k+1]), 0.f));
            tv.z = tf32(fmaxf(fmaf(v.z, sa[k+2], sc[k+2]), 0.f));
            tv.w = tf32(fmaxf(fmaf(v.w, sa[k+3], sc[k+3]), 0.f));
        }
        *(uint4*)&s_a[lp*68 + k] = tv;
    }
    __syncthreads();
    int wid = tid >> 5, lane = tid & 31;
    int g = lane >> 2, tg = lane & 3;
    int m0 = wid*16;
    const uint* ua = (const uint*)s_a;
    const uint* ub = (const uint*)s_b;
    float c[16][4];
    #pragma unroll
    for (int nt = 0; nt < 16; nt++)
        #pragma unroll
        for (int j = 0; j < 4; j++) c[nt][j] = 0.f;
    #pragma unroll
    for (int kc = 0; kc < 8; kc++) {
        int k0 = kc*8;
        uint a0 = ua[(m0+g)*68   + k0 + tg];
        uint a1 = ua[(m0+g+8)*68 + k0 + tg];
        uint a2 = ua[(m0+g)*68   + k0 + tg + 4];
        uint a3 = ua[(m0+g+8)*68 + k0 + tg + 4];
        #pragma unroll
        for (int nt = 0; nt < 16; nt++) {
            uint b0 = ub[(k0+tg)*136   + nt*8 + g];
            uint b1 = ub[(k0+tg+4)*136 + nt*8 + g];
            mma_tf32(c[nt], a0, a1, a2, a3, b0, b1);
        }
    }
    __syncthreads();
    float* stage = dsm;              // [p][o] pitch 132
    #pragma unroll
    for (int nt = 0; nt < 16; nt++) {
        int n0 = nt*8 + tg*2;
        *(float2*)&stage[(m0+g)*132   + n0] = make_float2(c[nt][0], c[nt][1]);
        *(float2*)&stage[(m0+g+8)*132 + n0] = make_float2(c[nt][2], c[nt][3]);
    }
    __syncthreads();
    for (int idx = tid; idx < 128*32; idx += 256) {
        int lp = idx >> 5, q = idx & 31;
        int p = pbase + lp;
        if (p < n)
            *(float4*)&d_lin2[(size_t)p*128 + q*4] = *(const float4*)&stage[lp*132 + q*4];
    }
    {
        int col = tid & 127, half = tid >> 7;
        float s = 0.f, s2 = 0.f;
        int r0 = half*64;
        for (int r = r0; r < r0+64; r++) {
            float v = stage[r*132 + col];
            s += v; s2 += v*v;
        }
        red[half*128 + col] = s;
        red[256 + half*128 + col] = s2;
        __syncthreads();
        if (half == 0) {
            atomicAdd(&d_stats[128+col], red[col] + red[128+col]);
            atomicAdd(&d_stats[256+col], red[256+col] + red[384+col]);
        }
        __syncthreads();
    }
    bn_finalize_inline(1, gridDim.x, tid, 128, invn, 128, 128, g2, b2);
}

// segment-max of bn_relu(lin2[:, :64]) into dense image
__global__ void k_cylmax(const float* __restrict__ pts, const float* __restrict__ cylidx, int n) {
    __shared__ float sa[64], sc[64];
    if (threadIdx.x < 64) { sa[threadIdx.x] = d_bn[128+threadIdx.x]; sc[threadIdx.x] = d_bn[256+threadIdx.x]; }
    __syncthreads();
    int i = blockIdx.x*blockDim.x + threadIdx.x;
    if (i >= n) return;
    int b = (int)pts[(size_t)i*5];
    int iy = (int)floorf(cylidx[2*(size_t)i]);   iy = max(0, min(iy, 511));
    int ix = (int)floorf(cylidx[2*(size_t)i+1]); ix = max(0, min(ix, 47));
    unsigned* dst = (unsigned*)&d_dense[(((size_t)b*512 + iy)*48 + ix)*64];
    const float4* src = (const float4*)&d_lin2[(size_t)i*128];
    #pragma unroll
    for (int j = 0; j < 16; j++) {
        float4 v = src[j];
        int c = j*4;
        float r0 = fmaxf(fmaf(v.x, sa[c+0], sc[c+0]), 0.f);
        float r1 = fmaxf(fmaf(v.y, sa[c+1], sc[c+1]), 0.f);
        float r2 = fmaxf(fmaf(v.z, sa[c+2], sc[c+2]), 0.f);
        float r3 = fmaxf(fmaf(v.w, sa[c+3], sc[c+3]), 0.f);
        atomicMax(dst+c+0, __float_as_uint(r0));
        atomicMax(dst+c+1, __float_as_uint(r1));
        atomicMax(dst+c+2, __float_as_uint(r2));
        atomicMax(dst+c+3, __float_as_uint(r3));
    }
}

// ---------------- conv: tf32 + bf16 correction MMA, fused stats ----------------
#define CV_SMEM ((180*68 + 180*36*2 + 192*72 + 96*72*2)*4)
__global__ void __launch_bounds__(256) k_conv(const float* __restrict__ gc,
                                              const float* __restrict__ bc) {
    extern __shared__ float dsm[];
    float* s_ih  = dsm;                       // [pos][cin] pitch 68 (tf32 hi, fp32)
    uint*  s_cah = (uint*)(dsm + 180*68);     // [pos][cinpair] pitch 36
    uint*  s_cal = s_cah + 180*36;
    float* s_wh  = (float*)(s_cal + 180*36);  // [k][f] pitch 72
    uint*  s_cwh = (uint*)(s_wh + 192*72);    // [kpair][f] pitch 72
    uint*  s_cwl = s_cwh + 96*72;
    __shared__ float red[512];
    int x0 = blockIdx.x*16, y0 = blockIdx.y*8, bb = blockIdx.z;
    int tid = threadIdx.x;
    for (int idx = tid; idx < 180*16; idx += 256) {
        int pos = idx >> 4, c4 = idx & 15;
        int hy = pos / 18, hx = pos - hy*18;
        int gy = y0 + hy - 1, gx = x0 + hx - 1;
        float4 v = make_float4(0.f,0.f,0.f,0.f);
        if (gy >= 0 && gy < 512 && gx >= 0 && gx < 48)
            v = *(const float4*)&d_dense[(((size_t)bb*512 + gy)*48 + gx)*64 + c4*4];
        float h0,l0,h1,l1,h2,l2,h3,l3;
        tf32split(v.x, h0, l0); tf32split(v.y, h1, l1);
        tf32split(v.z, h2, l2); tf32split(v.w, h3, l3);
        *(float4*)&s_ih[pos*68 + c4*4] = make_float4(h0,h1,h2,h3);
        s_cah[pos*36 + c4*2]   = pkbf2(h0, h1);
        s_cah[pos*36 + c4*2+1] = pkbf2(h2, h3);
        s_cal[pos*36 + c4*2]   = pkbf2(l0, l1);
        s_cal[pos*36 + c4*2+1] = pkbf2(l2, l3);
    }
    int wid = tid >> 5, lane = tid & 31;
    int g = lane >> 2, tg = lane & 3;
    const uint* uih = (const uint*)s_ih;
    const uint* uwh = (const uint*)s_wh;
    float c[8][4];
    #pragma unroll
    for (int nt = 0; nt < 8; nt++)
        #pragma unroll
        for (int j = 0; j < 4; j++) c[nt][j] = 0.f;
    for (int dy = 0; dy < 3; dy++) {
        __syncthreads();
        for (int t = tid; t < 12288; t += 256) {
            int k = t >> 6, f = t & 63;
            s_wh[k*72 + f] = d_wt_hi[dy*12288 + t];
        }
        for (int t = tid; t < 6144; t += 256) {
            int kp = t >> 6, f = t & 63;
            s_cwh[kp*72 + f] = d_wcb_h[dy*6144 + t];
            s_cwl[kp*72 + f] = d_wcb_l[dy*6144 + t];
        }
        __syncthreads();
        int hbase = (wid + dy)*18;
        #pragma unroll
        for (int ch = 0; ch < 24; ch++) {
            int dx = ch >> 3, cin0 = (ch & 7)*8;
            int k0 = ch*8, kp0 = ch*4;
            int cp0 = (ch & 7)*4;
            int pos0 = hbase + g + dx, pos1 = pos0 + 8;
            uint a0 = uih[pos0*68 + cin0 + tg];
            uint a1 = uih[pos1*68 + cin0 + tg];
            uint a2 = uih[pos0*68 + cin0 + tg + 4];
            uint a3 = uih[pos1*68 + cin0 + tg + 4];
            uint ac0 = s_cah[pos0*36 + cp0 + tg];
            uint ac1 = s_cah[pos1*36 + cp0 + tg];
            uint ac2 = s_cal[pos0*36 + cp0 + tg];
            uint ac3 = s_cal[pos1*36 + cp0 + tg];
            #pragma unroll
            for (int nt = 0; nt < 8; nt++) {
                int col = nt*8 + g;
                uint b0 = uwh[(k0+tg)*72   + col];
                uint b1 = uwh[(k0+tg+4)*72 + col];
                uint bc0 = s_cwl[(kp0+tg)*72 + col];
                uint bc1 = s_cwh[(kp0+tg)*72 + col];
                mma_tf32(c[nt], a0, a1, a2, a3, b0, b1);
                mma_bf16(c[nt], ac0, ac1, ac2, ac3, bc0, bc1);
            }
        }
    }
    float* stage = (float*)s_cah;    // [pos][ch] pitch 68
    __syncthreads();
    #pragma unroll
    for (int nt = 0; nt < 8; nt++) {
        int col = nt*8 + tg*2;
        *(float2*)&stage[(wid*16 + g)*68   + col] = make_float2(c[nt][0], c[nt][1]);
        *(float2*)&stage[(wid*16 + g + 8)*68 + col] = make_float2(c[nt][2], c[nt][3]);
    }
    __syncthreads();
    for (int idx = tid; idx < 128*16; idx += 256) {
        int pos = idx >> 4, q = idx & 15;
        int gy = y0 + (pos >> 4), gx = x0 + (pos & 15);
        *(float4*)&d_conv[(((size_t)bb*512 + gy)*48 + gx)*64 + q*4] =
            *(const float4*)&stage[pos*68 + q*4];
    }
    {
        int col = tid & 63, qtr = tid >> 6;
        float s = 0.f, s2 = 0.f;
        int r0 = qtr*32;
        for (int r = r0; r < r0+32; r++) {
            float v = stage[r*68 + col];
            s += v; s2 += v*v;
        }
        red[qtr*64 + col] = s;
        red[256 + qtr*64 + col] = s2;
        __syncthreads();
        if (qtr == 0) {
            atomicAdd(&d_stats[384+col], red[col] + red[64+col] + red[128+col] + red[192+col]);
            atomicAdd(&d_stats[448+col], red[256+col] + red[320+col] + red[384+col] + red[448+col]);
        }
        __syncthreads();
    }
    unsigned nblocks = gridDim.x * gridDim.y * gridDim.z;
    bn_finalize_inline(2, nblocks, tid, 64, 1.0f/98304.0f, 384, 384, gc, bc);
}

// ---------------- lin3: tf32 MMA GEMM [N,128]@[128,64], gather inlined + fused stats ----------------
#define L3_SMEM ((128*132 + 128*72)*4)
__global__ void __launch_bounds__(256) k_lin3(const float* __restrict__ pts,
        const float* __restrict__ cylidx, const float* __restrict__ w3,
        const float* __restrict__ g3, const float* __restrict__ b3, int n, float invn) {
    extern __shared__ float dsm[];
    float* s_a = dsm;                 // [p][k] pitch 132
    float* s_b = dsm + 128*132;       // [k][o] pitch 72
    __shared__ float pa[64], pc[64], ca[64], cs[64];
    __shared__ float s_w4[4][128];
    __shared__ int   s_o4[4][128];
    __shared__ float red[512];
    int tid = threadIdx.x;
    if (tid < 64) {
        pa[tid] = d_bn[192+tid]; pc[tid] = d_bn[320+tid];
        ca[tid] = d_bn[384+tid]; cs[tid] = d_bn[448+tid];
    }
    for (int t = tid; t < 8192; t += 256) {
        int o = t >> 7, k = t & 127;
        s_b[k*72 + o] = __uint_as_float(tf32(w3[t]));
    }
    int pbase = blockIdx.x*128;
    if (tid < 128) {
        int p = pbase + tid;
        int i = (p < n) ? p : (n-1);
        float yq = cylidx[2*(size_t)i], xq = cylidx[2*(size_t)i+1];
        int y0i = (int)floorf(yq); int y1i = min(y0i+1, 511); y0i = min(max(y0i,0), 511);
        int x0i = (int)floorf(xq); int x1i = min(x0i+1, 47);  x0i = min(max(x0i,0), 47);
        s_w4[0][tid] = ((float)x1i - xq)*((float)y1i - yq);
        s_w4[1][tid] = ((float)x1i - xq)*(yq - (float)y0i);
        s_w4[2][tid] = (xq - (float)x0i)*((float)y1i - yq);
        s_w4[3][tid] = (xq - (float)x0i)*(yq - (float)y0i);
        int b = (int)pts[(size_t)i*5];
        int base = b*512*48*64;
        s_o4[0][tid] = base + (y0i*48 + x0i)*64;
        s_o4[1][tid] = base + (y1i*48 + x0i)*64;
        s_o4[2][tid] = base + (y0i*48 + x1i)*64;
        s_o4[3][tid] = base + (y1i*48 + x1i)*64;
    }
    __syncthreads();
    for (int idx = tid; idx < 128*16; idx += 256) {
        int lp = idx >> 4, kq = idx & 15;
        int p = pbase + lp, k = kq*4;
        uint4 tv = make_uint4(0u,0u,0u,0u);
        if (p < n) {
            float4 v = *(const float4*)&d_lin2[(size_t)p*128 + 64 + k];
            tv.x = tf32(fmaxf(fmaf(v.x, pa[k+0], pc[k+0]), 0.f));
            tv.y = tf32(fmaxf(fmaf(v.y, pa[k+1], pc[k+1]), 0.f));
            tv.z = tf32(fmaxf(fmaf(v.z, pa[k+2], pc[k+2]), 0.f));
            tv.w = tf32(fmaxf(fmaf(v.w, pa[k+3], pc[k+3]), 0.f));
        }
        *(uint4*)&s_a[lp*132 + k] = tv;
    }
    for (int idx = tid; idx < 128*16; idx += 256) {
        int lp = idx >> 4, kq = idx & 15;
        int p = pbase + lp, c = kq*4;
        uint4 tv = make_uint4(0u,0u,0u,0u);
        if (p < n) {
            float wa = s_w4[0][lp], wb = s_w4[1][lp], wcw = s_w4[2][lp], wd = s_w4[3][lp];
            float4 av = *(const float4*)&d_conv[s_o4[0][lp] + c];
            float4 bv = *(const float4*)&d_conv[s_o4[1][lp] + c];
            float4 cv = *(const float4*)&d_conv[s_o4[2][lp] + c];
            float4 dv = *(const float4*)&d_conv[s_o4[3][lp] + c];
            float rx = wa*fmaxf(fmaf(av.x, ca[c+0], cs[c+0]),0.f) + wb*fmaxf(fmaf(bv.x, ca[c+0], cs[c+0]),0.f)
                + wcw*fmaxf(fmaf(cv.x, ca[c+0], cs[c+0]),0.f) + wd*fmaxf(fmaf(dv.x, ca[c+0], cs[c+0]),0.f);
            float ry = wa*fmaxf(fmaf(av.y, ca[c+1], cs[c+1]),0.f) + wb*fmaxf(fmaf(bv.y, ca[c+1], cs[c+1]),0.f)
                + wcw*fmaxf(fmaf(cv.y, ca[c+1], cs[c+1]),0.f) + wd*fmaxf(fmaf(dv.y, ca[c+1], cs[c+1]),0.f);
            float rz = wa*fmaxf(fmaf(av.z, ca[c+2], cs[c+2]),0.f) + wb*fmaxf(fmaf(bv.z, ca[c+2], cs[c+2]),0.f)
                + wcw*fmaxf(fmaf(cv.z, ca[c+2], cs[c+2]),0.f) + wd*fmaxf(fmaf(dv.z, ca[c+2], cs[c+2]),0.f);
            float rw = wa*fmaxf(fmaf(av.w, ca[c+3], cs[c+3]),0.f) + wb*fmaxf(fmaf(bv.w, ca[c+3], cs[c+3]),0.f)
                + wcw*fmaxf(fmaf(cv.w, ca[c+3], cs[c+3]),0.f) + wd*fmaxf(fmaf(dv.w, ca[c+3], cs[c+3]),0.f);
            tv.x = tf32(rx); tv.y = tf32(ry); tv.z = tf32(rz); tv.w = tf32(rw);
        }
        *(uint4*)&s_a[lp*132 + 64 + c] = tv;
    }
    __syncthreads();
    int wid = tid >> 5, lane = tid & 31;
    int g = lane >> 2, tg = lane & 3;
    int m0 = wid*16;
    const uint* ua = (const uint*)s_a;
    const uint* ub = (const uint*)s_b;
    float c[8][4];
    #pragma unroll
    for (int nt = 0; nt < 8; nt++)
        #pragma unroll
        for (int j = 0; j < 4; j++) c[nt][j] = 0.f;
    #pragma unroll
    for (int kc = 0; kc < 16; kc++) {
        int k0 = kc*8;
        uint a0 = ua[(m0+g)*132   + k0 + tg];
        uint a1 = ua[(m0+g+8)*132 + k0 + tg];
        uint a2 = ua[(m0+g)*132   + k0 + tg + 4];
        uint a3 = ua[(m0+g+8)*132 + k0 + tg + 4];
        #pragma unroll
        for (int nt = 0; nt < 8; nt++) {
            uint b0 = ub[(k0+tg)*72   + nt*8 + g];
            uint b1 = ub[(k0+tg+4)*72 + nt*8 + g];
            mma_tf32(c[nt], a0, a1, a2, a3, b0, b1);
        }
    }
    __syncthreads();
    float* stage = dsm;              // [p][o] pitch 68
    #pragma unroll
    for (int nt = 0; nt < 8; nt++) {
        int n0 = nt*8 + tg*2;
        *(float2*)&stage[(m0+g)*68   + n0] = make_float2(c[nt][0], c[nt][1]);
        *(float2*)&stage[(m0+g+8)*68 + n0] = make_float2(c[nt][2], c[nt][3]);
    }
    __syncthreads();
    for (int idx = tid; idx < 128*16; idx += 256) {
        int lp = idx >> 4, q = idx & 15;
        int p = pbase + lp;
        if (p < n)
            *(float4*)&d_lin3[(size_t)p*64 + q*4] = *(const float4*)&stage[lp*68 + q*4];
    }
    {
        int col = tid & 63, qtr = tid >> 6;
        float s = 0.f, s2 = 0.f;
        int r0 = qtr*32;
        for (int r = r0; r < r0+32; r++) {
            float v = stage[r*68 + col];
            s += v; s2 += v*v;
        }
        red[qtr*64 + col] = s;
        red[256 + qtr*64 + col] = s2;
        __syncthreads();
        if (qtr == 0) {
            atomicAdd(&d_stats[512+col], red[col] + red[64+col] + red[128+col] + red[192+col]);
            atomicAdd(&d_stats[576+col], red[256+col] + red[320+col] + red[384+col] + red[448+col]);
        }
        __syncthreads();
    }
    bn_finalize_inline(3, gridDim.x, tid, 64, invn, 512, 512, g3, b3);
}

// final: bn_relu(lin3) -> out; atomicMax into bev_max; extra blocks do voxel coords
__global__ void k_final(const int* __restrict__ binv, const int* __restrict__ bcoord,
                        float* __restrict__ out, int n, int nb, int nblk) {
    if (blockIdx.x >= nblk) {
        int i = (blockIdx.x - nblk)*blockDim.x + threadIdx.x;
        if (i < nb) {
            int c = bcoord[i];
            int vb = c / 55000;
            int r  = c % 55000;
            int vx = r / 250;
            int vy = r % 250;
            float* o = out + (size_t)n*64 + (size_t)nb*64 + (size_t)i*4;
            o[0] = (float)vb; o[1] = 0.f; o[2] = (float)vy; o[3] = (float)vx;
        }
        return;
    }
    __shared__ float sa[64], sc[64];
    if (threadIdx.x < 64) { sa[threadIdx.x] = d_bn[512+threadIdx.x]; sc[threadIdx.x] = d_bn[576+threadIdx.x]; }
    __syncthreads();
    int i = blockIdx.x*blockDim.x + threadIdx.x;
    if (i >= n) return;
    int bi = binv[i];
    const float4* src = (const float4*)&d_lin3[(size_t)i*64];
    float4* dst = (float4*)(out + (size_t)i*64);
    unsigned* mx = (unsigned*)(out + (size_t)n*64 + (size_t)bi*64);
    #pragma unroll
    for (int j = 0; j < 16; j++) {
        float4 v = src[j];
        int c = j*4;
        float r0 = fmaxf(fmaf(v.x, sa[c+0], sc[c+0]), 0.f);
        float r1 = fmaxf(fmaf(v.y, sa[c+1], sc[c+1]), 0.f);
        float r2 = fmaxf(fmaf(v.z, sa[c+2], sc[c+2]), 0.f);
        float r3 = fmaxf(fmaf(v.w, sa[c+3], sc[c+3]), 0.f);
        dst[j] = make_float4(r0, r1, r2, r3);
        atomicMax(mx+c+0, __float_as_uint(r0));
        atomicMax(mx+c+1, __float_as_uint(r1));
        atomicMax(mx+c+2, __float_as_uint(r2));
        atomicMax(mx+c+3, __float_as_uint(r3));
    }
}

// ---------------- launcher ----------------
extern "C" void kernel_launch(void* const* d_in, const int* in_sizes, int n_in,
                              void* d_out, int out_size) {
    const float* points = (const float*)d_in[0];
    const float* pcyl   = (const float*)d_in[1];
    const float* cylidx = (const float*)d_in[2];
    const float* bevidx = (const float*)d_in[3];
    const float* w1 = (const float*)d_in[4];
    const float* g1 = (const float*)d_in[5];
    const float* b1 = (const float*)d_in[6];
    const float* w2 = (const float*)d_in[7];
    const float* g2 = (const float*)d_in[8];
    const float* b2 = (const float*)d_in[9];
    const float* wc = (const float*)d_in[10];
    const float* gc = (const float*)d_in[11];
    const float* bc = (const float*)d_in[12];
    const float* w3 = (const float*)d_in[13];
    const float* g3 = (const float*)d_in[14];
    const float* b3 = (const float*)d_in[15];
    const int* binv   = (const int*)d_in[16];
    const int* bcoord = (const int*)d_in[17];
    const int* cinv   = (const int*)d_in[18];

    int n  = in_sizes[0] / 5;
    int nb = in_sizes[17];
    int nc = in_sizes[19];
    float* out = (float*)d_out;
    float invn = 1.0f/(float)n;

    static bool attr_done = false;
    if (!attr_done) {
        cudaFuncSetAttribute(k_lin1, cudaFuncAttributeMaxDynamicSharedMemorySize, L1_SMEM);
        cudaFuncSetAttribute(k_conv, cudaFuncAttributeMaxDynamicSharedMemorySize, CV_SMEM);
        cudaFuncSetAttribute(k_lin2, cudaFuncAttributeMaxDynamicSharedMemorySize, L2_SMEM);
        cudaFuncSetAttribute(k_lin3, cudaFuncAttributeMaxDynamicSharedMemorySize, L3_SMEM);
        attr_done = true;
    }

    int nblk = (n + 255) / 256;
    int gblk = (n + 127) / 128;
    k_zero<<<512, 256>>>(out + (size_t)n*64, nb, nc, wc);
    k_scatter<<<nblk, 256>>>(points, pcyl, binv, cinv, n);
    k_lin1<<<nblk, 256, L1_SMEM>>>(points, pcyl, cylidx, bevidx, binv, cinv, w1, g1, b1, n, invn);
    k_lin2<<<gblk, 256, L2_SMEM>>>(w2, g2, b2, n, invn);
    k_cylmax<<<nblk, 256>>>(points, cylidx, n);
    dim3 cg(3, 64, 4);
    k_conv<<<cg, 256, CV_SMEM>>>(gc, bc);
    k_lin3<<<gblk, 256, L3_SMEM>>>(points, cylidx, w3, g3, b3, n, invn);
    int vblk = (nb + 255) / 256;
    k_final<<<nblk + vblk, 256>>>(binv, bcoord, out, n, nb, nblk);
}

// round 12
// speedup vs baseline: 1.3575x; 1.0278x over previous
#include <cuda_runtime.h>
#include <math.h>

typedef unsigned long long ull;
typedef unsigned int uint;

// ---------------- problem constants ----------------
#define NPTS_MAX 200000
#define NB_MAX   220000
#define NC_MAX   98304
#define IMG_ELEMS (4*512*48*64)

#define CVS0 (6.2831853f/512.0f)
#define CVS1 0.125f
#define CR0  (-3.14159265f)
#define CR1  (-2.0f)

// ---------------- scratch ----------------
__device__ float d_lin1[(size_t)NPTS_MAX*64];
__device__ float d_lin2[(size_t)NPTS_MAX*128];
__device__ float d_lin3[(size_t)NPTS_MAX*64];
__device__ float d_dense[IMG_ELEMS];
__device__ float d_conv[IMG_ELEMS];
__device__ float d_bevsum[NB_MAX*4];
__device__ float d_cylsum[NC_MAX*4];
__device__ float d_stats[1024];
__device__ float d_bn[1024];  // lin1 a@0 c@64; lin2 a@128 c@256; conv a@384 c@448; lin3 a@512 c@576
__device__ unsigned d_ctr[8];
__device__ float d_wt_hi[3*192*64];   // [dy][dx*64+cin][f]
__device__ uint  d_wcb_h[3*96*64];    // [dy][kpair][f], bf16(hi) pairs
__device__ uint  d_wcb_l[3*96*64];

// ---------------- helpers ----------------
__device__ __forceinline__ uint tf32(float f) {
    uint r; asm("cvt.rna.tf32.f32 %0, %1;" : "=r"(r) : "f"(f)); return r;
}
__device__ __forceinline__ void tf32split(float v, float& hi, float& lo) {
    uint h = tf32(v);
    hi = __uint_as_float(h);
    lo = v - hi;
}
__device__ __forceinline__ uint pkbf2(float ev, float od) {
    uint r; asm("cvt.rn.bf16x2.f32 %0, %1, %2;" : "=r"(r) : "f"(od), "f"(ev)); return r;
}
__device__ __forceinline__ void mma_tf32(float* c, uint a0, uint a1, uint a2, uint a3, uint b0, uint b1) {
    asm volatile("mma.sync.aligned.m16n8k8.row.col.f32.tf32.tf32.f32 "
                 "{%0,%1,%2,%3},{%4,%5,%6,%7},{%8,%9},{%0,%1,%2,%3};"
                 : "+f"(c[0]), "+f"(c[1]), "+f"(c[2]), "+f"(c[3])
                 : "r"(a0), "r"(a1), "r"(a2), "r"(a3), "r"(b0), "r"(b1));
}
__device__ __forceinline__ void mma_bf16(float* c, uint a0, uint a1, uint a2, uint a3, uint b0, uint b1) {
    asm volatile("mma.sync.aligned.m16n8k16.row.col.f32.bf16.bf16.f32 "
                 "{%0,%1,%2,%3},{%4,%5,%6,%7},{%8,%9},{%0,%1,%2,%3};"
                 : "+f"(c[0]), "+f"(c[1]), "+f"(c[2]), "+f"(c[3])
                 : "r"(a0), "r"(a1), "r"(a2), "r"(a3), "r"(b0), "r"(b1));
}
__device__ __forceinline__ void bn_finalize_inline(int ctr_idx, unsigned nblocks, int tid,
                                                   int C, float invn, int sbase, int bbase,
                                                   const float* g, const float* b) {
    __threadfence();
    __shared__ unsigned s_ord;
    if (tid == 0) s_ord = atomicAdd(&d_ctr[ctr_idx], 1u);
    __syncthreads();
    if (s_ord == nblocks - 1 && tid < C) {
        float m = __ldcg(&d_stats[sbase + tid]) * invn;
        float v = __ldcg(&d_stats[sbase + C + tid]) * invn - m*m;
        float a = g[tid] * rsqrtf(v + 1e-3f);
        d_bn[bbase + tid]     = a;
        d_bn[bbase + C + tid] = b[tid] - m*a;
    }
}

// ---------------- utility kernels ----------------
__global__ void __launch_bounds__(256) k_zero(float* outbev, int nb, int nc,
                                              const float* __restrict__ wc) {
    size_t tid = (size_t)blockIdx.x * blockDim.x + threadIdx.x;
    size_t stride = (size_t)gridDim.x * blockDim.x;
    if (tid < 18432) {
        int t = (int)tid;
        int f = t & 63;
        int q = t >> 6;
        int cinp = q & 31;
        int dxy = q >> 5;
        int dx = dxy % 3, dy = dxy / 3;
        int cin0 = cinp*2;
        float v0 = wc[(size_t)f*576 + cin0*9     + dy*3 + dx];
        float v1 = wc[(size_t)f*576 + (cin0+1)*9 + dy*3 + dx];
        float h0, l0, h1, l1;
        tf32split(v0, h0, l0);
        tf32split(v1, h1, l1);
        d_wt_hi[dy*12288 + (dx*64+cin0)*64 + f]   = h0;
        d_wt_hi[dy*12288 + (dx*64+cin0+1)*64 + f] = h1;
        d_wcb_h[dy*6144 + (dx*32+cinp)*64 + f] = pkbf2(h0, h1);
        d_wcb_l[dy*6144 + (dx*32+cinp)*64 + f] = pkbf2(l0, l1);
    }
    float4 z = make_float4(0.f, 0.f, 0.f, 0.f);
    float4* p = (float4*)d_dense;
    for (size_t i = tid; i < IMG_ELEMS/4; i += stride) p[i] = z;
    float4* q = (float4*)outbev;
    size_t obw = (size_t)nb * 16;
    for (size_t i = tid; i < obw; i += stride) q[i] = z;
    float4* bs = (float4*)d_bevsum;
    for (size_t i = tid; i < (size_t)nb; i += stride) bs[i] = z;
    float4* cs = (float4*)d_cylsum;
    for (size_t i = tid; i < (size_t)nc; i += stride) cs[i] = z;
    if (tid < 256) ((float4*)d_stats)[tid] = z;
    if (tid < 8) d_ctr[tid] = 0u;
}

__global__ void k_scatter(const float* __restrict__ pts, const float* __restrict__ pcyl,
                          const int* __restrict__ binv, const int* __restrict__ cinv, int n) {
    int i = blockIdx.x*blockDim.x + threadIdx.x;
    if (i >= n) return;
    float x = pts[(size_t)i*5+1], y = pts[(size_t)i*5+2], z = pts[(size_t)i*5+3];
    int bi = binv[i], ci = cinv[i];
    atomicAdd(&d_bevsum[bi*4+0], x);
    atomicAdd(&d_bevsum[bi*4+1], y);
    atomicAdd(&d_bevsum[bi*4+2], z);
    atomicAdd(&d_bevsum[bi*4+3], 1.0f);
    float p0 = pcyl[(size_t)i*3], p1 = pcyl[(size_t)i*3+1], p2 = pcyl[(size_t)i*3+2];
    atomicAdd(&d_cylsum[ci*4+0], p0);
    atomicAdd(&d_cylsum[ci*4+1], p1);
    atomicAdd(&d_cylsum[ci*4+2], p2);
    atomicAdd(&d_cylsum[ci*4+3], 1.0f);
}

// ---------------- lin1: tf32+bf16corr MMA [N,16]@[16,64], fused stats ----------------
#define L1_SMEM (17408*4)
__global__ void __launch_bounds__(256) k_lin1(
        const float* __restrict__ pts, const float* __restrict__ pcyl,
        const float* __restrict__ cylidx, const float* __restrict__ bevidx,
        const int* __restrict__ binv, const int* __restrict__ cinv,
        const float* __restrict__ w1, const float* __restrict__ g1,
        const float* __restrict__ b1, int n, float invn) {
    extern __shared__ float dsm[];
    float* s_a  = dsm;                       // [p][k] pitch 20
    uint*  s_cah = (uint*)(dsm + 5120);      // [p][kp] pitch 12
    uint*  s_cal = s_cah + 3072;
    float* s_b  = (float*)(s_cal + 3072);    // [k][o] pitch 68
    uint*  s_bch = (uint*)(s_b + 1088);      // [kp][o] pitch 72
    uint*  s_bcl = s_bch + 576;
    __shared__ float red[512];
    int tid = threadIdx.x;
    for (int t = tid; t < 512; t += 256) {
        int o = t & 63, kp = t >> 6;
        float h0,l0,h1,l1;
        tf32split(w1[o*16 + 2*kp],   h0, l0);
        tf32split(w1[o*16 + 2*kp+1], h1, l1);
        s_b[(2*kp)*68 + o]   = h0;
        s_b[(2*kp+1)*68 + o] = h1;
        s_bch[kp*72 + o] = pkbf2(h0, h1);
        s_bcl[kp*72 + o] = pkbf2(l0, l1);
    }
    int pbase = blockIdx.x*256;
    int p = pbase + tid;
    {
        float f[16];
        #pragma unroll
        for (int k = 0; k < 16; k++) f[k] = 0.f;
        if (p < n) {
            size_t i = (size_t)p;
            float x = pts[i*5+1], y = pts[i*5+2], z = pts[i*5+3], it = pts[i*5+4];
            float phi = pcyl[i*3], zc = pcyl[i*3+1], rho = pcyl[i*3+2];
            float bix = bevidx[2*i], biy = bevidx[2*i+1];
            float cix = cylidx[2*i], ciy = cylidx[2*i+1];
            int bi = binv[p], ci = cinv[p];
            float bcnt = d_bevsum[bi*4+3];
            float bmx = d_bevsum[bi*4]/bcnt, bmy = d_bevsum[bi*4+1]/bcnt;
            float ccnt = d_cylsum[ci*4+3];
            float cm0 = d_cylsum[ci*4]/ccnt, cm1 = d_cylsum[ci*4+1]/ccnt;
            f[0]=x; f[1]=y; f[2]=z; f[3]=phi; f[4]=zc; f[5]=rho;
            f[6] = x - ((floorf(bix)+0.5f)*0.32f + 0.0f);
            f[7] = y - ((floorf(biy)+0.5f)*0.32f + (-40.0f));
            f[8] = phi - ((floorf(cix)+0.5f)*CVS0 + CR0);
            f[9] = zc  - ((floorf(ciy)+0.5f)*CVS1 + CR1);
            f[10]= x - bmx; f[11]= y - bmy;
            f[12]= phi - cm0; f[13]= zc - cm1;
            f[14]= sqrtf(x*x + y*y + z*z);
            f[15]= it;
        }
        float h[16], l[16];
        #pragma unroll
        for (int k = 0; k < 16; k++) tf32split(f[k], h[k], l[k]);
        #pragma unroll
        for (int k4 = 0; k4 < 4; k4++)
            *(float4*)&s_a[tid*20 + k4*4] = make_float4(h[4*k4],h[4*k4+1],h[4*k4+2],h[4*k4+3]);
        #pragma unroll
        for (int kp = 0; kp < 8; kp++) {
            s_cah[tid*12 + kp] = pkbf2(h[2*kp], h[2*kp+1]);
            s_cal[tid*12 + kp] = pkbf2(l[2*kp], l[2*kp+1]);
        }
    }
    __syncthreads();
    int wid = tid >> 5, lane = tid & 31;
    int g = lane >> 2, tg = lane & 3;
    int m0 = wid*32;
    const uint* ua = (const uint*)s_a;
    const uint* ub = (const uint*)s_b;
    float c[2][8][4];
    #pragma unroll
    for (int mt = 0; mt < 2; mt++)
        #pragma unroll
        for (int nt = 0; nt < 8; nt++)
            #pragma unroll
            for (int j = 0; j < 4; j++) c[mt][nt][j] = 0.f;
    #pragma unroll
    for (int kc = 0; kc < 2; kc++) {
        int k0 = kc*8, kp0 = kc*4;
        uint a0[2], a1[2], a2[2], a3[2], ac0[2], ac1[2], ac2[2], ac3[2];
        #pragma unroll
        for (int mt = 0; mt < 2; mt++) {
            int mb = m0 + mt*16;
            a0[mt] = ua[(mb+g)*20   + k0 + tg];
            a1[mt] = ua[(mb+g+8)*20 + k0 + tg];
            a2[mt] = ua[(mb+g)*20   + k0 + tg + 4];
            a3[mt] = ua[(mb+g+8)*20 + k0 + tg + 4];
            ac0[mt] = s_cah[(mb+g)*12   + kp0 + tg];
            ac1[mt] = s_cah[(mb+g+8)*12 + kp0 + tg];
            ac2[mt] = s_cal[(mb+g)*12   + kp0 + tg];
            ac3[mt] = s_cal[(mb+g+8)*12 + kp0 + tg];
        }
        #pragma unroll
        for (int nt = 0; nt < 8; nt++) {
            int col = nt*8 + g;
            uint b0 = ub[(k0+tg)*68   + col];
            uint b1 = ub[(k0+tg+4)*68 + col];
            uint bc0 = s_bcl[(kp0+tg)*72 + col];
            uint bc1 = s_bch[(kp0+tg)*72 + col];
            #pragma unroll
            for (int mt = 0; mt < 2; mt++) {
                mma_tf32(c[mt][nt], a0[mt], a1[mt], a2[mt], a3[mt], b0, b1);
                mma_bf16(c[mt][nt], ac0[mt], ac1[mt], ac2[mt], ac3[mt], bc0, bc1);
            }
        }
    }
    __syncthreads();
    float* stage = dsm;              // [p][o] pitch 68
    #pragma unroll
    for (int mt = 0; mt < 2; mt++) {
        int mb = m0 + mt*16;
        #pragma unroll
        for (int nt = 0; nt < 8; nt++) {
            int n0 = nt*8 + tg*2;
            *(float2*)&stage[(mb+g)*68   + n0] = make_float2(c[mt][nt][0], c[mt][nt][1]);
            *(float2*)&stage[(mb+g+8)*68 + n0] = make_float2(c[mt][nt][2], c[mt][nt][3]);
        }
    }
    __syncthreads();
    for (int idx = tid; idx < 256*16; idx += 256) {
        int lp = idx >> 4, q = idx & 15;
        int pp = pbase + lp;
        if (pp < n)
            *(float4*)&d_lin1[(size_t)pp*64 + q*4] = *(const float4*)&stage[lp*68 + q*4];
    }
    {
        int col = tid & 63, qtr = tid >> 6;
        float s = 0.f, s2 = 0.f;
        int r0 = qtr*64;
        for (int r = r0; r < r0+64; r++) {
            float v = stage[r*68 + col];
            s += v; s2 += v*v;
        }
        red[qtr*64 + col] = s;
        red[256 + qtr*64 + col] = s2;
        __syncthreads();
        if (qtr == 0) {
            atomicAdd(&d_stats[col],    red[col] + red[64+col] + red[128+col] + red[192+col]);
            atomicAdd(&d_stats[64+col], red[256+col] + red[320+col] + red[384+col] + red[448+col]);
        }
        __syncthreads();
    }
    bn_finalize_inline(0, gridDim.x, tid, 64, invn, 0, 0, g1, b1);
}

// ---------------- lin2: tf32 MMA GEMM [N,64]@[64,128], 2m x 8n warp tile ----------------
#define L2_SMEM (17408*4)
__global__ void __launch_bounds__(256) k_lin2(const float* __restrict__ w2,
        const float* __restrict__ g2, const float* __restrict__ b2, int n, float invn) {
    extern __shared__ float dsm[];
    float* s_a = dsm;                // [p][k] pitch 68
    float* s_b = dsm + 128*68;       // [k][o] pitch 136
    __shared__ float sa[64], sc[64];
    __shared__ float red[512];
    int tid = threadIdx.x;
    if (tid < 64) { sa[tid] = d_bn[tid]; sc[tid] = d_bn[64+tid]; }
    for (int t = tid; t < 8192; t += 256) {
        int o = t >> 6, k = t & 63;
        s_b[k*136 + o] = __uint_as_float(tf32(w2[t]));
    }
    __syncthreads();
    int pbase = blockIdx.x*128;
    for (int idx = tid; idx < 128*16; idx += 256) {
        int lp = idx >> 4, kq = idx & 15;
        int p = pbase + lp, k = kq*4;
        uint4 tv = make_uint4(0u,0u,0u,0u);
        if (p < n) {
            float4 v = *(const float4*)&d_lin1[(size_t)p*64 + k];
            tv.x = tf32(fmaxf(fmaf(v.x, sa[k+0], sc[k+0]), 0.f));
            tv.y = tf32(fmaxf(fmaf(v.y, sa[k+1], sc[k+1]), 0.f));
            tv.z = tf32(fmaxf(fmaf(v.z, sa[k+2], sc[k+2]), 0.f));
            tv.w = tf32(fmaxf(fmaf(v.w, sa[k+3], sc[k+3]), 0.f));
        }
        *(uint4*)&s_a[lp*68 + k] = tv;
    }
    __syncthreads();
    int wid = tid >> 5, lane = tid & 31;
    int g = lane >> 2, tg = lane & 3;
    int wm = wid >> 1, wn = wid & 1;
    int m0 = wm*32, nb0 = wn*64;
    const uint* ua = (const uint*)s_a;
    const uint* ub = (const uint*)s_b;
    float c[2][8][4];
    #pragma unroll
    for (int mt = 0; mt < 2; mt++)
        #pragma unroll
        for (int nt = 0; nt < 8; nt++)
            #pragma unroll
            for (int j = 0; j < 4; j++) c[mt][nt][j] = 0.f;
    #pragma unroll
    for (int kc = 0; kc < 8; kc++) {
        int k0 = kc*8;
        uint a0[2], a1[2], a2[2], a3[2];
        #pragma unroll
        for (int mt = 0; mt < 2; mt++) {
            int mb = m0 + mt*16;
            a0[mt] = ua[(mb+g)*68   + k0 + tg];
            a1[mt] = ua[(mb+g+8)*68 + k0 + tg];
            a2[mt] = ua[(mb+g)*68   + k0 + tg + 4];
            a3[mt] = ua[(mb+g+8)*68 + k0 + tg + 4];
        }
        #pragma unroll
        for (int nt = 0; nt < 8; nt++) {
            int col = nb0 + nt*8 + g;
            uint b0 = ub[(k0+tg)*136   + col];
            uint b1 = ub[(k0+tg+4)*136 + col];
            mma_tf32(c[0][nt], a0[0], a1[0], a2[0], a3[0], b0, b1);
            mma_tf32(c[1][nt], a0[1], a1[1], a2[1], a3[1], b0, b1);
        }
    }
    __syncthreads();
    float* stage = dsm;              // [p][o] pitch 132
    #pragma unroll
    for (int mt = 0; mt < 2; mt++) {
        int mb = m0 + mt*16;
        #pragma unroll
        for (int nt = 0; nt < 8; nt++) {
            int n0 = nb0 + nt*8 + tg*2;
            *(float2*)&stage[(mb+g)*132   + n0] = make_float2(c[mt][nt][0], c[mt][nt][1]);
            *(float2*)&stage[(mb+g+8)*132 + n0] = make_float2(c[mt][nt][2], c[mt][nt][3]);
        }
    }
    __syncthreads();
    for (int idx = tid; idx < 128*32; idx += 256) {
        int lp = idx >> 5, q = idx & 31;
        int p = pbase + lp;
        if (p < n)
            *(float4*)&d_lin2[(size_t)p*128 + q*4] = *(const float4*)&stage[lp*132 + q*4];
    }
    {
        int col = tid & 127, half = tid >> 7;
        float s = 0.f, s2 = 0.f;
        int r0 = half*64;
        for (int r = r0; r < r0+64; r++) {
            float v = stage[r*132 + col];
            s += v; s2 += v*v;
        }
        red[half*128 + col] = s;
        red[256 + half*128 + col] = s2;
        __syncthreads();
        if (half == 0) {
            atomicAdd(&d_stats[128+col], red[col] + red[128+col]);
            atomicAdd(&d_stats[256+col], red[256+col] + red[384+col]);
        }
        __syncthreads();
    }
    bn_finalize_inline(1, gridDim.x, tid, 128, invn, 128, 128, g2, b2);
}

// segment-max of bn_relu(lin2[:, :64]) into dense image
__global__ void k_cylmax(const float* __restrict__ pts, const float* __restrict__ cylidx, int n) {
    __shared__ float sa[64], sc[64];
    if (threadIdx.x < 64) { sa[threadIdx.x] = d_bn[128+threadIdx.x]; sc[threadIdx.x] = d_bn[256+threadIdx.x]; }
    __syncthreads();
    int i = blockIdx.x*blockDim.x + threadIdx.x;
    if (i >= n) return;
    int b = (int)pts[(size_t)i*5];
    int iy = (int)floorf(cylidx[2*(size_t)i]);   iy = max(0, min(iy, 511));
    int ix = (int)floorf(cylidx[2*(size_t)i+1]); ix = max(0, min(ix, 47));
    unsigned* dst = (unsigned*)&d_dense[(((size_t)b*512 + iy)*48 + ix)*64];
    const float4* src = (const float4*)&d_lin2[(size_t)i*128];
    #pragma unroll
    for (int j = 0; j < 16; j++) {
        float4 v = src[j];
        int c = j*4;
        float r0 = fmaxf(fmaf(v.x, sa[c+0], sc[c+0]), 0.f);
        float r1 = fmaxf(fmaf(v.y, sa[c+1], sc[c+1]), 0.f);
        float r2 = fmaxf(fmaf(v.z, sa[c+2], sc[c+2]), 0.f);
        float r3 = fmaxf(fmaf(v.w, sa[c+3], sc[c+3]), 0.f);
        atomicMax(dst+c+0, __float_as_uint(r0));
        atomicMax(dst+c+1, __float_as_uint(r1));
        atomicMax(dst+c+2, __float_as_uint(r2));
        atomicMax(dst+c+3, __float_as_uint(r3));
    }
}

// ---------------- conv: tf32 + bf16 corr MMA, 2m x 4n warp tile, fused stats ----------------
#define CV_SMEM ((180*68 + 180*36*2 + 192*72 + 96*72*2)*4)
__global__ void __launch_bounds__(256) k_conv(const float* __restrict__ gc,
                                              const float* __restrict__ bc) {
    extern __shared__ float dsm[];
    float* s_ih  = dsm;                       // [pos][cin] pitch 68
    uint*  s_cah = (uint*)(dsm + 180*68);     // [pos][cinpair] pitch 36
    uint*  s_cal = s_cah + 180*36;
    float* s_wh  = (float*)(s_cal + 180*36);  // [k][f] pitch 72
    uint*  s_cwh = (uint*)(s_wh + 192*72);    // [kpair][f] pitch 72
    uint*  s_cwl = s_cwh + 96*72;
    __shared__ float red[512];
    int x0 = blockIdx.x*16, y0 = blockIdx.y*8, bb = blockIdx.z;
    int tid = threadIdx.x;
    for (int idx = tid; idx < 180*16; idx += 256) {
        int pos = idx >> 4, c4 = idx & 15;
        int hy = pos / 18, hx = pos - hy*18;
        int gy = y0 + hy - 1, gx = x0 + hx - 1;
        float4 v = make_float4(0.f,0.f,0.f,0.f);
        if (gy >= 0 && gy < 512 && gx >= 0 && gx < 48)
            v = *(const float4*)&d_dense[(((size_t)bb*512 + gy)*48 + gx)*64 + c4*4];
        float h0,l0,h1,l1,h2,l2,h3,l3;
        tf32split(v.x, h0, l0); tf32split(v.y, h1, l1);
        tf32split(v.z, h2, l2); tf32split(v.w, h3, l3);
        *(float4*)&s_ih[pos*68 + c4*4] = make_float4(h0,h1,h2,h3);
        s_cah[pos*36 + c4*2]   = pkbf2(h0, h1);
        s_cah[pos*36 + c4*2+1] = pkbf2(h2, h3);
        s_cal[pos*36 + c4*2]   = pkbf2(l0, l1);
        s_cal[pos*36 + c4*2+1] = pkbf2(l2, l3);
    }
    int wid = tid >> 5, lane = tid & 31;
    int g = lane >> 2, tg = lane & 3;
    int wm = wid >> 1, wn = wid & 1;
    const uint* uih = (const uint*)s_ih;
    const uint* uwh = (const uint*)s_wh;
    float c[2][4][4];
    #pragma unroll
    for (int mt = 0; mt < 2; mt++)
        #pragma unroll
        for (int nt = 0; nt < 4; nt++)
            #pragma unroll
            for (int j = 0; j < 4; j++) c[mt][nt][j] = 0.f;
    for (int dy = 0; dy < 3; dy++) {
        __syncthreads();
        for (int t = tid; t < 12288; t += 256) {
            int k = t >> 6, f = t & 63;
            s_wh[k*72 + f] = d_wt_hi[dy*12288 + t];
        }
        for (int t = tid; t < 6144; t += 256) {
            int kp = t >> 6, f = t & 63;
            s_cwh[kp*72 + f] = d_wcb_h[dy*6144 + t];
            s_cwl[kp*72 + f] = d_wcb_l[dy*6144 + t];
        }
        __syncthreads();
        #pragma unroll
        for (int ch = 0; ch < 24; ch++) {
            int dx = ch >> 3, cin0 = (ch & 7)*8;
            int k0 = ch*8, kp0 = ch*4;
            int cp0 = (ch & 7)*4;
            uint a0[2], a1[2], a2[2], a3[2], ac0[2], ac1[2], ac2[2], ac3[2];
            #pragma unroll
            for (int mt = 0; mt < 2; mt++) {
                int hbase = (2*wm + mt + dy)*18;
                int pos0 = hbase + g + dx, pos1 = pos0 + 8;
                a0[mt] = uih[pos0*68 + cin0 + tg];
                a1[mt] = uih[pos1*68 + cin0 + tg];
                a2[mt] = uih[pos0*68 + cin0 + tg + 4];
                a3[mt] = uih[pos1*68 + cin0 + tg + 4];
                ac0[mt] = s_cah[pos0*36 + cp0 + tg];
                ac1[mt] = s_cah[pos1*36 + cp0 + tg];
                ac2[mt] = s_cal[pos0*36 + cp0 + tg];
                ac3[mt] = s_cal[pos1*36 + cp0 + tg];
            }
            #pragma unroll
            for (int nt = 0; nt < 4; nt++) {
                int col = wn*32 + nt*8 + g;
                uint b0 = uwh[(k0+tg)*72   + col];
                uint b1 = uwh[(k0+tg+4)*72 + col];
                uint bc0 = s_cwl[(kp0+tg)*72 + col];
                uint bc1 = s_cwh[(kp0+tg)*72 + col];
                #pragma unroll
                for (int mt = 0; mt < 2; mt++) {
                    mma_tf32(c[mt][nt], a0[mt], a1[mt], a2[mt], a3[mt], b0, b1);
                    mma_bf16(c[mt][nt], ac0[mt], ac1[mt], ac2[mt], ac3[mt], bc0, bc1);
                }
            }
        }
    }
    float* stage = (float*)s_cah;    // [pos][ch] pitch 68
    __syncthreads();
    #pragma unroll
    for (int mt = 0; mt < 2; mt++) {
        int prow = (2*wm + mt)*16;
        #pragma unroll
        for (int nt = 0; nt < 4; nt++) {
            int col = wn*32 + nt*8 + tg*2;
            *(float2*)&stage[(prow + g)*68   + col] = make_float2(c[mt][nt][0], c[mt][nt][1]);
            *(float2*)&stage[(prow + g + 8)*68 + col] = make_float2(c[mt][nt][2], c[mt][nt][3]);
        }
    }
    __syncthreads();
    for (int idx = tid; idx < 128*16; idx += 256) {
        int pos = idx >> 4, q = idx & 15;
        int gy = y0 + (pos >> 4), gx = x0 + (pos & 15);
        *(float4*)&d_conv[(((size_t)bb*512 + gy)*48 + gx)*64 + q*4] =
            *(const float4*)&stage[pos*68 + q*4];
    }
    {
        int col = tid & 63, qtr = tid >> 6;
        float s = 0.f, s2 = 0.f;
        int r0 = qtr*32;
        for (int r = r0; r < r0+32; r++) {
            float v = stage[r*68 + col];
            s += v; s2 += v*v;
        }
        red[qtr*64 + col] = s;
        red[256 + qtr*64 + col] = s2;
        __syncthreads();
        if (qtr == 0) {
            atomicAdd(&d_stats[384+col], red[col] + red[64+col] + red[128+col] + red[192+col]);
            atomicAdd(&d_stats[448+col], red[256+col] + red[320+col] + red[384+col] + red[448+col]);
        }
        __syncthreads();
    }
    unsigned nblocks = gridDim.x * gridDim.y * gridDim.z;
    bn_finalize_inline(2, nblocks, tid, 64, 1.0f/98304.0f, 384, 384, gc, bc);
}

// ---------------- lin3: tf32 MMA [N,128]@[128,64], 2m x 4n warp tile, gather inlined ----------------
#define L3_SMEM ((128*132 + 128*72)*4)
__global__ void __launch_bounds__(256) k_lin3(const float* __restrict__ pts,
        const float* __restrict__ cylidx, const float* __restrict__ w3,
        const float* __restrict__ g3, const float* __restrict__ b3, int n, float invn) {
    extern __shared__ float dsm[];
    float* s_a = dsm;                 // [p][k] pitch 132
    float* s_b = dsm + 128*132;       // [k][o] pitch 72
    __shared__ float pa[64], pc[64], ca[64], cs[64];
    __shared__ float s_w4[4][128];
    __shared__ int   s_o4[4][128];
    __shared__ float red[512];
    int tid = threadIdx.x;
    if (tid < 64) {
        pa[tid] = d_bn[192+tid]; pc[tid] = d_bn[320+tid];
        ca[tid] = d_bn[384+tid]; cs[tid] = d_bn[448+tid];
    }
    for (int t = tid; t < 8192; t += 256) {
        int o = t >> 7, k = t & 127;
        s_b[k*72 + o] = __uint_as_float(tf32(w3[t]));
    }
    int pbase = blockIdx.x*128;
    if (tid < 128) {
        int p = pbase + tid;
        int i = (p < n) ? p : (n-1);
        float yq = cylidx[2*(size_t)i], xq = cylidx[2*(size_t)i+1];
        int y0i = (int)floorf(yq); int y1i = min(y0i+1, 511); y0i = min(max(y0i,0), 511);
        int x0i = (int)floorf(xq); int x1i = min(x0i+1, 47);  x0i = min(max(x0i,0), 47);
        s_w4[0][tid] = ((float)x1i - xq)*((float)y1i - yq);
        s_w4[1][tid] = ((float)x1i - xq)*(yq - (float)y0i);
        s_w4[2][tid] = (xq - (float)x0i)*((float)y1i - yq);
        s_w4[3][tid] = (xq - (float)x0i)*(yq - (float)y0i);
        int b = (int)pts[(size_t)i*5];
        int base = b*512*48*64;
        s_o4[0][tid] = base + (y0i*48 + x0i)*64;
        s_o4[1][tid] = base + (y1i*48 + x0i)*64;
        s_o4[2][tid] = base + (y0i*48 + x1i)*64;
        s_o4[3][tid] = base + (y1i*48 + x1i)*64;
    }
    __syncthreads();
    for (int idx = tid; idx < 128*16; idx += 256) {
        int lp = idx >> 4, kq = idx & 15;
        int p = pbase + lp, k = kq*4;
        uint4 tv = make_uint4(0u,0u,0u,0u);
        if (p < n) {
            float4 v = *(const float4*)&d_lin2[(size_t)p*128 + 64 + k];
            tv.x = tf32(fmaxf(fmaf(v.x, pa[k+0], pc[k+0]), 0.f));
            tv.y = tf32(fmaxf(fmaf(v.y, pa[k+1], pc[k+1]), 0.f));
            tv.z = tf32(fmaxf(fmaf(v.z, pa[k+2], pc[k+2]), 0.f));
            tv.w = tf32(fmaxf(fmaf(v.w, pa[k+3], pc[k+3]), 0.f));
        }
        *(uint4*)&s_a[lp*132 + k] = tv;
    }
    for (int idx = tid; idx < 128*16; idx += 256) {
        int lp = idx >> 4, kq = idx & 15;
        int p = pbase + lp, c = kq*4;
        uint4 tv = make_uint4(0u,0u,0u,0u);
        if (p < n) {
            float wa = s_w4[0][lp], wb = s_w4[1][lp], wcw = s_w4[2][lp], wd = s_w4[3][lp];
            float4 av = *(const float4*)&d_conv[s_o4[0][lp] + c];
            float4 bv = *(const float4*)&d_conv[s_o4[1][lp] + c];
            float4 cv = *(const float4*)&d_conv[s_o4[2][lp] + c];
            float4 dv = *(const float4*)&d_conv[s_o4[3][lp] + c];
            float rx = wa*fmaxf(fmaf(av.x, ca[c+0], cs[c+0]),0.f) + wb*fmaxf(fmaf(bv.x, ca[c+0], cs[c+0]),0.f)
                + wcw*fmaxf(fmaf(cv.x, ca[c+0], cs[c+0]),0.f) + wd*fmaxf(fmaf(dv.x, ca[c+0], cs[c+0]),0.f);
            float ry = wa*fmaxf(fmaf(av.y, ca[c+1], cs[c+1]),0.f) + wb*fmaxf(fmaf(bv.y, ca[c+1], cs[c+1]),0.f)
                + wcw*fmaxf(fmaf(cv.y, ca[c+1], cs[c+1]),0.f) + wd*fmaxf(fmaf(dv.y, ca[c+1], cs[c+1]),0.f);
            float rz = wa*fmaxf(fmaf(av.z, ca[c+2], cs[c+2]),0.f) + wb*fmaxf(fmaf(bv.z, ca[c+2], cs[c+2]),0.f)
                + wcw*fmaxf(fmaf(cv.z, ca[c+2], cs[c+2]),0.f) + wd*fmaxf(fmaf(dv.z, ca[c+2], cs[c+2]),0.f);
            float rw = wa*fmaxf(fmaf(av.w, ca[c+3], cs[c+3]),0.f) + wb*fmaxf(fmaf(bv.w, ca[c+3], cs[c+3]),0.f)
                + wcw*fmaxf(fmaf(cv.w, ca[c+3], cs[c+3]),0.f) + wd*fmaxf(fmaf(dv.w, ca[c+3], cs[c+3]),0.f);
            tv.x = tf32(rx); tv.y = tf32(ry); tv.z = tf32(rz); tv.w = tf32(rw);
        }
        *(uint4*)&s_a[lp*132 + 64 + c] = tv;
    }
    __syncthreads();
    int wid = tid >> 5, lane = tid & 31;
    int g = lane >> 2, tg = lane & 3;
    int wm = wid >> 1, wn = wid & 1;
    int m0 = wm*32;
    const uint* ua = (const uint*)s_a;
    const uint* ub = (const uint*)s_b;
    float c[2][4][4];
    #pragma unroll
    for (int mt = 0; mt < 2; mt++)
        #pragma unroll
        for (int nt = 0; nt < 4; nt++)
            #pragma unroll
            for (int j = 0; j < 4; j++) c[mt][nt][j] = 0.f;
    #pragma unroll
    for (int kc = 0; kc < 16; kc++) {
        int k0 = kc*8;
        uint a0[2], a1[2], a2[2], a3[2];
        #pragma unroll
        for (int mt = 0; mt < 2; mt++) {
            int mb = m0 + mt*16;
            a0[mt] = ua[(mb+g)*132   + k0 + tg];
            a1[mt] = ua[(mb+g+8)*132 + k0 + tg];
            a2[mt] = ua[(mb+g)*132   + k0 + tg + 4];
            a3[mt] = ua[(mb+g+8)*132 + k0 + tg + 4];
        }
        #pragma unroll
        for (int nt = 0; nt < 4; nt++) {
            int col = wn*32 + nt*8 + g;
            uint b0 = ub[(k0+tg)*72   + col];
            uint b1 = ub[(k0+tg+4)*72 + col];
            mma_tf32(c[0][nt], a0[0], a1[0], a2[0], a3[0], b0, b1);
            mma_tf32(c[1][nt], a0[1], a1[1], a2[1], a3[1], b0, b1);
        }
    }
    __syncthreads();
    float* stage = dsm;              // [p][o] pitch 68
    #pragma unroll
    for (int mt = 0; mt < 2; mt++) {
        int mb = m0 + mt*16;
        #pragma unroll
        for (int nt = 0; nt < 4; nt++) {
            int n0 = wn*32 + nt*8 + tg*2;
            *(float2*)&stage[(mb+g)*68   + n0] = make_float2(c[mt][nt][0], c[mt][nt][1]);
            *(float2*)&stage[(mb+g+8)*68 + n0] = make_float2(c[mt][nt][2], c[mt][nt][3]);
        }
    }
    __syncthreads();
    for (int idx = tid; idx < 128*16; idx += 256) {
        int lp = idx >> 4, q = idx & 15;
        int p = pbase + lp;
        if (p < n)
            *(float4*)&d_lin3[(size_t)p*64 + q*4] = *(const float4*)&stage[lp*68 + q*4];
    }
    {
        int col = tid & 63, qtr = tid >> 6;
        float s = 0.f, s2 = 0.f;
        int r0 = qtr*32;
        for (int r = r0; r < r0+32; r++) {
            float v = stage[r*68 + col];
            s += v; s2 += v*v;
        }
        red[qtr*64 + col] = s;
        red[256 + qtr*64 + col] = s2;
        __syncthreads();
        if (qtr == 0) {
            atomicAdd(&d_stats[512+col], red[col] + red[64+col] + red[128+col] + red[192+col]);
            atomicAdd(&d_stats[576+col], red[256+col] + red[320+col] + red[384+col] + red[448+col]);
        }
        __syncthreads();
    }
    bn_finalize_inline(3, gridDim.x, tid, 64, invn, 512, 512, g3, b3);
}

// final: bn_relu(lin3) -> out; atomicMax into bev_max; extra blocks do voxel coords
__global__ void k_final(const int* __restrict__ binv, const int* __restrict__ bcoord,
                        float* __restrict__ out, int n, int nb, int nblk) {
    if (blockIdx.x >= nblk) {
        int i = (blockIdx.x - nblk)*blockDim.x + threadIdx.x;
        if (i < nb) {
            int c = bcoord[i];
            int vb = c / 55000;
            int r  = c % 55000;
            int vx = r / 250;
            int vy = r % 250;
            float* o = out + (size_t)n*64 + (size_t)nb*64 + (size_t)i*4;
            o[0] = (float)vb; o[1] = 0.f; o[2] = (float)vy; o[3] = (float)vx;
        }
        return;
    }
    __shared__ float sa[64], sc[64];
    if (threadIdx.x < 64) { sa[threadIdx.x] = d_bn[512+threadIdx.x]; sc[threadIdx.x] = d_bn[576+threadIdx.x]; }
    __syncthreads();
    int i = blockIdx.x*blockDim.x + threadIdx.x;
    if (i >= n) return;
    int bi = binv[i];
    const float4* src = (const float4*)&d_lin3[(size_t)i*64];
    float4* dst = (float4*)(out + (size_t)i*64);
    unsigned* mx = (unsigned*)(out + (size_t)n*64 + (size_t)bi*64);
    #pragma unroll
    for (int j = 0; j < 16; j++) {
        float4 v = src[j];
        int c = j*4;
        float r0 = fmaxf(fmaf(v.x, sa[c+0], sc[c+0]), 0.f);
        float r1 = fmaxf(fmaf(v.y, sa[c+1], sc[c+1]), 0.f);
        float r2 = fmaxf(fmaf(v.z, sa[c+2], sc[c+2]), 0.f);
        float r3 = fmaxf(fmaf(v.w, sa[c+3], sc[c+3]), 0.f);
        dst[j] = make_float4(r0, r1, r2, r3);
        atomicMax(mx+c+0, __float_as_uint(r0));
        atomicMax(mx+c+1, __float_as_uint(r1));
        atomicMax(mx+c+2, __float_as_uint(r2));
        atomicMax(mx+c+3, __float_as_uint(r3));
    }
}

// ---------------- launcher ----------------
extern "C" void kernel_launch(void* const* d_in, const int* in_sizes, int n_in,
                              void* d_out, int out_size) {
    const float* points = (const float*)d_in[0];
    const float* pcyl   = (const float*)d_in[1];
    const float* cylidx = (const float*)d_in[2];
    const float* bevidx = (const float*)d_in[3];
    const float* w1 = (const float*)d_in[4];
    const float* g1 = (const float*)d_in[5];
    const float* b1 = (const float*)d_in[6];
    const float* w2 = (const float*)d_in[7];
    const float* g2 = (const float*)d_in[8];
    const float* b2 = (const float*)d_in[9];
    const float* wc = (const float*)d_in[10];
    const float* gc = (const float*)d_in[11];
    const float* bc = (const float*)d_in[12];
    const float* w3 = (const float*)d_in[13];
    const float* g3 = (const float*)d_in[14];
    const float* b3 = (const float*)d_in[15];
    const int* binv   = (const int*)d_in[16];
    const int* bcoord = (const int*)d_in[17];
    const int* cinv   = (const int*)d_in[18];

    int n  = in_sizes[0] / 5;
    int nb = in_sizes[17];
    int nc = in_sizes[19];
    float* out = (float*)d_out;
    float invn = 1.0f/(float)n;

    static bool attr_done = false;
    if (!attr_done) {
        cudaFuncSetAttribute(k_lin1, cudaFuncAttributeMaxDynamicSharedMemorySize, L1_SMEM);
        cudaFuncSetAttribute(k_conv, cudaFuncAttributeMaxDynamicSharedMemorySize, CV_SMEM);
        cudaFuncSetAttribute(k_lin2, cudaFuncAttributeMaxDynamicSharedMemorySize, L2_SMEM);
        cudaFuncSetAttribute(k_lin3, cudaFuncAttributeMaxDynamicSharedMemorySize, L3_SMEM);
        attr_done = true;
    }

    int nblk = (n + 255) / 256;
    int gblk = (n + 127) / 128;
    k_zero<<<512, 256>>>(out + (size_t)n*64, nb, nc, wc);
    k_scatter<<<nblk, 256>>>(points, pcyl, binv, cinv, n);
    k_lin1<<<nblk, 256, L1_SMEM>>>(points, pcyl, cylidx, bevidx, binv, cinv, w1, g1, b1, n, invn);
    k_lin2<<<gblk, 256, L2_SMEM>>>(w2, g2, b2, n, invn);
    k_cylmax<<<nblk, 256>>>(points, cylidx, n);
    dim3 cg(3, 64, 4);
    k_conv<<<cg, 256, CV_SMEM>>>(gc, bc);
    k_lin3<<<gblk, 256, L3_SMEM>>>(points, cylidx, w3, g3, b3, n, invn);
    int vblk = (nb + 255) / 256;
    k_final<<<nblk + vblk, 256>>>(binv, bcoord, out, n, nb, nblk);
}

// round 13
// speedup vs baseline: 1.3776x; 1.0148x over previous
#include <cuda_runtime.h>
#include <math.h>

typedef unsigned long long ull;
typedef unsigned int uint;

// ---------------- problem constants ----------------
#define NPTS_MAX 200000
#define NB_MAX   220000
#define NC_MAX   98304
#define IMG_ELEMS (4*512*48*64)

#define CVS0 (6.2831853f/512.0f)
#define CVS1 0.125f
#define CR0  (-3.14159265f)
#define CR1  (-2.0f)

// ---------------- scratch ----------------
__device__ float d_lin1[(size_t)NPTS_MAX*64];
__device__ float d_lin2[(size_t)NPTS_MAX*128];
__device__ float d_lin3[(size_t)NPTS_MAX*64];
__device__ float d_dense[IMG_ELEMS];
__device__ float d_conv[IMG_ELEMS];
__device__ float d_bevsum[NB_MAX*4];
__device__ float d_cylsum[NC_MAX*4];
__device__ float d_stats[1024];
__device__ float d_bn[1024];  // lin1 a@0 c@64; lin2 a@128 c@256; conv a@384 c@448; lin3 a@512 c@576
__device__ unsigned d_ctr[8];
__device__ float d_wt_hi[3*192*64];
__device__ uint  d_wcb_h[3*96*64];
__device__ uint  d_wcb_l[3*96*64];

// ---------------- helpers ----------------
__device__ __forceinline__ uint tf32(float f) {
    uint r; asm("cvt.rna.tf32.f32 %0, %1;" : "=r"(r) : "f"(f)); return r;
}
__device__ __forceinline__ void tf32split(float v, float& hi, float& lo) {
    uint h = tf32(v);
    hi = __uint_as_float(h);
    lo = v - hi;
}
__device__ __forceinline__ uint pkbf2(float ev, float od) {
    uint r; asm("cvt.rn.bf16x2.f32 %0, %1, %2;" : "=r"(r) : "f"(od), "f"(ev)); return r;
}
__device__ __forceinline__ void mma_tf32(float* c, uint a0, uint a1, uint a2, uint a3, uint b0, uint b1) {
    asm volatile("mma.sync.aligned.m16n8k8.row.col.f32.tf32.tf32.f32 "
                 "{%0,%1,%2,%3},{%4,%5,%6,%7},{%8,%9},{%0,%1,%2,%3};"
                 : "+f"(c[0]), "+f"(c[1]), "+f"(c[2]), "+f"(c[3])
                 : "r"(a0), "r"(a1), "r"(a2), "r"(a3), "r"(b0), "r"(b1));
}
__device__ __forceinline__ void mma_bf16(float* c, uint a0, uint a1, uint a2, uint a3, uint b0, uint b1) {
    asm volatile("mma.sync.aligned.m16n8k16.row.col.f32.bf16.bf16.f32 "
                 "{%0,%1,%2,%3},{%4,%5,%6,%7},{%8,%9},{%0,%1,%2,%3};"
                 : "+f"(c[0]), "+f"(c[1]), "+f"(c[2]), "+f"(c[3])
                 : "r"(a0), "r"(a1), "r"(a2), "r"(a3), "r"(b0), "r"(b1));
}
__device__ __forceinline__ void bn_finalize_inline(int ctr_idx, unsigned nblocks, int tid,
                                                   int C, float invn, int sbase, int bbase,
                                                   const float* g, const float* b) {
    __threadfence();
    __shared__ unsigned s_ord;
    if (tid == 0) s_ord = atomicAdd(&d_ctr[ctr_idx], 1u);
    __syncthreads();
    if (s_ord == nblocks - 1 && tid < C) {
        float m = __ldcg(&d_stats[sbase + tid]) * invn;
        float v = __ldcg(&d_stats[sbase + C + tid]) * invn - m*m;
        float a = g[tid] * rsqrtf(v + 1e-3f);
        d_bn[bbase + tid]     = a;
        d_bn[bbase + C + tid] = b[tid] - m*a;
    }
}

// ---------------- utility kernels ----------------
__global__ void __launch_bounds__(256) k_zero(float* outbev, int nb, int nc,
                                              const float* __restrict__ wc) {
    size_t tid = (size_t)blockIdx.x * blockDim.x + threadIdx.x;
    size_t stride = (size_t)gridDim.x * blockDim.x;
    if (tid < 18432) {
        int t = (int)tid;
        int f = t & 63;
        int q = t >> 6;
        int cinp = q & 31;
        int dxy = q >> 5;
        int dx = dxy % 3, dy = dxy / 3;
        int cin0 = cinp*2;
        float v0 = wc[(size_t)f*576 + cin0*9     + dy*3 + dx];
        float v1 = wc[(size_t)f*576 + (cin0+1)*9 + dy*3 + dx];
        float h0, l0, h1, l1;
        tf32split(v0, h0, l0);
        tf32split(v1, h1, l1);
        d_wt_hi[dy*12288 + (dx*64+cin0)*64 + f]   = h0;
        d_wt_hi[dy*12288 + (dx*64+cin0+1)*64 + f] = h1;
        d_wcb_h[dy*6144 + (dx*32+cinp)*64 + f] = pkbf2(h0, h1);
        d_wcb_l[dy*6144 + (dx*32+cinp)*64 + f] = pkbf2(l0, l1);
    }
    float4 z = make_float4(0.f, 0.f, 0.f, 0.f);
    float4* p = (float4*)d_dense;
    for (size_t i = tid; i < IMG_ELEMS/4; i += stride) p[i] = z;
    float4* q = (float4*)outbev;
    size_t obw = (size_t)nb * 16;
    for (size_t i = tid; i < obw; i += stride) q[i] = z;
    float4* bs = (float4*)d_bevsum;
    for (size_t i = tid; i < (size_t)nb; i += stride) bs[i] = z;
    float4* cs = (float4*)d_cylsum;
    for (size_t i = tid; i < (size_t)nc; i += stride) cs[i] = z;
    if (tid < 256) ((float4*)d_stats)[tid] = z;
    if (tid < 8) d_ctr[tid] = 0u;
}

__global__ void k_scatter(const float* __restrict__ pts, const float* __restrict__ pcyl,
                          const int* __restrict__ binv, const int* __restrict__ cinv, int n) {
    int i = blockIdx.x*blockDim.x + threadIdx.x;
    if (i >= n) return;
    float x = pts[(size_t)i*5+1], y = pts[(size_t)i*5+2], z = pts[(size_t)i*5+3];
    int bi = binv[i], ci = cinv[i];
    atomicAdd(&d_bevsum[bi*4+0], x);
    atomicAdd(&d_bevsum[bi*4+1], y);
    atomicAdd(&d_bevsum[bi*4+2], z);
    atomicAdd(&d_bevsum[bi*4+3], 1.0f);
    float p0 = pcyl[(size_t)i*3], p1 = pcyl[(size_t)i*3+1], p2 = pcyl[(size_t)i*3+2];
    atomicAdd(&d_cylsum[ci*4+0], p0);
    atomicAdd(&d_cylsum[ci*4+1], p1);
    atomicAdd(&d_cylsum[ci*4+2], p2);
    atomicAdd(&d_cylsum[ci*4+3], 1.0f);
}

// ---------------- lin1: tf32+bf16corr MMA [N,16]@[16,64], fused stats ----------------
#define L1_SMEM (17408*4)
__global__ void __launch_bounds__(256) k_lin1(
        const float* __restrict__ pts, const float* __restrict__ pcyl,
        const float* __restrict__ cylidx, const float* __restrict__ bevidx,
        const int* __restrict__ binv, const int* __restrict__ cinv,
        const float* __restrict__ w1, const float* __restrict__ g1,
        const float* __restrict__ b1, int n, float invn) {
    extern __shared__ float dsm[];
    float* s_a  = dsm;                       // [p][k] pitch 20
    uint*  s_cah = (uint*)(dsm + 5120);      // [p][kp] pitch 12
    uint*  s_cal = s_cah + 3072;
    float* s_b  = (float*)(s_cal + 3072);    // [k][o] pitch 68
    uint*  s_bch = (uint*)(s_b + 1088);      // [kp][o] pitch 72
    uint*  s_bcl = s_bch + 576;
    __shared__ float red[512];
    int tid = threadIdx.x;
    for (int t = tid; t < 512; t += 256) {
        int o = t & 63, kp = t >> 6;
        float h0,l0,h1,l1;
        tf32split(w1[o*16 + 2*kp],   h0, l0);
        tf32split(w1[o*16 + 2*kp+1], h1, l1);
        s_b[(2*kp)*68 + o]   = h0;
        s_b[(2*kp+1)*68 + o] = h1;
        s_bch[kp*72 + o] = pkbf2(h0, h1);
        s_bcl[kp*72 + o] = pkbf2(l0, l1);
    }
    int pbase = blockIdx.x*256;
    int p = pbase + tid;
    {
        float f[16];
        #pragma unroll
        for (int k = 0; k < 16; k++) f[k] = 0.f;
        if (p < n) {
            size_t i = (size_t)p;
            float x = pts[i*5+1], y = pts[i*5+2], z = pts[i*5+3], it = pts[i*5+4];
            float phi = pcyl[i*3], zc = pcyl[i*3+1], rho = pcyl[i*3+2];
            float bix = bevidx[2*i], biy = bevidx[2*i+1];
            float cix = cylidx[2*i], ciy = cylidx[2*i+1];
            int bi = binv[p], ci = cinv[p];
            float bcnt = d_bevsum[bi*4+3];
            float bmx = d_bevsum[bi*4]/bcnt, bmy = d_bevsum[bi*4+1]/bcnt;
            float ccnt = d_cylsum[ci*4+3];
            float cm0 = d_cylsum[ci*4]/ccnt, cm1 = d_cylsum[ci*4+1]/ccnt;
            f[0]=x; f[1]=y; f[2]=z; f[3]=phi; f[4]=zc; f[5]=rho;
            f[6] = x - ((floorf(bix)+0.5f)*0.32f + 0.0f);
            f[7] = y - ((floorf(biy)+0.5f)*0.32f + (-40.0f));
            f[8] = phi - ((floorf(cix)+0.5f)*CVS0 + CR0);
            f[9] = zc  - ((floorf(ciy)+0.5f)*CVS1 + CR1);
            f[10]= x - bmx; f[11]= y - bmy;
            f[12]= phi - cm0; f[13]= zc - cm1;
            f[14]= sqrtf(x*x + y*y + z*z);
            f[15]= it;
        }
        float h[16], l[16];
        #pragma unroll
        for (int k = 0; k < 16; k++) tf32split(f[k], h[k], l[k]);
        #pragma unroll
        for (int k4 = 0; k4 < 4; k4++)
            *(float4*)&s_a[tid*20 + k4*4] = make_float4(h[4*k4],h[4*k4+1],h[4*k4+2],h[4*k4+3]);
        #pragma unroll
        for (int kp = 0; kp < 8; kp++) {
            s_cah[tid*12 + kp] = pkbf2(h[2*kp], h[2*kp+1]);
            s_cal[tid*12 + kp] = pkbf2(l[2*kp], l[2*kp+1]);
        }
    }
    __syncthreads();
    int wid = tid >> 5, lane = tid & 31;
    int g = lane >> 2, tg = lane & 3;
    int m0 = wid*32;
    const uint* ua = (const uint*)s_a;
    const uint* ub = (const uint*)s_b;
    float c[2][8][4];
    #pragma unroll
    for (int mt = 0; mt < 2; mt++)
        #pragma unroll
        for (int nt = 0; nt < 8; nt++)
            #pragma unroll
            for (int j = 0; j < 4; j++) c[mt][nt][j] = 0.f;
    #pragma unroll
    for (int kc = 0; kc < 2; kc++) {
        int k0 = kc*8, kp0 = kc*4;
        uint a0[2], a1[2], a2[2], a3[2], ac0[2], ac1[2], ac2[2], ac3[2];
        #pragma unroll
        for (int mt = 0; mt < 2; mt++) {
            int mb = m0 + mt*16;
            a0[mt] = ua[(mb+g)*20   + k0 + tg];
            a1[mt] = ua[(mb+g+8)*20 + k0 + tg];
            a2[mt] = ua[(mb+g)*20   + k0 + tg + 4];
            a3[mt] = ua[(mb+g+8)*20 + k0 + tg + 4];
            ac0[mt] = s_cah[(mb+g)*12   + kp0 + tg];
            ac1[mt] = s_cah[(mb+g+8)*12 + kp0 + tg];
            ac2[mt] = s_cal[(mb+g)*12   + kp0 + tg];
            ac3[mt] = s_cal[(mb+g+8)*12 + kp0 + tg];
        }
        #pragma unroll
        for (int nt = 0; nt < 8; nt++) {
            int col = nt*8 + g;
            uint b0 = ub[(k0+tg)*68   + col];
            uint b1 = ub[(k0+tg+4)*68 + col];
            uint bc0 = s_bcl[(kp0+tg)*72 + col];
            uint bc1 = s_bch[(kp0+tg)*72 + col];
            #pragma unroll
            for (int mt = 0; mt < 2; mt++) {
                mma_tf32(c[mt][nt], a0[mt], a1[mt], a2[mt], a3[mt], b0, b1);
                mma_bf16(c[mt][nt], ac0[mt], ac1[mt], ac2[mt], ac3[mt], bc0, bc1);
            }
        }
    }
    __syncthreads();
    float* stage = dsm;              // [p][o] pitch 68
    #pragma unroll
    for (int mt = 0; mt < 2; mt++) {
        int mb = m0 + mt*16;
        #pragma unroll
        for (int nt = 0; nt < 8; nt++) {
            int n0 = nt*8 + tg*2;
            *(float2*)&stage[(mb+g)*68   + n0] = make_float2(c[mt][nt][0], c[mt][nt][1]);
            *(float2*)&stage[(mb+g+8)*68 + n0] = make_float2(c[mt][nt][2], c[mt][nt][3]);
        }
    }
    __syncthreads();
    for (int idx = tid; idx < 256*16; idx += 256) {
        int lp = idx >> 4, q = idx & 15;
        int pp = pbase + lp;
        if (pp < n)
            *(float4*)&d_lin1[(size_t)pp*64 + q*4] = *(const float4*)&stage[lp*68 + q*4];
    }
    {
        int col = tid & 63, qtr = tid >> 6;
        float s = 0.f, s2 = 0.f;
        int r0 = qtr*64;
        for (int r = r0; r < r0+64; r++) {
            float v = stage[r*68 + col];
            s += v; s2 += v*v;
        }
        red[qtr*64 + col] = s;
        red[256 + qtr*64 + col] = s2;
        __syncthreads();
        if (qtr == 0) {
            atomicAdd(&d_stats[col],    red[col] + red[64+col] + red[128+col] + red[192+col]);
            atomicAdd(&d_stats[64+col], red[256+col] + red[320+col] + red[384+col] + red[448+col]);
        }
        __syncthreads();
    }
    bn_finalize_inline(0, gridDim.x, tid, 64, invn, 0, 0, g1, b1);
}

// ---------------- lin2: tf32 MMA GEMM [N,64]@[64,128], 1m x 16n warp tile (R11 shape) ----------------
#define L2_SMEM (17408*4)
__global__ void __launch_bounds__(256) k_lin2(const float* __restrict__ w2,
        const float* __restrict__ g2, const float* __restrict__ b2, int n, float invn) {
    extern __shared__ float dsm[];
    float* s_a = dsm;                // [p][k] pitch 68
    float* s_b = dsm + 128*68;       // [k][o] pitch 136
    __shared__ float sa[64], sc[64];
    __shared__ float red[512];
    int tid = threadIdx.x;
    if (tid < 64) { sa[tid] = d_bn[tid]; sc[tid] = d_bn[64+tid]; }
    for (int t = tid; t < 8192; t += 256) {
        int o = t >> 6, k = t & 63;
        s_b[k*136 + o] = __uint_as_float(tf32(w2[t]));
    }
    __syncthreads();
    int pbase = blockIdx.x*128;
    for (int idx = tid; idx < 128*16; idx += 256) {
        int lp = idx >> 4, kq = idx & 15;
        int p = pbase + lp, k = kq*4;
        uint4 tv = make_uint4(0u,0u,0u,0u);
        if (p < n) {
            float4 v = *(const float4*)&d_lin1[(size_t)p*64 + k];
            tv.x = tf32(fmaxf(fmaf(v.x, sa[k+0], sc[k+0]), 0.f));
            tv.y = tf32(fmaxf(fmaf(v.y, sa[k+1], sc[k+1]), 0.f));
            tv.z = tf32(fmaxf(fmaf(v.z, sa[k+2], sc[k+2]), 0.f));
            tv.w = tf32(fmaxf(fmaf(v.w, sa[k+3], sc[k+3]), 0.f));
        }
        *(uint4*)&s_a[lp*68 + k] = tv;
    }
    __syncthreads();
    int wid = tid >> 5, lane = tid & 31;
    int g = lane >> 2, tg = lane & 3;
    int m0 = wid*16;
    const uint* ua = (const uint*)s_a;
    const uint* ub = (const uint*)s_b;
    float c[16][4];
    #pragma unroll
    for (int nt = 0; nt < 16; nt++)
        #pragma unroll
        for (int j = 0; j < 4; j++) c[nt][j] = 0.f;
    #pragma unroll
    for (int kc = 0; kc < 8; kc++) {
        int k0 = kc*8;
        uint a0 = ua[(m0+g)*68   + k0 + tg];
        uint a1 = ua[(m0+g+8)*68 + k0 + tg];
        uint a2 = ua[(m0+g)*68   + k0 + tg + 4];
        uint a3 = ua[(m0+g+8)*68 + k0 + tg + 4];
        #pragma unroll
        for (int nt = 0; nt < 16; nt++) {
            uint b0 = ub[(k0+tg)*136   + nt*8 + g];
            uint b1 = ub[(k0+tg+4)*136 + nt*8 + g];
            mma_tf32(c[nt], a0, a1, a2, a3, b0, b1);
        }
    }
    __syncthreads();
    float* stage = dsm;              // [p][o] pitch 132
    #pragma unroll
    for (int nt = 0; nt < 16; nt++) {
        int n0 = nt*8 + tg*2;
        *(float2*)&stage[(m0+g)*132   + n0] = make_float2(c[nt][0], c[nt][1]);
        *(float2*)&stage[(m0+g+8)*132 + n0] = make_float2(c[nt][2], c[nt][3]);
    }
    __syncthreads();
    for (int idx = tid; idx < 128*32; idx += 256) {
        int lp = idx >> 5, q = idx & 31;
        int p = pbase + lp;
        if (p < n)
            *(float4*)&d_lin2[(size_t)p*128 + q*4] = *(const float4*)&stage[lp*132 + q*4];
    }
    {
        int col = tid & 127, half = tid >> 7;
        float s = 0.f, s2 = 0.f;
        int r0 = half*64;
        for (int r = r0; r < r0+64; r++) {
            float v = stage[r*132 + col];
            s += v; s2 += v*v;
        }
        red[half*128 + col] = s;
        red[256 + half*128 + col] = s2;
        __syncthreads();
        if (half == 0) {
            atomicAdd(&d_stats[128+col], red[col] + red[128+col]);
            atomicAdd(&d_stats[256+col], red[256+col] + red[384+col]);
        }
        __syncthreads();
    }
    bn_finalize_inline(1, gridDim.x, tid, 128, invn, 128, 128, g2, b2);
}

// segment-max of bn_relu(lin2[:, :64]) into dense image
__global__ void k_cylmax(const float* __restrict__ pts, const float* __restrict__ cylidx, int n) {
    __shared__ float sa[64], sc[64];
    if (threadIdx.x < 64) { sa[threadIdx.x] = d_bn[128+threadIdx.x]; sc[threadIdx.x] = d_bn[256+threadIdx.x]; }
    __syncthreads();
    int i = blockIdx.x*blockDim.x + threadIdx.x;
    if (i >= n) return;
    int b = (int)pts[(size_t)i*5];
    int iy = (int)floorf(cylidx[2*(size_t)i]);   iy = max(0, min(iy, 511));
    int ix = (int)floorf(cylidx[2*(size_t)i+1]); ix = max(0, min(ix, 47));
    unsigned* dst = (unsigned*)&d_dense[(((size_t)b*512 + iy)*48 + ix)*64];
    const float4* src = (const float4*)&d_lin2[(size_t)i*128];
    #pragma unroll
    for (int j = 0; j < 16; j++) {
        float4 v = src[j];
        int c = j*4;
        float r0 = fmaxf(fmaf(v.x, sa[c+0], sc[c+0]), 0.f);
        float r1 = fmaxf(fmaf(v.y, sa[c+1], sc[c+1]), 0.f);
        float r2 = fmaxf(fmaf(v.z, sa[c+2], sc[c+2]), 0.f);
        float r3 = fmaxf(fmaf(v.w, sa[c+3], sc[c+3]), 0.f);
        atomicMax(dst+c+0, __float_as_uint(r0));
        atomicMax(dst+c+1, __float_as_uint(r1));
        atomicMax(dst+c+2, __float_as_uint(r2));
        atomicMax(dst+c+3, __float_as_uint(r3));
    }
}

// ---------------- conv: tf32 + bf16 corr MMA, 2m x 4n warp tile, fused stats ----------------
#define CV_SMEM ((180*68 + 180*36*2 + 192*72 + 96*72*2)*4)
__global__ void __launch_bounds__(256) k_conv(const float* __restrict__ gc,
                                              const float* __restrict__ bc) {
    extern __shared__ float dsm[];
    float* s_ih  = dsm;                       // [pos][cin] pitch 68
    uint*  s_cah = (uint*)(dsm + 180*68);     // [pos][cinpair] pitch 36
    uint*  s_cal = s_cah + 180*36;
    float* s_wh  = (float*)(s_cal + 180*36);  // [k][f] pitch 72
    uint*  s_cwh = (uint*)(s_wh + 192*72);    // [kpair][f] pitch 72
    uint*  s_cwl = s_cwh + 96*72;
    __shared__ float red[512];
    int x0 = blockIdx.x*16, y0 = blockIdx.y*8, bb = blockIdx.z;
    int tid = threadIdx.x;
    for (int idx = tid; idx < 180*16; idx += 256) {
        int pos = idx >> 4, c4 = idx & 15;
        int hy = pos / 18, hx = pos - hy*18;
        int gy = y0 + hy - 1, gx = x0 + hx - 1;
        float4 v = make_float4(0.f,0.f,0.f,0.f);
        if (gy >= 0 && gy < 512 && gx >= 0 && gx < 48)
            v = *(const float4*)&d_dense[(((size_t)bb*512 + gy)*48 + gx)*64 + c4*4];
        float h0,l0,h1,l1,h2,l2,h3,l3;
        tf32split(v.x, h0, l0); tf32split(v.y, h1, l1);
        tf32split(v.z, h2, l2); tf32split(v.w, h3, l3);
        *(float4*)&s_ih[pos*68 + c4*4] = make_float4(h0,h1,h2,h3);
        s_cah[pos*36 + c4*2]   = pkbf2(h0, h1);
        s_cah[pos*36 + c4*2+1] = pkbf2(h2, h3);
        s_cal[pos*36 + c4*2]   = pkbf2(l0, l1);
        s_cal[pos*36 + c4*2+1] = pkbf2(l2, l3);
    }
    int wid = tid >> 5, lane = tid & 31;
    int g = lane >> 2, tg = lane & 3;
    int wm = wid >> 1, wn = wid & 1;
    const uint* uih = (const uint*)s_ih;
    const uint* uwh = (const uint*)s_wh;
    float c[2][4][4];
    #pragma unroll
    for (int mt = 0; mt < 2; mt++)
        #pragma unroll
        for (int nt = 0; nt < 4; nt++)
            #pragma unroll
            for (int j = 0; j < 4; j++) c[mt][nt][j] = 0.f;
    for (int dy = 0; dy < 3; dy++) {
        __syncthreads();
        for (int t = tid; t < 12288; t += 256) {
            int k = t >> 6, f = t & 63;
            s_wh[k*72 + f] = d_wt_hi[dy*12288 + t];
        }
        for (int t = tid; t < 6144; t += 256) {
            int kp = t >> 6, f = t & 63;
            s_cwh[kp*72 + f] = d_wcb_h[dy*6144 + t];
            s_cwl[kp*72 + f] = d_wcb_l[dy*6144 + t];
        }
        __syncthreads();
        #pragma unroll
        for (int ch = 0; ch < 24; ch++) {
            int dx = ch >> 3, cin0 = (ch & 7)*8;
            int k0 = ch*8, kp0 = ch*4;
            int cp0 = (ch & 7)*4;
            uint a0[2], a1[2], a2[2], a3[2], ac0[2], ac1[2], ac2[2], ac3[2];
            #pragma unroll
            for (int mt = 0; mt < 2; mt++) {
                int hbase = (2*wm + mt + dy)*18;
                int pos0 = hbase + g + dx, pos1 = pos0 + 8;
                a0[mt] = uih[pos0*68 + cin0 + tg];
                a1[mt] = uih[pos1*68 + cin0 + tg];
                a2[mt] = uih[pos0*68 + cin0 + tg + 4];
                a3[mt] = uih[pos1*68 + cin0 + tg + 4];
                ac0[mt] = s_cah[pos0*36 + cp0 + tg];
                ac1[mt] = s_cah[pos1*36 + cp0 + tg];
                ac2[mt] = s_cal[pos0*36 + cp0 + tg];
                ac3[mt] = s_cal[pos1*36 + cp0 + tg];
            }
            #pragma unroll
            for (int nt = 0; nt < 4; nt++) {
                int col = wn*32 + nt*8 + g;
                uint b0 = uwh[(k0+tg)*72   + col];
                uint b1 = uwh[(k0+tg+4)*72 + col];
                uint bc0 = s_cwl[(kp0+tg)*72 + col];
                uint bc1 = s_cwh[(kp0+tg)*72 + col];
                #pragma unroll
                for (int mt = 0; mt < 2; mt++) {
                    mma_tf32(c[mt][nt], a0[mt], a1[mt], a2[mt], a3[mt], b0, b1);
                    mma_bf16(c[mt][nt], ac0[mt], ac1[mt], ac2[mt], ac3[mt], bc0, bc1);
                }
            }
        }
    }
    float* stage = (float*)s_cah;    // [pos][ch] pitch 68
    __syncthreads();
    #pragma unroll
    for (int mt = 0; mt < 2; mt++) {
        int prow = (2*wm + mt)*16;
        #pragma unroll
        for (int nt = 0; nt < 4; nt++) {
            int col = wn*32 + nt*8 + tg*2;
            *(float2*)&stage[(prow + g)*68   + col] = make_float2(c[mt][nt][0], c[mt][nt][1]);
            *(float2*)&stage[(prow + g + 8)*68 + col] = make_float2(c[mt][nt][2], c[mt][nt][3]);
        }
    }
    __syncthreads();
    for (int idx = tid; idx < 128*16; idx += 256) {
        int pos = idx >> 4, q = idx & 15;
        int gy = y0 + (pos >> 4), gx = x0 + (pos & 15);
        *(float4*)&d_conv[(((size_t)bb*512 + gy)*48 + gx)*64 + q*4] =
            *(const float4*)&stage[pos*68 + q*4];
    }
    {
        int col = tid & 63, qtr = tid >> 6;
        float s = 0.f, s2 = 0.f;
        int r0 = qtr*32;
        for (int r = r0; r < r0+32; r++) {
            float v = stage[r*68 + col];
            s += v; s2 += v*v;
        }
        red[qtr*64 + col] = s;
        red[256 + qtr*64 + col] = s2;
        __syncthreads();
        if (qtr == 0) {
            atomicAdd(&d_stats[384+col], red[col] + red[64+col] + red[128+col] + red[192+col]);
            atomicAdd(&d_stats[448+col], red[256+col] + red[320+col] + red[384+col] + red[448+col]);
        }
        __syncthreads();
    }
    unsigned nblocks = gridDim.x * gridDim.y * gridDim.z;
    bn_finalize_inline(2, nblocks, tid, 64, 1.0f/98304.0f, 384, 384, gc, bc);
}

// ---------------- lin3: tf32 MMA [N,128]@[128,64], 2m x 4n warp tile, gather inlined ----------------
#define L3_SMEM ((128*132 + 128*72)*4)
__global__ void __launch_bounds__(256) k_lin3(const float* __restrict__ pts,
        const float* __restrict__ cylidx, const float* __restrict__ w3,
        const float* __restrict__ g3, const float* __restrict__ b3, int n, float invn) {
    extern __shared__ float dsm[];
    float* s_a = dsm;                 // [p][k] pitch 132
    float* s_b = dsm + 128*132;       // [k][o] pitch 72
    __shared__ float pa[64], pc[64], ca[64], cs[64];
    __shared__ float s_w4[4][128];
    __shared__ int   s_o4[4][128];
    __shared__ float red[512];
    int tid = threadIdx.x;
    if (tid < 64) {
        pa[tid] = d_bn[192+tid]; pc[tid] = d_bn[320+tid];
        ca[tid] = d_bn[384+tid]; cs[tid] = d_bn[448+tid];
    }
    for (int t = tid; t < 8192; t += 256) {
        int o = t >> 7, k = t & 127;
        s_b[k*72 + o] = __uint_as_float(tf32(w3[t]));
    }
    int pbase = blockIdx.x*128;
    if (tid < 128) {
        int p = pbase + tid;
        int i = (p < n) ? p : (n-1);
        float yq = cylidx[2*(size_t)i], xq = cylidx[2*(size_t)i+1];
        int y0i = (int)floorf(yq); int y1i = min(y0i+1, 511); y0i = min(max(y0i,0), 511);
        int x0i = (int)floorf(xq); int x1i = min(x0i+1, 47);  x0i = min(max(x0i,0), 47);
        s_w4[0][tid] = ((float)x1i - xq)*((float)y1i - yq);
        s_w4[1][tid] = ((float)x1i - xq)*(yq - (float)y0i);
        s_w4[2][tid] = (xq - (float)x0i)*((float)y1i - yq);
        s_w4[3][tid] = (xq - (float)x0i)*(yq - (float)y0i);
        int b = (int)pts[(size_t)i*5];
        int base = b*512*48*64;
        s_o4[0][tid] = base + (y0i*48 + x0i)*64;
        s_o4[1][tid] = base + (y1i*48 + x0i)*64;
        s_o4[2][tid] = base + (y0i*48 + x1i)*64;
        s_o4[3][tid] = base + (y1i*48 + x1i)*64;
    }
    __syncthreads();
    for (int idx = tid; idx < 128*16; idx += 256) {
        int lp = idx >> 4, kq = idx & 15;
        int p = pbase + lp, k = kq*4;
        uint4 tv = make_uint4(0u,0u,0u,0u);
        if (p < n) {
            float4 v = *(const float4*)&d_lin2[(size_t)p*128 + 64 + k];
            tv.x = tf32(fmaxf(fmaf(v.x, pa[k+0], pc[k+0]), 0.f));
            tv.y = tf32(fmaxf(fmaf(v.y, pa[k+1], pc[k+1]), 0.f));
            tv.z = tf32(fmaxf(fmaf(v.z, pa[k+2], pc[k+2]), 0.f));
            tv.w = tf32(fmaxf(fmaf(v.w, pa[k+3], pc[k+3]), 0.f));
        }
        *(uint4*)&s_a[lp*132 + k] = tv;
    }
    for (int idx = tid; idx < 128*16; idx += 256) {
        int lp = idx >> 4, kq = idx & 15;
        int p = pbase + lp, c = kq*4;
        uint4 tv = make_uint4(0u,0u,0u,0u);
        if (p < n) {
            float wa = s_w4[0][lp], wb = s_w4[1][lp], wcw = s_w4[2][lp], wd = s_w4[3][lp];
            float4 av = *(const float4*)&d_conv[s_o4[0][lp] + c];
            float4 bv = *(const float4*)&d_conv[s_o4[1][lp] + c];
            float4 cv = *(const float4*)&d_conv[s_o4[2][lp] + c];
            float4 dv = *(const float4*)&d_conv[s_o4[3][lp] + c];
            float rx = wa*fmaxf(fmaf(av.x, ca[c+0], cs[c+0]),0.f) + wb*fmaxf(fmaf(bv.x, ca[c+0], cs[c+0]),0.f)
                + wcw*fmaxf(fmaf(cv.x, ca[c+0], cs[c+0]),0.f) + wd*fmaxf(fmaf(dv.x, ca[c+0], cs[c+0]),0.f);
            float ry = wa*fmaxf(fmaf(av.y, ca[c+1], cs[c+1]),0.f) + wb*fmaxf(fmaf(bv.y, ca[c+1], cs[c+1]),0.f)
                + wcw*fmaxf(fmaf(cv.y, ca[c+1], cs[c+1]),0.f) + wd*fmaxf(fmaf(dv.y, ca[c+1], cs[c+1]),0.f);
            float rz = wa*fmaxf(fmaf(av.z, ca[c+2], cs[c+2]),0.f) + wb*fmaxf(fmaf(bv.z, ca[c+2], cs[c+2]),0.f)
                + wcw*fmaxf(fmaf(cv.z, ca[c+2], cs[c+2]),0.f) + wd*fmaxf(fmaf(dv.z, ca[c+2], cs[c+2]),0.f);
            float rw = wa*fmaxf(fmaf(av.w, ca[c+3], cs[c+3]),0.f) + wb*fmaxf(fmaf(bv.w, ca[c+3], cs[c+3]),0.f)
                + wcw*fmaxf(fmaf(cv.w, ca[c+3], cs[c+3]),0.f) + wd*fmaxf(fmaf(dv.w, ca[c+3], cs[c+3]),0.f);
            tv.x = tf32(rx); tv.y = tf32(ry); tv.z = tf32(rz); tv.w = tf32(rw);
        }
        *(uint4*)&s_a[lp*132 + 64 + c] = tv;
    }
    __syncthreads();
    int wid = tid >> 5, lane = tid & 31;
    int g = lane >> 2, tg = lane & 3;
    int wm = wid >> 1, wn = wid & 1;
    int m0 = wm*32;
    const uint* ua = (const uint*)s_a;
    const uint* ub = (const uint*)s_b;
    float c[2][4][4];
    #pragma unroll
    for (int mt = 0; mt < 2; mt++)
        #pragma unroll
        for (int nt = 0; nt < 4; nt++)
            #pragma unroll
            for (int j = 0; j < 4; j++) c[mt][nt][j] = 0.f;
    #pragma unroll
    for (int kc = 0; kc < 16; kc++) {
        int k0 = kc*8;
        uint a0[2], a1[2], a2[2], a3[2];
        #pragma unroll
        for (int mt = 0; mt < 2; mt++) {
            int mb = m0 + mt*16;
            a0[mt] = ua[(mb+g)*132   + k0 + tg];
            a1[mt] = ua[(mb+g+8)*132 + k0 + tg];
            a2[mt] = ua[(mb+g)*132   + k0 + tg + 4];
            a3[mt] = ua[(mb+g+8)*132 + k0 + tg + 4];
        }
        #pragma unroll
        for (int nt = 0; nt < 4; nt++) {
            int col = wn*32 + nt*8 + g;
            uint b0 = ub[(k0+tg)*72   + col];
            uint b1 = ub[(k0+tg+4)*72 + col];
            mma_tf32(c[0][nt], a0[0], a1[0], a2[0], a3[0], b0, b1);
            mma_tf32(c[1][nt], a0[1], a1[1], a2[1], a3[1], b0, b1);
        }
    }
    __syncthreads();
    float* stage = dsm;              // [p][o] pitch 68
    #pragma unroll
    for (int mt = 0; mt < 2; mt++) {
        int mb = m0 + mt*16;
        #pragma unroll
        for (int nt = 0; nt < 4; nt++) {
            int n0 = wn*32 + nt*8 + tg*2;
            *(float2*)&stage[(mb+g)*68   + n0] = make_float2(c[mt][nt][0], c[mt][nt][1]);
            *(float2*)&stage[(mb+g+8)*68 + n0] = make_float2(c[mt][nt][2], c[mt][nt][3]);
        }
    }
    __syncthreads();
    for (int idx = tid; idx < 128*16; idx += 256) {
        int lp = idx >> 4, q = idx & 15;
        int p = pbase + lp;
        if (p < n)
            *(float4*)&d_lin3[(size_t)p*64 + q*4] = *(const float4*)&stage[lp*68 + q*4];
    }
    {
        int col = tid & 63, qtr = tid >> 6;
        float s = 0.f, s2 = 0.f;
        int r0 = qtr*32;
        for (int r = r0; r < r0+32; r++) {
            float v = stage[r*68 + col];
            s += v; s2 += v*v;
        }
        red[qtr*64 + col] = s;
        red[256 + qtr*64 + col] = s2;
        __syncthreads();
        if (qtr == 0) {
            atomicAdd(&d_stats[512+col], red[col] + red[64+col] + red[128+col] + red[192+col]);
            atomicAdd(&d_stats[576+col], red[256+col] + red[320+col] + red[384+col] + red[448+col]);
        }
        __syncthreads();
    }
    bn_finalize_inline(3, gridDim.x, tid, 64, invn, 512, 512, g3, b3);
}

// final: bn_relu(lin3) -> out; atomicMax into bev_max; extra blocks do voxel coords
__global__ void k_final(const int* __restrict__ binv, const int* __restrict__ bcoord,
                        float* __restrict__ out, int n, int nb, int nblk) {
    if (blockIdx.x >= nblk) {
        int i = (blockIdx.x - nblk)*blockDim.x + threadIdx.x;
        if (i < nb) {
            int c = bcoord[i];
            int vb = c / 55000;
            int r  = c % 55000;
            int vx = r / 250;
            int vy = r % 250;
            float* o = out + (size_t)n*64 + (size_t)nb*64 + (size_t)i*4;
            o[0] = (float)vb; o[1] = 0.f; o[2] = (float)vy; o[3] = (float)vx;
        }
        return;
    }
    __shared__ float sa[64], sc[64];
    if (threadIdx.x < 64) { sa[threadIdx.x] = d_bn[512+threadIdx.x]; sc[threadIdx.x] = d_bn[576+threadIdx.x]; }
    __syncthreads();
    int i = blockIdx.x*blockDim.x + threadIdx.x;
    if (i >= n) return;
    int bi = binv[i];
    const float4* src = (const float4*)&d_lin3[(size_t)i*64];
    float4* dst = (float4*)(out + (size_t)i*64);
    unsigned* mx = (unsigned*)(out + (size_t)n*64 + (size_t)bi*64);
    #pragma unroll
    for (int j = 0; j < 16; j++) {
        float4 v = src[j];
        int c = j*4;
        float r0 = fmaxf(fmaf(v.x, sa[c+0], sc[c+0]), 0.f);
        float r1 = fmaxf(fmaf(v.y, sa[c+1], sc[c+1]), 0.f);
        float r2 = fmaxf(fmaf(v.z, sa[c+2], sc[c+2]), 0.f);
        float r3 = fmaxf(fmaf(v.w, sa[c+3], sc[c+3]), 0.f);
        dst[j] = make_float4(r0, r1, r2, r3);
        atomicMax(mx+c+0, __float_as_uint(r0));
        atomicMax(mx+c+1, __float_as_uint(r1));
        atomicMax(mx+c+2, __float_as_uint(r2));
        atomicMax(mx+c+3, __float_as_uint(r3));
    }
}

// ---------------- launcher ----------------
extern "C" void kernel_launch(void* const* d_in, const int* in_sizes, int n_in,
                              void* d_out, int out_size) {
    const float* points = (const float*)d_in[0];
    const float* pcyl   = (const float*)d_in[1];
    const float* cylidx = (const float*)d_in[2];
    const float* bevidx = (const float*)d_in[3];
    const float* w1 = (const float*)d_in[4];
    const float* g1 = (const float*)d_in[5];
    const float* b1 = (const float*)d_in[6];
    const float* w2 = (const float*)d_in[7];
    const float* g2 = (const float*)d_in[8];
    const float* b2 = (const float*)d_in[9];
    const float* wc = (const float*)d_in[10];
    const float* gc = (const float*)d_in[11];
    const float* bc = (const float*)d_in[12];
    const float* w3 = (const float*)d_in[13];
    const float* g3 = (const float*)d_in[14];
    const float* b3 = (const float*)d_in[15];
    const int* binv   = (const int*)d_in[16];
    const int* bcoord = (const int*)d_in[17];
    const int* cinv   = (const int*)d_in[18];

    int n  = in_sizes[0] / 5;
    int nb = in_sizes[17];
    int nc = in_sizes[19];
    float* out = (float*)d_out;
    float invn = 1.0f/(float)n;

    static bool attr_done = false;
    if (!attr_done) {
        cudaFuncSetAttribute(k_lin1, cudaFuncAttributeMaxDynamicSharedMemorySize, L1_SMEM);
        cudaFuncSetAttribute(k_conv, cudaFuncAttributeMaxDynamicSharedMemorySize, CV_SMEM);
        cudaFuncSetAttribute(k_lin2, cudaFuncAttributeMaxDynamicSharedMemorySize, L2_SMEM);
        cudaFuncSetAttribute(k_lin3, cudaFuncAttributeMaxDynamicSharedMemorySize, L3_SMEM);
        attr_done = true;
    }

    int nblk = (n + 255) / 256;
    int gblk = (n + 127) / 128;
    k_zero<<<512, 256>>>(out + (size_t)n*64, nb, nc, wc);
    k_scatter<<<nblk, 256>>>(points, pcyl, binv, cinv, n);
    k_lin1<<<nblk, 256, L1_SMEM>>>(points, pcyl, cylidx, bevidx, binv, cinv, w1, g1, b1, n, invn);
    k_lin2<<<gblk, 256, L2_SMEM>>>(w2, g2, b2, n, invn);
    k_cylmax<<<nblk, 256>>>(points, cylidx, n);
    dim3 cg(3, 64, 4);
    k_conv<<<cg, 256, CV_SMEM>>>(gc, bc);
    k_lin3<<<gblk, 256, L3_SMEM>>>(points, cylidx, w3, g3, b3, n, invn);
    int vblk = (nb + 255) / 256;
    k_final<<<nblk + vblk, 256>>>(binv, bcoord, out, n, nb, nblk);
}